// round 1
// baseline (speedup 1.0000x reference)
#include <cuda_runtime.h>
#include <math.h>

#define B_ 4
#define T_ 2048
#define E_ 1024
#define H_ 16
#define D_ 64

// Scratch (allocation-free): 3 x 32 MB
__device__ float g_Qh[B_*H_*T_*D_];   // [b,h,t,d]
__device__ float g_Kh[B_*H_*T_*D_];   // [b,h,t,d]  (also used as V)
__device__ float g_AO[B_*T_*E_];      // [b,t,(h d)]

// ---------------------------------------------------------------------------
// C = A @ W^T.  A: MxK row-major, W: NxK row-major.
// MODE 0: C[m*N+n] flat.  MODE 1: head-split C[((b*H+h)*T+t)*D+d].
// 64x64 tile, BK=16, 256 threads, 4x4 per-thread microtile.
// ---------------------------------------------------------------------------
template<int MODE>
__global__ __launch_bounds__(256) void gemm_nt(const float* __restrict__ A,
                                               const float* __restrict__ W,
                                               float* __restrict__ C,
                                               int M, int N, int K)
{
    __shared__ float As[16][64];   // [k][m]
    __shared__ float Bs[16][64];   // [k][n]
    const int tid = threadIdx.x;
    const int tx = tid & 15, ty = tid >> 4;
    const int m0 = blockIdx.y * 64;
    const int n0 = blockIdx.x * 64;
    const int lr = tid >> 2;          // 0..63
    const int lc = (tid & 3) * 4;     // 0,4,8,12

    float acc[4][4];
    #pragma unroll
    for (int i = 0; i < 4; i++)
        #pragma unroll
        for (int j = 0; j < 4; j++) acc[i][j] = 0.f;

    const float* Ap = A + (size_t)(m0 + lr) * K + lc;
    const float* Wp = W + (size_t)(n0 + lr) * K + lc;

    for (int k0 = 0; k0 < K; k0 += 16) {
        float4 av = *(const float4*)(Ap + k0);
        float4 wv = *(const float4*)(Wp + k0);
        As[lc+0][lr] = av.x; As[lc+1][lr] = av.y; As[lc+2][lr] = av.z; As[lc+3][lr] = av.w;
        Bs[lc+0][lr] = wv.x; Bs[lc+1][lr] = wv.y; Bs[lc+2][lr] = wv.z; Bs[lc+3][lr] = wv.w;
        __syncthreads();
        #pragma unroll
        for (int kk = 0; kk < 16; kk++) {
            float4 a = *(const float4*)&As[kk][ty*4];
            float4 b = *(const float4*)&Bs[kk][tx*4];
            float ar[4] = {a.x, a.y, a.z, a.w};
            float br[4] = {b.x, b.y, b.z, b.w};
            #pragma unroll
            for (int i = 0; i < 4; i++)
                #pragma unroll
                for (int j = 0; j < 4; j++)
                    acc[i][j] = fmaf(ar[i], br[j], acc[i][j]);
        }
        __syncthreads();
    }

    #pragma unroll
    for (int i = 0; i < 4; i++) {
        int m = m0 + ty*4 + i;
        int n = n0 + tx*4;
        float4 v = make_float4(acc[i][0], acc[i][1], acc[i][2], acc[i][3]);
        if (MODE == 0) {
            *(float4*)(C + (size_t)m * N + n) = v;
        } else {
            int b = m >> 11, t = m & (T_ - 1);
            int h = n >> 6,  d = n & 63;
            *(float4*)(C + ((((size_t)b * H_ + h) * T_ + t) * D_ + d)) = v;
        }
    }
}

// ---------------------------------------------------------------------------
// Causal flash attention, V == K (share_kv).
// One block per (b,h, 64-row q tile). 256 threads, 4x4 microtiles.
// Dynamic smem: Qs[64][64], Ks[64][64], Kst[64][68] (d-major), Ps[64][64].
// ---------------------------------------------------------------------------
#define KST_LD 68
#define ATTN_SMEM ((3*64*64 + 64*KST_LD) * (int)sizeof(float))

__global__ __launch_bounds__(256) void attn_kernel(const float* __restrict__ Qh,
                                                   const float* __restrict__ Kh,
                                                   float* __restrict__ AO)
{
    extern __shared__ float sm[];
    float* Qs  = sm;                      // [64][64]  q-major, pre-scaled
    float* Ks  = sm + 4096;               // [64][64]  k-major (V tile for PV)
    float* Kst = sm + 8192;               // [64][68]  d-major (for QK^T)
    float* Ps  = sm + 8192 + 64*KST_LD;   // [64][64]

    const int tid = threadIdx.x;
    const int tx = tid & 15, ty = tid >> 4;
    const int tx4 = tx * 4, ty4 = ty * 4;
    const int qt = 31 - (int)blockIdx.x;  // heavy (long-causal) tiles launch first
    const int bh = blockIdx.y;

    const float* Qbase = Qh + (size_t)bh * T_ * D_;
    const float* Kbase = Kh + (size_t)bh * T_ * D_;

    // Load Q tile once, folded scale 1/sqrt(64)
    #pragma unroll
    for (int s = 0; s < 4; s++) {
        int idx = tid + s * 256;          // float4 slot 0..1023
        int r = idx >> 4;
        int c = (idx & 15) * 4;
        float4 qv = *(const float4*)(Qbase + (size_t)(qt*64 + r) * D_ + c);
        qv.x *= 0.125f; qv.y *= 0.125f; qv.z *= 0.125f; qv.w *= 0.125f;
        *(float4*)&Qs[r*64 + c] = qv;
    }

    float mrow[4], lrow[4], Oc[4][4];
    #pragma unroll
    for (int i = 0; i < 4; i++) {
        mrow[i] = -1e30f; lrow[i] = 0.f;
        #pragma unroll
        for (int j = 0; j < 4; j++) Oc[i][j] = 0.f;
    }

    for (int kt = 0; kt <= qt; kt++) {
        __syncthreads();   // prev iteration done with Ks/Ps (also covers Q load on iter 0)

        // Load K tile: natural layout + d-major transpose
        #pragma unroll
        for (int s = 0; s < 4; s++) {
            int idx = tid + s * 256;
            int r = idx >> 4;
            int c = (idx & 15) * 4;
            float4 kv = *(const float4*)(Kbase + (size_t)(kt*64 + r) * D_ + c);
            *(float4*)&Ks[r*64 + c] = kv;
            Kst[(c+0)*KST_LD + r] = kv.x;
            Kst[(c+1)*KST_LD + r] = kv.y;
            Kst[(c+2)*KST_LD + r] = kv.z;
            Kst[(c+3)*KST_LD + r] = kv.w;
        }
        __syncthreads();

        // S = (Q/8) @ K^T : 4x4 per thread
        float Sc[4][4];
        #pragma unroll
        for (int i = 0; i < 4; i++)
            #pragma unroll
            for (int j = 0; j < 4; j++) Sc[i][j] = 0.f;

        #pragma unroll
        for (int d4 = 0; d4 < 16; d4++) {
            float4 qv[4];
            #pragma unroll
            for (int i = 0; i < 4; i++)
                qv[i] = *(const float4*)&Qs[(ty4+i)*64 + d4*4];
            #pragma unroll
            for (int dd = 0; dd < 4; dd++) {
                float4 kv = *(const float4*)&Kst[(d4*4 + dd)*KST_LD + tx4];
                float kr[4] = {kv.x, kv.y, kv.z, kv.w};
                #pragma unroll
                for (int i = 0; i < 4; i++) {
                    float qc = (dd == 0) ? qv[i].x : (dd == 1) ? qv[i].y
                             : (dd == 2) ? qv[i].z : qv[i].w;
                    #pragma unroll
                    for (int j = 0; j < 4; j++)
                        Sc[i][j] = fmaf(qc, kr[j], Sc[i][j]);
                }
            }
        }

        // Causal mask: only diagonal tile has partial validity
        if (kt == qt) {
            #pragma unroll
            for (int i = 0; i < 4; i++)
                #pragma unroll
                for (int j = 0; j < 4; j++)
                    if (tx4 + j > ty4 + i) Sc[i][j] = -1e30f;
        }

        // Online softmax (row owned by 16-lane group sharing ty)
        #pragma unroll
        for (int i = 0; i < 4; i++) {
            float mx = fmaxf(fmaxf(Sc[i][0], Sc[i][1]), fmaxf(Sc[i][2], Sc[i][3]));
            #pragma unroll
            for (int off = 8; off > 0; off >>= 1)
                mx = fmaxf(mx, __shfl_xor_sync(0xffffffffu, mx, off));
            float mnew = fmaxf(mrow[i], mx);
            float p0 = __expf(Sc[i][0] - mnew);
            float p1 = __expf(Sc[i][1] - mnew);
            float p2 = __expf(Sc[i][2] - mnew);
            float p3 = __expf(Sc[i][3] - mnew);
            float psum = p0 + p1 + p2 + p3;
            #pragma unroll
            for (int off = 8; off > 0; off >>= 1)
                psum += __shfl_xor_sync(0xffffffffu, psum, off);
            float corr = __expf(mrow[i] - mnew);
            lrow[i] = lrow[i] * corr + psum;
            mrow[i] = mnew;
            #pragma unroll
            for (int j = 0; j < 4; j++) Oc[i][j] *= corr;
            *(float4*)&Ps[(ty4+i)*64 + tx4] = make_float4(p0, p1, p2, p3);
        }
        __syncthreads();

        // O += P @ V  (V = Ks, natural [k][d] layout)
        #pragma unroll
        for (int k4 = 0; k4 < 16; k4++) {
            float4 pv[4];
            #pragma unroll
            for (int i = 0; i < 4; i++)
                pv[i] = *(const float4*)&Ps[(ty4+i)*64 + k4*4];
            #pragma unroll
            for (int kk = 0; kk < 4; kk++) {
                float4 vv = *(const float4*)&Ks[(k4*4 + kk)*64 + tx4];
                float vr[4] = {vv.x, vv.y, vv.z, vv.w};
                #pragma unroll
                for (int i = 0; i < 4; i++) {
                    float pc = (kk == 0) ? pv[i].x : (kk == 1) ? pv[i].y
                             : (kk == 2) ? pv[i].z : pv[i].w;
                    #pragma unroll
                    for (int j = 0; j < 4; j++)
                        Oc[i][j] = fmaf(pc, vr[j], Oc[i][j]);
                }
            }
        }
    }

    // Epilogue: normalize and write [b, t, h*64+d]
    int b = bh >> 4, h = bh & 15;
    #pragma unroll
    for (int i = 0; i < 4; i++) {
        float inv = 1.0f / lrow[i];
        int t = qt*64 + ty4 + i;
        float4 ov = make_float4(Oc[i][0]*inv, Oc[i][1]*inv, Oc[i][2]*inv, Oc[i][3]*inv);
        *(float4*)(AO + ((size_t)b * T_ + t) * E_ + h*64 + tx4) = ov;
    }
}

// ---------------------------------------------------------------------------
extern "C" void kernel_launch(void* const* d_in, const int* in_sizes, int n_in,
                              void* d_out, int out_size)
{
    const float* q  = (const float*)d_in[0];
    const float* k  = (const float*)d_in[1];
    // d_in[2] (v) is dead: reference uses share_kv (vh = kh)
    const float* Wq = (const float*)d_in[3];
    const float* Wk = (const float*)d_in[4];
    const float* Wo = (const float*)d_in[5];
    float* out = (float*)d_out;

    float *pQh, *pKh, *pAO;
    cudaGetSymbolAddress((void**)&pQh, g_Qh);
    cudaGetSymbolAddress((void**)&pKh, g_Kh);
    cudaGetSymbolAddress((void**)&pAO, g_AO);

    dim3 gg(E_/64, (B_*T_)/64);   // (16, 128)
    gemm_nt<1><<<gg, 256>>>(q, Wq, pQh, B_*T_, E_, E_);
    gemm_nt<1><<<gg, 256>>>(k, Wk, pKh, B_*T_, E_, E_);

    cudaFuncSetAttribute(attn_kernel,
                         cudaFuncAttributeMaxDynamicSharedMemorySize, ATTN_SMEM);
    attn_kernel<<<dim3(32, B_*H_), 256, ATTN_SMEM>>>(pQh, pKh, pAO);

    gemm_nt<0><<<gg, 256>>>(pAO, Wo, out, B_*T_, E_, E_);
}

// round 3
// speedup vs baseline: 1.5158x; 1.5158x over previous
#include <cuda_runtime.h>
#include <cuda_bf16.h>
#include <math.h>
#include <stdint.h>

#define B_ 4
#define T_ 2048
#define E_ 1024
#define H_ 16
#define D_ 64
#define M_TOT (B_*T_)   // 8192

// ---------------- scratch (allocation-free) ----------------
__device__ __align__(16) __nv_bfloat16 g_qhi[M_TOT*E_], g_qlo[M_TOT*E_];
__device__ __align__(16) __nv_bfloat16 g_khi[M_TOT*E_], g_klo[M_TOT*E_];
__device__ __align__(16) __nv_bfloat16 g_wqhi[E_*E_],  g_wqlo[E_*E_];
__device__ __align__(16) __nv_bfloat16 g_wkhi[E_*E_],  g_wklo[E_*E_];
__device__ __align__(16) __nv_bfloat16 g_wohi[E_*E_],  g_wolo[E_*E_];
__device__ __align__(16) __nv_bfloat16 g_aohi[M_TOT*E_], g_aolo[M_TOT*E_];
__device__ float g_Qh[M_TOT*E_];   // [b,h,t,d]
__device__ float g_Kh[M_TOT*E_];   // [b,h,t,d] (also V)
__device__ float g_AO[M_TOT*E_];   // [b,t,(h d)]

// ---------------- helpers ----------------
__device__ __forceinline__ uint32_t smem_u32(const void* p) {
    uint32_t a;
    asm("{ .reg .u64 t; cvta.to.shared.u64 t, %1; cvt.u32.u64 %0, t; }" : "=r"(a) : "l"(p));
    return a;
}
__device__ __forceinline__ void cp16(uint32_t saddr, const void* gaddr) {
    asm volatile("cp.async.cg.shared.global [%0], [%1], 16;" :: "r"(saddr), "l"(gaddr));
}
#define CP_COMMIT() asm volatile("cp.async.commit_group;" ::: "memory")
#define CP_WAIT(n)  asm volatile("cp.async.wait_group %0;" :: "n"(n) : "memory")

__device__ __forceinline__ void ldm_x4(uint32_t& r0, uint32_t& r1, uint32_t& r2, uint32_t& r3,
                                       uint32_t addr) {
    asm volatile("ldmatrix.sync.aligned.m8n8.x4.shared.b16 {%0,%1,%2,%3}, [%4];"
                 : "=r"(r0), "=r"(r1), "=r"(r2), "=r"(r3) : "r"(addr));
}
__device__ __forceinline__ void mma16816(float& d0, float& d1, float& d2, float& d3,
                                         uint32_t a0, uint32_t a1, uint32_t a2, uint32_t a3,
                                         uint32_t b0, uint32_t b1) {
    asm volatile("mma.sync.aligned.m16n8k16.row.col.f32.bf16.bf16.f32 "
                 "{%0,%1,%2,%3}, {%4,%5,%6,%7}, {%8,%9}, {%0,%1,%2,%3};"
                 : "+f"(d0), "+f"(d1), "+f"(d2), "+f"(d3)
                 : "r"(a0), "r"(a1), "r"(a2), "r"(a3), "r"(b0), "r"(b1));
}

// ---------------- fp32 -> bf16 hi/lo split ----------------
__global__ __launch_bounds__(256) void split_kernel(const float4* __restrict__ src,
                                                    __nv_bfloat162* __restrict__ hi,
                                                    __nv_bfloat162* __restrict__ lo,
                                                    int n4)
{
    int i = blockIdx.x * 256 + threadIdx.x;
    if (i >= n4) return;
    float4 v = src[i];
    __nv_bfloat16 h0 = __float2bfloat16_rn(v.x);
    __nv_bfloat16 h1 = __float2bfloat16_rn(v.y);
    __nv_bfloat16 h2 = __float2bfloat16_rn(v.z);
    __nv_bfloat16 h3 = __float2bfloat16_rn(v.w);
    __nv_bfloat16 l0 = __float2bfloat16_rn(v.x - __bfloat162float(h0));
    __nv_bfloat16 l1 = __float2bfloat16_rn(v.y - __bfloat162float(h1));
    __nv_bfloat16 l2 = __float2bfloat16_rn(v.z - __bfloat162float(h2));
    __nv_bfloat16 l3 = __float2bfloat16_rn(v.w - __bfloat162float(h3));
    hi[2*i]   = __nv_bfloat162(h0, h1);
    hi[2*i+1] = __nv_bfloat162(h2, h3);
    lo[2*i]   = __nv_bfloat162(l0, l1);
    lo[2*i+1] = __nv_bfloat162(l2, l3);
}

// ---------------------------------------------------------------------------
// HMMA GEMM: C = A @ W^T, bf16-split 3-pass accumulate.
// A,[W]: K-major (row stride 1024 bf16). Block 128x128, Kchunk=32, 8 warps.
// Smem rows padded to 40 bf16 (80B) -> ldmatrix conflict-free.
// ---------------------------------------------------------------------------
#define SROWB 80                         // bytes per smem row (32 bf16 + pad)
#define TILEB (128 * SROWB)              // 10240 B per operand tile
#define NCHUNK 96                        // 3 passes x 32 K-chunks

template<int MODE>
__global__ __launch_bounds__(256) void gemm_mma(const __nv_bfloat16* __restrict__ Ahi,
                                                const __nv_bfloat16* __restrict__ Alo,
                                                const __nv_bfloat16* __restrict__ Bhi,
                                                const __nv_bfloat16* __restrict__ Blo,
                                                float* __restrict__ C)
{
    __shared__ __align__(16) char smA[2][TILEB];
    __shared__ __align__(16) char smB[2][TILEB];

    const int tid = threadIdx.x;
    const int wid = tid >> 5, lid = tid & 31;
    const int warp_m = wid & 3, warp_n = wid >> 2;      // 4 x 2 warp grid
    const int m0 = blockIdx.y * 128, n0 = blockIdx.x * 128;

    const char* Asel[3] = { (const char*)Ahi, (const char*)Ahi, (const char*)Alo };
    const char* Bsel[3] = { (const char*)Bhi, (const char*)Blo, (const char*)Bhi };

    // global-load slots: idx = tid + q*256 (0..511): row = idx>>2, 16B-col = idx&3
    const int gr = tid >> 2, gc = tid & 3;

    float acc[2][8][4];
    #pragma unroll
    for (int i = 0; i < 2; i++)
        #pragma unroll
        for (int j = 0; j < 8; j++)
            #pragma unroll
            for (int c = 0; c < 4; c++) acc[i][j][c] = 0.f;

    const uint32_t sA0 = smem_u32(smA[0]), sB0 = smem_u32(smB[0]);

    auto issue = [&](int chunk) {
        const int p = chunk >> 5, kc = chunk & 31;
        const int st = chunk & 1;
        const char* Ab = Asel[p];
        const char* Bb = Bsel[p];
        const size_t colB = (size_t)kc * 64;   // 32 bf16 = 64 bytes per chunk
        #pragma unroll
        for (int q = 0; q < 2; q++) {
            int r = gr + q * 64;
            cp16(sA0 + st * TILEB + r * SROWB + gc * 16,
                 Ab + (size_t)(m0 + r) * 2048 + colB + gc * 16);
            cp16(sB0 + st * TILEB + r * SROWB + gc * 16,
                 Bb + (size_t)(n0 + r) * 2048 + colB + gc * 16);
        }
        CP_COMMIT();
    };

    issue(0);
    for (int i = 0; i < NCHUNK; i++) {
        if (i + 1 < NCHUNK) { issue(i + 1); CP_WAIT(1); }
        else                { CP_WAIT(0); }
        __syncthreads();

        const int st = i & 1;
        const uint32_t bA = sA0 + st * TILEB;
        const uint32_t bB = sB0 + st * TILEB;
        // lane address pattern shared by A and B x4 loads:
        const int lrow = lid & 15, lcol = (lid >> 4) * 16;

        #pragma unroll
        for (int s = 0; s < 2; s++) {               // two k16 steps per chunk
            uint32_t a[2][4];
            #pragma unroll
            for (int mt = 0; mt < 2; mt++) {
                uint32_t addr = bA + (warp_m*32 + mt*16 + lrow) * SROWB + s*32 + lcol;
                ldm_x4(a[mt][0], a[mt][1], a[mt][2], a[mt][3], addr);
            }
            uint32_t b[8][2];
            #pragma unroll
            for (int np = 0; np < 4; np++) {
                uint32_t r0, r1, r2, r3;
                uint32_t addr = bB + (warp_n*64 + np*16 + lrow) * SROWB + s*32 + lcol;
                ldm_x4(r0, r1, r2, r3, addr);
                b[np*2][0] = r0;   b[np*2][1] = r2;
                b[np*2+1][0] = r1; b[np*2+1][1] = r3;
            }
            #pragma unroll
            for (int mt = 0; mt < 2; mt++)
                #pragma unroll
                for (int nt = 0; nt < 8; nt++)
                    mma16816(acc[mt][nt][0], acc[mt][nt][1], acc[mt][nt][2], acc[mt][nt][3],
                             a[mt][0], a[mt][1], a[mt][2], a[mt][3],
                             b[nt][0], b[nt][1]);
        }
        __syncthreads();
    }

    // epilogue
    const int gid = lid >> 2, tig = lid & 3;
    #pragma unroll
    for (int mt = 0; mt < 2; mt++) {
        #pragma unroll
        for (int nt = 0; nt < 8; nt++) {
            int m = m0 + warp_m*32 + mt*16 + gid;
            int n = n0 + warp_n*64 + nt*8 + tig*2;
            #pragma unroll
            for (int half = 0; half < 2; half++) {
                int mm = m + half * 8;
                float2 v = half ? make_float2(acc[mt][nt][2], acc[mt][nt][3])
                                : make_float2(acc[mt][nt][0], acc[mt][nt][1]);
                if (MODE == 0) {
                    *(float2*)(C + (size_t)mm * E_ + n) = v;
                } else {
                    int b = mm >> 11, t = mm & (T_ - 1);
                    int h = n >> 6,  d = n & 63;
                    *(float2*)(C + ((((size_t)b * H_ + h) * T_ + t) * D_ + d)) = v;
                }
            }
        }
    }
}

// ---------------------------------------------------------------------------
// Causal flash attention, V == K (share_kv). fp32 SIMT (round-1 proven).
// ---------------------------------------------------------------------------
#define KST_LD 68
#define ATTN_SMEM ((3*64*64 + 64*KST_LD) * (int)sizeof(float))

__global__ __launch_bounds__(256) void attn_kernel(const float* __restrict__ Qh,
                                                   const float* __restrict__ Kh,
                                                   float* __restrict__ AO)
{
    extern __shared__ float sm[];
    float* Qs  = sm;
    float* Ks  = sm + 4096;
    float* Kst = sm + 8192;
    float* Ps  = sm + 8192 + 64*KST_LD;

    const int tid = threadIdx.x;
    const int tx = tid & 15, ty = tid >> 4;
    const int tx4 = tx * 4, ty4 = ty * 4;
    const int qt = 31 - (int)blockIdx.x;
    const int bh = blockIdx.y;

    const float* Qbase = Qh + (size_t)bh * T_ * D_;
    const float* Kbase = Kh + (size_t)bh * T_ * D_;

    #pragma unroll
    for (int s = 0; s < 4; s++) {
        int idx = tid + s * 256;
        int r = idx >> 4;
        int c = (idx & 15) * 4;
        float4 qv = *(const float4*)(Qbase + (size_t)(qt*64 + r) * D_ + c);
        qv.x *= 0.125f; qv.y *= 0.125f; qv.z *= 0.125f; qv.w *= 0.125f;
        *(float4*)&Qs[r*64 + c] = qv;
    }

    float mrow[4], lrow[4], Oc[4][4];
    #pragma unroll
    for (int i = 0; i < 4; i++) {
        mrow[i] = -1e30f; lrow[i] = 0.f;
        #pragma unroll
        for (int j = 0; j < 4; j++) Oc[i][j] = 0.f;
    }

    for (int kt = 0; kt <= qt; kt++) {
        __syncthreads();
        #pragma unroll
        for (int s = 0; s < 4; s++) {
            int idx = tid + s * 256;
            int r = idx >> 4;
            int c = (idx & 15) * 4;
            float4 kv = *(const float4*)(Kbase + (size_t)(kt*64 + r) * D_ + c);
            *(float4*)&Ks[r*64 + c] = kv;
            Kst[(c+0)*KST_LD + r] = kv.x;
            Kst[(c+1)*KST_LD + r] = kv.y;
            Kst[(c+2)*KST_LD + r] = kv.z;
            Kst[(c+3)*KST_LD + r] = kv.w;
        }
        __syncthreads();

        float Sc[4][4];
        #pragma unroll
        for (int i = 0; i < 4; i++)
            #pragma unroll
            for (int j = 0; j < 4; j++) Sc[i][j] = 0.f;

        #pragma unroll
        for (int d4 = 0; d4 < 16; d4++) {
            float4 qv[4];
            #pragma unroll
            for (int i = 0; i < 4; i++)
                qv[i] = *(const float4*)&Qs[(ty4+i)*64 + d4*4];
            #pragma unroll
            for (int dd = 0; dd < 4; dd++) {
                float4 kv = *(const float4*)&Kst[(d4*4 + dd)*KST_LD + tx4];
                float kr[4] = {kv.x, kv.y, kv.z, kv.w};
                #pragma unroll
                for (int i = 0; i < 4; i++) {
                    float qc = (dd == 0) ? qv[i].x : (dd == 1) ? qv[i].y
                             : (dd == 2) ? qv[i].z : qv[i].w;
                    #pragma unroll
                    for (int j = 0; j < 4; j++)
                        Sc[i][j] = fmaf(qc, kr[j], Sc[i][j]);
                }
            }
        }

        if (kt == qt) {
            #pragma unroll
            for (int i = 0; i < 4; i++)
                #pragma unroll
                for (int j = 0; j < 4; j++)
                    if (tx4 + j > ty4 + i) Sc[i][j] = -1e30f;
        }

        #pragma unroll
        for (int i = 0; i < 4; i++) {
            float mx = fmaxf(fmaxf(Sc[i][0], Sc[i][1]), fmaxf(Sc[i][2], Sc[i][3]));
            #pragma unroll
            for (int off = 8; off > 0; off >>= 1)
                mx = fmaxf(mx, __shfl_xor_sync(0xffffffffu, mx, off));
            float mnew = fmaxf(mrow[i], mx);
            float p0 = __expf(Sc[i][0] - mnew);
            float p1 = __expf(Sc[i][1] - mnew);
            float p2 = __expf(Sc[i][2] - mnew);
            float p3 = __expf(Sc[i][3] - mnew);
            float psum = p0 + p1 + p2 + p3;
            #pragma unroll
            for (int off = 8; off > 0; off >>= 1)
                psum += __shfl_xor_sync(0xffffffffu, psum, off);
            float corr = __expf(mrow[i] - mnew);
            lrow[i] = lrow[i] * corr + psum;
            mrow[i] = mnew;
            #pragma unroll
            for (int j = 0; j < 4; j++) Oc[i][j] *= corr;
            *(float4*)&Ps[(ty4+i)*64 + tx4] = make_float4(p0, p1, p2, p3);
        }
        __syncthreads();

        #pragma unroll
        for (int k4 = 0; k4 < 16; k4++) {
            float4 pv[4];
            #pragma unroll
            for (int i = 0; i < 4; i++)
                pv[i] = *(const float4*)&Ps[(ty4+i)*64 + k4*4];
            #pragma unroll
            for (int kk = 0; kk < 4; kk++) {
                float4 vv = *(const float4*)&Ks[(k4*4 + kk)*64 + tx4];
                float vr[4] = {vv.x, vv.y, vv.z, vv.w};
                #pragma unroll
                for (int i = 0; i < 4; i++) {
                    float pc = (kk == 0) ? pv[i].x : (kk == 1) ? pv[i].y
                             : (kk == 2) ? pv[i].z : pv[i].w;
                    #pragma unroll
                    for (int j = 0; j < 4; j++)
                        Oc[i][j] = fmaf(pc, vr[j], Oc[i][j]);
                }
            }
        }
    }

    int b = bh >> 4, h = bh & 15;
    #pragma unroll
    for (int i = 0; i < 4; i++) {
        float inv = 1.0f / lrow[i];
        int t = qt*64 + ty4 + i;
        float4 ov = make_float4(Oc[i][0]*inv, Oc[i][1]*inv, Oc[i][2]*inv, Oc[i][3]*inv);
        *(float4*)(AO + ((size_t)b * T_ + t) * E_ + h*64 + tx4) = ov;
    }
}

// ---------------------------------------------------------------------------
extern "C" void kernel_launch(void* const* d_in, const int* in_sizes, int n_in,
                              void* d_out, int out_size)
{
    const float* q  = (const float*)d_in[0];
    const float* k  = (const float*)d_in[1];
    // d_in[2] (v) dead: share_kv
    const float* Wq = (const float*)d_in[3];
    const float* Wk = (const float*)d_in[4];
    const float* Wo = (const float*)d_in[5];
    float* out = (float*)d_out;

    float *pQh, *pKh, *pAO;
    __nv_bfloat16 *pqhi,*pqlo,*pkhi,*pklo,*pwqhi,*pwqlo,*pwkhi,*pwklo,*pwohi,*pwolo,*paohi,*paolo;
    cudaGetSymbolAddress((void**)&pQh, g_Qh);
    cudaGetSymbolAddress((void**)&pKh, g_Kh);
    cudaGetSymbolAddress((void**)&pAO, g_AO);
    cudaGetSymbolAddress((void**)&pqhi, g_qhi);   cudaGetSymbolAddress((void**)&pqlo, g_qlo);
    cudaGetSymbolAddress((void**)&pkhi, g_khi);   cudaGetSymbolAddress((void**)&pklo, g_klo);
    cudaGetSymbolAddress((void**)&pwqhi, g_wqhi); cudaGetSymbolAddress((void**)&pwqlo, g_wqlo);
    cudaGetSymbolAddress((void**)&pwkhi, g_wkhi); cudaGetSymbolAddress((void**)&pwklo, g_wklo);
    cudaGetSymbolAddress((void**)&pwohi, g_wohi); cudaGetSymbolAddress((void**)&pwolo, g_wolo);
    cudaGetSymbolAddress((void**)&paohi, g_aohi); cudaGetSymbolAddress((void**)&paolo, g_aolo);

    static bool attr_done = false;
    if (!attr_done) {
        cudaFuncSetAttribute(attn_kernel, cudaFuncAttributeMaxDynamicSharedMemorySize, ATTN_SMEM);
        attr_done = true;
    }

    const int n4_big = M_TOT * E_ / 4;
    const int n4_w   = E_ * E_ / 4;
    split_kernel<<<(n4_big + 255)/256, 256>>>((const float4*)q, (__nv_bfloat162*)pqhi, (__nv_bfloat162*)pqlo, n4_big);
    split_kernel<<<(n4_big + 255)/256, 256>>>((const float4*)k, (__nv_bfloat162*)pkhi, (__nv_bfloat162*)pklo, n4_big);
    split_kernel<<<(n4_w + 255)/256, 256>>>((const float4*)Wq, (__nv_bfloat162*)pwqhi, (__nv_bfloat162*)pwqlo, n4_w);
    split_kernel<<<(n4_w + 255)/256, 256>>>((const float4*)Wk, (__nv_bfloat162*)pwkhi, (__nv_bfloat162*)pwklo, n4_w);
    split_kernel<<<(n4_w + 255)/256, 256>>>((const float4*)Wo, (__nv_bfloat162*)pwohi, (__nv_bfloat162*)pwolo, n4_w);

    dim3 gg(E_/128, M_TOT/128);   // (8, 64)
    gemm_mma<1><<<gg, 256>>>(pqhi, pqlo, pwqhi, pwqlo, pQh);
    gemm_mma<1><<<gg, 256>>>(pkhi, pklo, pwkhi, pwklo, pKh);

    attn_kernel<<<dim3(32, B_*H_), 256, ATTN_SMEM>>>(pQh, pKh, pAO);

    split_kernel<<<(n4_big + 255)/256, 256>>>((const float4*)pAO, (__nv_bfloat162*)paohi, (__nv_bfloat162*)paolo, n4_big);
    gemm_mma<0><<<gg, 256>>>(paohi, paolo, pwohi, pwolo, out);
}

// round 5
// speedup vs baseline: 2.3748x; 1.5667x over previous
#include <cuda_runtime.h>
#include <cuda_bf16.h>
#include <math.h>
#include <stdint.h>

#define B_ 4
#define T_ 2048
#define E_ 1024
#define H_ 16
#define D_ 64
#define M_TOT (B_*T_)   // 8192

typedef __nv_bfloat16 bf16;
typedef __nv_bfloat162 bf162;

// ---------------- scratch (allocation-free) ----------------
__device__ __align__(16) bf16 g_qhi[M_TOT*E_], g_qlo[M_TOT*E_];     // input splits (E-major)
__device__ __align__(16) bf16 g_khi[M_TOT*E_], g_klo[M_TOT*E_];
__device__ __align__(16) bf16 g_wqhi[E_*E_],  g_wqlo[E_*E_];
__device__ __align__(16) bf16 g_wkhi[E_*E_],  g_wklo[E_*E_];
__device__ __align__(16) bf16 g_wohi[E_*E_],  g_wolo[E_*E_];
__device__ __align__(16) bf16 g_qhh[M_TOT*E_], g_qhl[M_TOT*E_];     // Q head [b,h,t,d] hi/lo (scaled 1/8)
__device__ __align__(16) bf16 g_khh[M_TOT*E_], g_khl[M_TOT*E_];     // K head hi/lo
__device__ __align__(16) bf16 g_aohi[M_TOT*E_], g_aolo[M_TOT*E_];   // attn out [b,t,(h d)] hi/lo

// ---------------- helpers ----------------
__device__ __forceinline__ uint32_t smem_u32(const void* p) {
    uint32_t a;
    asm("{ .reg .u64 t; cvta.to.shared.u64 t, %1; cvt.u32.u64 %0, t; }" : "=r"(a) : "l"(p));
    return a;
}
__device__ __forceinline__ void cp16(uint32_t saddr, const void* gaddr) {
    asm volatile("cp.async.cg.shared.global [%0], [%1], 16;" :: "r"(saddr), "l"(gaddr));
}
#define CP_COMMIT() asm volatile("cp.async.commit_group;" ::: "memory")
#define CP_WAIT(n)  asm volatile("cp.async.wait_group %0;" :: "n"(n) : "memory")

__device__ __forceinline__ void ldm_x4(uint32_t& r0, uint32_t& r1, uint32_t& r2, uint32_t& r3,
                                       uint32_t addr) {
    asm volatile("ldmatrix.sync.aligned.m8n8.x4.shared.b16 {%0,%1,%2,%3}, [%4];"
                 : "=r"(r0), "=r"(r1), "=r"(r2), "=r"(r3) : "r"(addr));
}
__device__ __forceinline__ void ldm_x4t(uint32_t& r0, uint32_t& r1, uint32_t& r2, uint32_t& r3,
                                        uint32_t addr) {
    asm volatile("ldmatrix.sync.aligned.m8n8.x4.trans.shared.b16 {%0,%1,%2,%3}, [%4];"
                 : "=r"(r0), "=r"(r1), "=r"(r2), "=r"(r3) : "r"(addr));
}
__device__ __forceinline__ void mma16816(float& d0, float& d1, float& d2, float& d3,
                                         uint32_t a0, uint32_t a1, uint32_t a2, uint32_t a3,
                                         uint32_t b0, uint32_t b1) {
    asm volatile("mma.sync.aligned.m16n8k16.row.col.f32.bf16.bf16.f32 "
                 "{%0,%1,%2,%3}, {%4,%5,%6,%7}, {%8,%9}, {%0,%1,%2,%3};"
                 : "+f"(d0), "+f"(d1), "+f"(d2), "+f"(d3)
                 : "r"(a0), "r"(a1), "r"(a2), "r"(a3), "r"(b0), "r"(b1));
}

// ---------------- fp32 -> bf16 hi/lo split ----------------
__global__ __launch_bounds__(256) void split_kernel(const float4* __restrict__ src,
                                                    bf162* __restrict__ hi,
                                                    bf162* __restrict__ lo,
                                                    int n4)
{
    int i = blockIdx.x * 256 + threadIdx.x;
    if (i >= n4) return;
    float4 v = src[i];
    bf16 h0 = __float2bfloat16_rn(v.x), h1 = __float2bfloat16_rn(v.y);
    bf16 h2 = __float2bfloat16_rn(v.z), h3 = __float2bfloat16_rn(v.w);
    bf16 l0 = __float2bfloat16_rn(v.x - __bfloat162float(h0));
    bf16 l1 = __float2bfloat16_rn(v.y - __bfloat162float(h1));
    bf16 l2 = __float2bfloat16_rn(v.z - __bfloat162float(h2));
    bf16 l3 = __float2bfloat16_rn(v.w - __bfloat162float(h3));
    hi[2*i]   = bf162(h0, h1);  hi[2*i+1] = bf162(h2, h3);
    lo[2*i]   = bf162(l0, l1);  lo[2*i+1] = bf162(l2, l3);
}

// ---------------------------------------------------------------------------
// HMMA GEMM: C = A @ W^T, bf16-split 3-pass.
// MODE 0: fp32 C flat [m][1024].  MODE 1: bf16 hi/lo head-split, scaled.
// ---------------------------------------------------------------------------
#define SROWB 80
#define TILEB (128 * SROWB)
#define NCHUNK 96

template<int MODE>
__global__ __launch_bounds__(256) void gemm_mma(const bf16* __restrict__ Ahi,
                                                const bf16* __restrict__ Alo,
                                                const bf16* __restrict__ Bhi,
                                                const bf16* __restrict__ Blo,
                                                float* __restrict__ Cf,
                                                bf16* __restrict__ Chi,
                                                bf16* __restrict__ Clo,
                                                float scale)
{
    __shared__ __align__(16) char smA[2][TILEB];
    __shared__ __align__(16) char smB[2][TILEB];

    const int tid = threadIdx.x;
    const int wid = tid >> 5, lid = tid & 31;
    const int warp_m = wid & 3, warp_n = wid >> 2;
    const int m0 = blockIdx.y * 128, n0 = blockIdx.x * 128;

    const char* Asel[3] = { (const char*)Ahi, (const char*)Ahi, (const char*)Alo };
    const char* Bsel[3] = { (const char*)Bhi, (const char*)Blo, (const char*)Bhi };
    const int gr = tid >> 2, gc = tid & 3;

    float acc[2][8][4];
    #pragma unroll
    for (int i = 0; i < 2; i++)
        #pragma unroll
        for (int j = 0; j < 8; j++)
            #pragma unroll
            for (int c = 0; c < 4; c++) acc[i][j][c] = 0.f;

    const uint32_t sA0 = smem_u32(smA[0]), sB0 = smem_u32(smB[0]);

    auto issue = [&](int chunk) {
        const int p = chunk >> 5, kc = chunk & 31;
        const int st = chunk & 1;
        const char* Ab = Asel[p];
        const char* Bb = Bsel[p];
        const size_t colB = (size_t)kc * 64;
        #pragma unroll
        for (int q = 0; q < 2; q++) {
            int r = gr + q * 64;
            cp16(sA0 + st * TILEB + r * SROWB + gc * 16,
                 Ab + (size_t)(m0 + r) * 2048 + colB + gc * 16);
            cp16(sB0 + st * TILEB + r * SROWB + gc * 16,
                 Bb + (size_t)(n0 + r) * 2048 + colB + gc * 16);
        }
        CP_COMMIT();
    };

    issue(0);
    for (int i = 0; i < NCHUNK; i++) {
        if (i + 1 < NCHUNK) { issue(i + 1); CP_WAIT(1); }
        else                { CP_WAIT(0); }
        __syncthreads();

        const int st = i & 1;
        const uint32_t bA = sA0 + st * TILEB;
        const uint32_t bB = sB0 + st * TILEB;
        const int lrow = lid & 15, lcol = (lid >> 4) * 16;

        #pragma unroll
        for (int s = 0; s < 2; s++) {
            uint32_t a[2][4];
            #pragma unroll
            for (int mt = 0; mt < 2; mt++) {
                uint32_t addr = bA + (warp_m*32 + mt*16 + lrow) * SROWB + s*32 + lcol;
                ldm_x4(a[mt][0], a[mt][1], a[mt][2], a[mt][3], addr);
            }
            uint32_t b[8][2];
            #pragma unroll
            for (int np = 0; np < 4; np++) {
                uint32_t r0, r1, r2, r3;
                uint32_t addr = bB + (warp_n*64 + np*16 + lrow) * SROWB + s*32 + lcol;
                ldm_x4(r0, r1, r2, r3, addr);
                b[np*2][0] = r0;   b[np*2][1] = r2;
                b[np*2+1][0] = r1; b[np*2+1][1] = r3;
            }
            #pragma unroll
            for (int mt = 0; mt < 2; mt++)
                #pragma unroll
                for (int nt = 0; nt < 8; nt++)
                    mma16816(acc[mt][nt][0], acc[mt][nt][1], acc[mt][nt][2], acc[mt][nt][3],
                             a[mt][0], a[mt][1], a[mt][2], a[mt][3],
                             b[nt][0], b[nt][1]);
        }
        __syncthreads();
    }

    const int gid = lid >> 2, tig = lid & 3;
    #pragma unroll
    for (int mt = 0; mt < 2; mt++) {
        #pragma unroll
        for (int nt = 0; nt < 8; nt++) {
            int m = m0 + warp_m*32 + mt*16 + gid;
            int n = n0 + warp_n*64 + nt*8 + tig*2;
            #pragma unroll
            for (int half = 0; half < 2; half++) {
                int mm = m + half * 8;
                float x0 = acc[mt][nt][half*2+0], x1 = acc[mt][nt][half*2+1];
                if (MODE == 0) {
                    *(float2*)(Cf + (size_t)mm * E_ + n) = make_float2(x0, x1);
                } else {
                    x0 *= scale; x1 *= scale;
                    bf16 h0 = __float2bfloat16_rn(x0), h1 = __float2bfloat16_rn(x1);
                    bf16 l0 = __float2bfloat16_rn(x0 - __bfloat162float(h0));
                    bf16 l1 = __float2bfloat16_rn(x1 - __bfloat162float(h1));
                    int b = mm >> 11, t = mm & (T_ - 1);
                    int h = n >> 6,  d = n & 63;
                    size_t idx = (((size_t)b * H_ + h) * T_ + t) * D_ + d;
                    *(bf162*)(Chi + idx) = bf162(h0, h1);
                    *(bf162*)(Clo + idx) = bf162(l0, l1);
                }
            }
        }
    }
}

// ---------------------------------------------------------------------------
// Causal flash attention, V == K (share_kv), bf16-split HMMA.
// CTA: 128 q-rows of one (b,h). 8 warps; warp w owns S rows w*16..w*16+15.
// ---------------------------------------------------------------------------
#define QSTRB 144                     // 72 bf16/row (64 data + 8 pad)
#define PSTRB 272                     // 136 bf16/row (128 data + 8 pad)
#define SM_QHI 0
#define SM_QLO (128*QSTRB)
#define SM_KHI (2*128*QSTRB)
#define SM_KLO (3*128*QSTRB)
#define SM_P   (4*128*QSTRB)
#define ATTN_SMEM (4*128*QSTRB + 128*PSTRB)   // 108544

__global__ __launch_bounds__(256) void attn_mma(const bf16* __restrict__ qhh,
                                                const bf16* __restrict__ qhl,
                                                const bf16* __restrict__ khh,
                                                const bf16* __restrict__ khl,
                                                bf16* __restrict__ aohi,
                                                bf16* __restrict__ aolo)
{
    extern __shared__ __align__(16) char smem[];
    const uint32_t sb = smem_u32(smem);
    const int tid = threadIdx.x;
    const int wid = tid >> 5, lid = tid & 31;
    const int wrow = wid * 16;
    const int gid = lid >> 2, tig = lid & 3;
    const int lrow = lid & 15, lcol = (lid >> 4) * 16;
    const int qt = 15 - (int)blockIdx.x;     // heavy tiles first
    const int bh = blockIdx.y;

    const char* Qhi = (const char*)(qhh + (size_t)bh * T_ * D_ + (size_t)qt * 128 * D_);
    const char* Qlo = (const char*)(qhl + (size_t)bh * T_ * D_ + (size_t)qt * 128 * D_);
    const char* Khi = (const char*)(khh + (size_t)bh * T_ * D_);
    const char* Klo = (const char*)(khl + (size_t)bh * T_ * D_);

    // load Q tiles (hi/lo), 128 rows x 128B
    #pragma unroll
    for (int i = 0; i < 4; i++) {
        int idx = tid + i * 256;
        int r = idx >> 3, c = (idx & 7) * 16;
        cp16(sb + SM_QHI + r * QSTRB + c, Qhi + (size_t)r * 128 + c);
        cp16(sb + SM_QLO + r * QSTRB + c, Qlo + (size_t)r * 128 + c);
    }
    CP_COMMIT();

    float mrow[2] = {-1e30f, -1e30f};
    float lrow_[2] = {0.f, 0.f};
    float o[8][4];
    #pragma unroll
    for (int nt = 0; nt < 8; nt++)
        #pragma unroll
        for (int c = 0; c < 4; c++) o[nt][c] = 0.f;

    for (int kt = 0; kt <= qt; kt++) {
        __syncthreads();                      // prev PV done with K smem
        #pragma unroll
        for (int i = 0; i < 4; i++) {
            int idx = tid + i * 256;
            int r = idx >> 3, c = (idx & 7) * 16;
            cp16(sb + SM_KHI + r * QSTRB + c, Khi + ((size_t)kt * 128 + r) * 128 + c);
            cp16(sb + SM_KLO + r * QSTRB + c, Klo + ((size_t)kt * 128 + r) * 128 + c);
        }
        CP_COMMIT();
        CP_WAIT(0);
        __syncthreads();

        // ---- S = Qs @ K^T : 3 passes ----
        float s[16][4];
        #pragma unroll
        for (int nt = 0; nt < 16; nt++)
            #pragma unroll
            for (int c = 0; c < 4; c++) s[nt][c] = 0.f;

        #pragma unroll
        for (int pass = 0; pass < 3; pass++) {
            const uint32_t bAq = sb + (pass == 2 ? SM_QLO : SM_QHI);
            const uint32_t bBk = sb + (pass == 1 ? SM_KLO : SM_KHI);
            #pragma unroll
            for (int ks = 0; ks < 4; ks++) {
                uint32_t a0,a1,a2,a3;
                ldm_x4(a0,a1,a2,a3, bAq + (wrow + lrow) * QSTRB + ks*32 + lcol);
                uint32_t b[16][2];
                #pragma unroll
                for (int np = 0; np < 8; np++) {
                    uint32_t r0,r1,r2,r3;
                    ldm_x4(r0,r1,r2,r3, bBk + (np*16 + lrow) * QSTRB + ks*32 + lcol);
                    b[np*2][0] = r0;   b[np*2][1] = r2;
                    b[np*2+1][0] = r1; b[np*2+1][1] = r3;
                }
                #pragma unroll
                for (int nt = 0; nt < 16; nt++)
                    mma16816(s[nt][0], s[nt][1], s[nt][2], s[nt][3],
                             a0, a1, a2, a3, b[nt][0], b[nt][1]);
            }
        }

        // ---- causal mask on diagonal tile ----
        if (kt == qt) {
            #pragma unroll
            for (int nt = 0; nt < 16; nt++)
                #pragma unroll
                for (int c = 0; c < 4; c++) {
                    int row = wrow + gid + (c >> 1) * 8;
                    int col = nt*8 + tig*2 + (c & 1);
                    if (col > row) s[nt][c] = -1e30f;
                }
        }

        // ---- online softmax (per row half) ----
        #pragma unroll
        for (int r = 0; r < 2; r++) {
            float mx = -1e30f;
            #pragma unroll
            for (int nt = 0; nt < 16; nt++)
                mx = fmaxf(mx, fmaxf(s[nt][r*2], s[nt][r*2+1]));
            mx = fmaxf(mx, __shfl_xor_sync(0xffffffffu, mx, 1));
            mx = fmaxf(mx, __shfl_xor_sync(0xffffffffu, mx, 2));
            float mnew = fmaxf(mrow[r], mx);
            float psum = 0.f;
            #pragma unroll
            for (int nt = 0; nt < 16; nt++) {
                float p0 = __expf(s[nt][r*2]   - mnew);
                float p1 = __expf(s[nt][r*2+1] - mnew);
                s[nt][r*2] = p0; s[nt][r*2+1] = p1;
                psum += p0 + p1;
            }
            psum += __shfl_xor_sync(0xffffffffu, psum, 1);
            psum += __shfl_xor_sync(0xffffffffu, psum, 2);
            float corr = __expf(mrow[r] - mnew);
            lrow_[r] = lrow_[r] * corr + psum;
            mrow[r] = mnew;
            #pragma unroll
            for (int nt = 0; nt < 8; nt++) {
                o[nt][r*2]   *= corr;
                o[nt][r*2+1] *= corr;
            }
        }

        // ---- write P_hi; PV passes hi (Vhi + Vlo) ----
        #pragma unroll
        for (int nt = 0; nt < 16; nt++)
            #pragma unroll
            for (int r = 0; r < 2; r++) {
                bf162 hv(__float2bfloat16_rn(s[nt][r*2]), __float2bfloat16_rn(s[nt][r*2+1]));
                *(bf162*)(smem + SM_P + (wrow + gid + r*8) * PSTRB + nt*16 + tig*4) = hv;
            }
        __syncwarp();
        #pragma unroll
        for (int ks = 0; ks < 8; ks++) {
            uint32_t a0,a1,a2,a3;
            ldm_x4(a0,a1,a2,a3, sb + SM_P + (wrow + lrow) * PSTRB + ks*32 + lcol);
            #pragma unroll
            for (int hl = 0; hl < 2; hl++) {
                const uint32_t bV = sb + (hl ? SM_KLO : SM_KHI);
                #pragma unroll
                for (int nb = 0; nb < 4; nb++) {
                    uint32_t r0,r1,r2,r3;
                    ldm_x4t(r0,r1,r2,r3, bV + (ks*16 + lrow) * QSTRB + nb*32 + lcol);
                    mma16816(o[nb*2][0],   o[nb*2][1],   o[nb*2][2],   o[nb*2][3],
                             a0,a1,a2,a3, r0, r1);
                    mma16816(o[nb*2+1][0], o[nb*2+1][1], o[nb*2+1][2], o[nb*2+1][3],
                             a0,a1,a2,a3, r2, r3);
                }
            }
        }
        __syncwarp();

        // ---- write P_lo; PV pass lo·Vhi ----
        #pragma unroll
        for (int nt = 0; nt < 16; nt++)
            #pragma unroll
            for (int r = 0; r < 2; r++) {
                float p0 = s[nt][r*2], p1 = s[nt][r*2+1];
                bf16 h0 = __float2bfloat16_rn(p0), h1 = __float2bfloat16_rn(p1);
                bf162 lv(__float2bfloat16_rn(p0 - __bfloat162float(h0)),
                         __float2bfloat16_rn(p1 - __bfloat162float(h1)));
                *(bf162*)(smem + SM_P + (wrow + gid + r*8) * PSTRB + nt*16 + tig*4) = lv;
            }
        __syncwarp();
        #pragma unroll
        for (int ks = 0; ks < 8; ks++) {
            uint32_t a0,a1,a2,a3;
            ldm_x4(a0,a1,a2,a3, sb + SM_P + (wrow + lrow) * PSTRB + ks*32 + lcol);
            #pragma unroll
            for (int nb = 0; nb < 4; nb++) {
                uint32_t r0,r1,r2,r3;
                ldm_x4t(r0,r1,r2,r3, sb + SM_KHI + (ks*16 + lrow) * QSTRB + nb*32 + lcol);
                mma16816(o[nb*2][0],   o[nb*2][1],   o[nb*2][2],   o[nb*2][3],
                         a0,a1,a2,a3, r0, r1);
                mma16816(o[nb*2+1][0], o[nb*2+1][1], o[nb*2+1][2], o[nb*2+1][3],
                         a0,a1,a2,a3, r2, r3);
            }
        }
    }

    // ---- epilogue: normalize, split, write [b,t,(h d)] ----
    const int b = bh >> 4, h = bh & 15;
    #pragma unroll
    for (int r = 0; r < 2; r++) {
        float inv = 1.0f / lrow_[r];
        int t = qt*128 + wrow + gid + r*8;
        #pragma unroll
        for (int nt = 0; nt < 8; nt++) {
            float x0 = o[nt][r*2] * inv, x1 = o[nt][r*2+1] * inv;
            bf16 h0 = __float2bfloat16_rn(x0), h1 = __float2bfloat16_rn(x1);
            bf16 l0 = __float2bfloat16_rn(x0 - __bfloat162float(h0));
            bf16 l1 = __float2bfloat16_rn(x1 - __bfloat162float(h1));
            size_t idx = ((size_t)b * T_ + t) * E_ + h*64 + nt*8 + tig*2;
            *(bf162*)(aohi + idx) = bf162(h0, h1);
            *(bf162*)(aolo + idx) = bf162(l0, l1);
        }
    }
}

// ---------------------------------------------------------------------------
extern "C" void kernel_launch(void* const* d_in, const int* in_sizes, int n_in,
                              void* d_out, int out_size)
{
    const float* q  = (const float*)d_in[0];
    const float* k  = (const float*)d_in[1];
    // d_in[2] (v) dead: share_kv
    const float* Wq = (const float*)d_in[3];
    const float* Wk = (const float*)d_in[4];
    const float* Wo = (const float*)d_in[5];
    float* out = (float*)d_out;

    bf16 *pqhi,*pqlo,*pkhi,*pklo,*pwqhi,*pwqlo,*pwkhi,*pwklo,*pwohi,*pwolo;
    bf16 *pqhh,*pqhl,*pkhh,*pkhl,*paohi,*paolo;
    cudaGetSymbolAddress((void**)&pqhi, g_qhi);   cudaGetSymbolAddress((void**)&pqlo, g_qlo);
    cudaGetSymbolAddress((void**)&pkhi, g_khi);   cudaGetSymbolAddress((void**)&pklo, g_klo);
    cudaGetSymbolAddress((void**)&pwqhi, g_wqhi); cudaGetSymbolAddress((void**)&pwqlo, g_wqlo);
    cudaGetSymbolAddress((void**)&pwkhi, g_wkhi); cudaGetSymbolAddress((void**)&pwklo, g_wklo);
    cudaGetSymbolAddress((void**)&pwohi, g_wohi); cudaGetSymbolAddress((void**)&pwolo, g_wolo);
    cudaGetSymbolAddress((void**)&pqhh, g_qhh);   cudaGetSymbolAddress((void**)&pqhl, g_qhl);
    cudaGetSymbolAddress((void**)&pkhh, g_khh);   cudaGetSymbolAddress((void**)&pkhl, g_khl);
    cudaGetSymbolAddress((void**)&paohi, g_aohi); cudaGetSymbolAddress((void**)&paolo, g_aolo);

    static bool attr_done = false;
    if (!attr_done) {
        cudaFuncSetAttribute(attn_mma, cudaFuncAttributeMaxDynamicSharedMemorySize, ATTN_SMEM);
        attr_done = true;
    }

    const int n4_big = M_TOT * E_ / 4;
    const int n4_w   = E_ * E_ / 4;
    split_kernel<<<(n4_big + 255)/256, 256>>>((const float4*)q, (bf162*)pqhi, (bf162*)pqlo, n4_big);
    split_kernel<<<(n4_big + 255)/256, 256>>>((const float4*)k, (bf162*)pkhi, (bf162*)pklo, n4_big);
    split_kernel<<<(n4_w + 255)/256, 256>>>((const float4*)Wq, (bf162*)pwqhi, (bf162*)pwqlo, n4_w);
    split_kernel<<<(n4_w + 255)/256, 256>>>((const float4*)Wk, (bf162*)pwkhi, (bf162*)pwklo, n4_w);
    split_kernel<<<(n4_w + 255)/256, 256>>>((const float4*)Wo, (bf162*)pwohi, (bf162*)pwolo, n4_w);

    dim3 gg(E_/128, M_TOT/128);   // (8, 64)
    gemm_mma<1><<<gg, 256>>>(pqhi, pqlo, pwqhi, pwqlo, nullptr, pqhh, pqhl, 0.125f);
    gemm_mma<1><<<gg, 256>>>(pkhi, pklo, pwkhi, pwklo, nullptr, pkhh, pkhl, 1.0f);

    attn_mma<<<dim3(16, B_*H_), 256, ATTN_SMEM>>>(pqhh, pqhl, pkhh, pkhl, paohi, paolo);

    gemm_mma<0><<<gg, 256>>>(paohi, paolo, pwohi, pwolo, out, nullptr, nullptr, 1.0f);
}

// round 6
// speedup vs baseline: 2.4409x; 1.0278x over previous
#include <cuda_runtime.h>
#include <cuda_bf16.h>
#include <math.h>
#include <stdint.h>

#define B_ 4
#define T_ 2048
#define E_ 1024
#define H_ 16
#define D_ 64
#define M_TOT (B_*T_)   // 8192

typedef __nv_bfloat16 bf16;
typedef __nv_bfloat162 bf162;

// ---------------- scratch (allocation-free) ----------------
__device__ __align__(16) bf16 g_qhi[M_TOT*E_], g_qlo[M_TOT*E_];     // input splits (E-major)
__device__ __align__(16) bf16 g_khi[M_TOT*E_], g_klo[M_TOT*E_];
__device__ __align__(16) bf16 g_wqhi[E_*E_],  g_wqlo[E_*E_];
__device__ __align__(16) bf16 g_wkhi[E_*E_],  g_wklo[E_*E_];
__device__ __align__(16) bf16 g_wohi[E_*E_],  g_wolo[E_*E_];
__device__ __align__(16) bf16 g_qhh[M_TOT*E_], g_qhl[M_TOT*E_];     // Q head [b,h,t,d] hi/lo (scaled 1/8)
__device__ __align__(16) bf16 g_khh[M_TOT*E_], g_khl[M_TOT*E_];     // K head hi/lo
__device__ __align__(16) bf16 g_aohi[M_TOT*E_], g_aolo[M_TOT*E_];   // attn out [b,t,(h d)] hi/lo

// ---------------- helpers ----------------
__device__ __forceinline__ uint32_t smem_u32(const void* p) {
    uint32_t a;
    asm("{ .reg .u64 t; cvta.to.shared.u64 t, %1; cvt.u32.u64 %0, t; }" : "=r"(a) : "l"(p));
    return a;
}
__device__ __forceinline__ void cp16(uint32_t saddr, const void* gaddr) {
    asm volatile("cp.async.cg.shared.global [%0], [%1], 16;" :: "r"(saddr), "l"(gaddr));
}
#define CP_COMMIT() asm volatile("cp.async.commit_group;" ::: "memory")
#define CP_WAIT(n)  asm volatile("cp.async.wait_group %0;" :: "n"(n) : "memory")

__device__ __forceinline__ void ldm_x4(uint32_t& r0, uint32_t& r1, uint32_t& r2, uint32_t& r3,
                                       uint32_t addr) {
    asm volatile("ldmatrix.sync.aligned.m8n8.x4.shared.b16 {%0,%1,%2,%3}, [%4];"
                 : "=r"(r0), "=r"(r1), "=r"(r2), "=r"(r3) : "r"(addr));
}
__device__ __forceinline__ void ldm_x4t(uint32_t& r0, uint32_t& r1, uint32_t& r2, uint32_t& r3,
                                        uint32_t addr) {
    asm volatile("ldmatrix.sync.aligned.m8n8.x4.trans.shared.b16 {%0,%1,%2,%3}, [%4];"
                 : "=r"(r0), "=r"(r1), "=r"(r2), "=r"(r3) : "r"(addr));
}
__device__ __forceinline__ void mma16816(float& d0, float& d1, float& d2, float& d3,
                                         uint32_t a0, uint32_t a1, uint32_t a2, uint32_t a3,
                                         uint32_t b0, uint32_t b1) {
    asm volatile("mma.sync.aligned.m16n8k16.row.col.f32.bf16.bf16.f32 "
                 "{%0,%1,%2,%3}, {%4,%5,%6,%7}, {%8,%9}, {%0,%1,%2,%3};"
                 : "+f"(d0), "+f"(d1), "+f"(d2), "+f"(d3)
                 : "r"(a0), "r"(a1), "r"(a2), "r"(a3), "r"(b0), "r"(b1));
}

// ---------------- fp32 -> bf16 hi/lo split ----------------
__global__ __launch_bounds__(256) void split_kernel(const float4* __restrict__ src,
                                                    bf162* __restrict__ hi,
                                                    bf162* __restrict__ lo,
                                                    int n4)
{
    int i = blockIdx.x * 256 + threadIdx.x;
    if (i >= n4) return;
    float4 v = src[i];
    bf16 h0 = __float2bfloat16_rn(v.x), h1 = __float2bfloat16_rn(v.y);
    bf16 h2 = __float2bfloat16_rn(v.z), h3 = __float2bfloat16_rn(v.w);
    bf16 l0 = __float2bfloat16_rn(v.x - __bfloat162float(h0));
    bf16 l1 = __float2bfloat16_rn(v.y - __bfloat162float(h1));
    bf16 l2 = __float2bfloat16_rn(v.z - __bfloat162float(h2));
    bf16 l3 = __float2bfloat16_rn(v.w - __bfloat162float(h3));
    hi[2*i]   = bf162(h0, h1);  hi[2*i+1] = bf162(h2, h3);
    lo[2*i]   = bf162(l0, l1);  lo[2*i+1] = bf162(l2, l3);
}

// ---------------------------------------------------------------------------
// HMMA GEMM: C = A @ W^T, bf16-split 3-pass.  (unchanged from round 5)
// ---------------------------------------------------------------------------
#define SROWB 80
#define TILEB (128 * SROWB)
#define NCHUNK 96

template<int MODE>
__global__ __launch_bounds__(256) void gemm_mma(const bf16* __restrict__ Ahi,
                                                const bf16* __restrict__ Alo,
                                                const bf16* __restrict__ Bhi,
                                                const bf16* __restrict__ Blo,
                                                float* __restrict__ Cf,
                                                bf16* __restrict__ Chi,
                                                bf16* __restrict__ Clo,
                                                float scale)
{
    __shared__ __align__(16) char smA[2][TILEB];
    __shared__ __align__(16) char smB[2][TILEB];

    const int tid = threadIdx.x;
    const int wid = tid >> 5, lid = tid & 31;
    const int warp_m = wid & 3, warp_n = wid >> 2;
    const int m0 = blockIdx.y * 128, n0 = blockIdx.x * 128;

    const char* Asel[3] = { (const char*)Ahi, (const char*)Ahi, (const char*)Alo };
    const char* Bsel[3] = { (const char*)Bhi, (const char*)Blo, (const char*)Bhi };
    const int gr = tid >> 2, gc = tid & 3;

    float acc[2][8][4];
    #pragma unroll
    for (int i = 0; i < 2; i++)
        #pragma unroll
        for (int j = 0; j < 8; j++)
            #pragma unroll
            for (int c = 0; c < 4; c++) acc[i][j][c] = 0.f;

    const uint32_t sA0 = smem_u32(smA[0]), sB0 = smem_u32(smB[0]);

    auto issue = [&](int chunk) {
        const int p = chunk >> 5, kc = chunk & 31;
        const int st = chunk & 1;
        const char* Ab = Asel[p];
        const char* Bb = Bsel[p];
        const size_t colB = (size_t)kc * 64;
        #pragma unroll
        for (int q = 0; q < 2; q++) {
            int r = gr + q * 64;
            cp16(sA0 + st * TILEB + r * SROWB + gc * 16,
                 Ab + (size_t)(m0 + r) * 2048 + colB + gc * 16);
            cp16(sB0 + st * TILEB + r * SROWB + gc * 16,
                 Bb + (size_t)(n0 + r) * 2048 + colB + gc * 16);
        }
        CP_COMMIT();
    };

    issue(0);
    for (int i = 0; i < NCHUNK; i++) {
        if (i + 1 < NCHUNK) { issue(i + 1); CP_WAIT(1); }
        else                { CP_WAIT(0); }
        __syncthreads();

        const int st = i & 1;
        const uint32_t bA = sA0 + st * TILEB;
        const uint32_t bB = sB0 + st * TILEB;
        const int lrow = lid & 15, lcol = (lid >> 4) * 16;

        #pragma unroll
        for (int s = 0; s < 2; s++) {
            uint32_t a[2][4];
            #pragma unroll
            for (int mt = 0; mt < 2; mt++) {
                uint32_t addr = bA + (warp_m*32 + mt*16 + lrow) * SROWB + s*32 + lcol;
                ldm_x4(a[mt][0], a[mt][1], a[mt][2], a[mt][3], addr);
            }
            uint32_t b[8][2];
            #pragma unroll
            for (int np = 0; np < 4; np++) {
                uint32_t r0, r1, r2, r3;
                uint32_t addr = bB + (warp_n*64 + np*16 + lrow) * SROWB + s*32 + lcol;
                ldm_x4(r0, r1, r2, r3, addr);
                b[np*2][0] = r0;   b[np*2][1] = r2;
                b[np*2+1][0] = r1; b[np*2+1][1] = r3;
            }
            #pragma unroll
            for (int mt = 0; mt < 2; mt++)
                #pragma unroll
                for (int nt = 0; nt < 8; nt++)
                    mma16816(acc[mt][nt][0], acc[mt][nt][1], acc[mt][nt][2], acc[mt][nt][3],
                             a[mt][0], a[mt][1], a[mt][2], a[mt][3],
                             b[nt][0], b[nt][1]);
        }
        __syncthreads();
    }

    const int gid = lid >> 2, tig = lid & 3;
    #pragma unroll
    for (int mt = 0; mt < 2; mt++) {
        #pragma unroll
        for (int nt = 0; nt < 8; nt++) {
            int m = m0 + warp_m*32 + mt*16 + gid;
            int n = n0 + warp_n*64 + nt*8 + tig*2;
            #pragma unroll
            for (int half = 0; half < 2; half++) {
                int mm = m + half * 8;
                float x0 = acc[mt][nt][half*2+0], x1 = acc[mt][nt][half*2+1];
                if (MODE == 0) {
                    *(float2*)(Cf + (size_t)mm * E_ + n) = make_float2(x0, x1);
                } else {
                    x0 *= scale; x1 *= scale;
                    bf16 h0 = __float2bfloat16_rn(x0), h1 = __float2bfloat16_rn(x1);
                    bf16 l0 = __float2bfloat16_rn(x0 - __bfloat162float(h0));
                    bf16 l1 = __float2bfloat16_rn(x1 - __bfloat162float(h1));
                    int b = mm >> 11, t = mm & (T_ - 1);
                    int h = n >> 6,  d = n & 63;
                    size_t idx = (((size_t)b * H_ + h) * T_ + t) * D_ + d;
                    *(bf162*)(Chi + idx) = bf162(h0, h1);
                    *(bf162*)(Clo + idx) = bf162(l0, l1);
                }
            }
        }
    }
}

// ---------------------------------------------------------------------------
// Causal flash attention, V == K (share_kv), bf16-split HMMA.
// Round 6: K double-buffered (cp.async issue-ahead), Q fragments preloaded to
// registers from global, K/V fragment reuse across hi/lo passes, dual P buffers.
// ---------------------------------------------------------------------------
#define QSTRB 144                     // 72 bf16/row (64 data + 8 pad)
#define PSTRB 272                     // 136 bf16/row (128 data + 8 pad)
#define KSTG  (128*QSTRB)             // 18432 B per K operand tile
#define SM_KHI(st) ((st)*2*KSTG)
#define SM_KLO(st) ((st)*2*KSTG + KSTG)
#define SM_PHI (4*KSTG)               // 73728
#define SM_PLO (SM_PHI + 128*PSTRB)   // 108544
#define ATTN_SMEM (SM_PLO + 128*PSTRB) // 143360

__global__ __launch_bounds__(256) void attn_mma(const bf16* __restrict__ qhh,
                                                const bf16* __restrict__ qhl,
                                                const bf16* __restrict__ khh,
                                                const bf16* __restrict__ khl,
                                                bf16* __restrict__ aohi,
                                                bf16* __restrict__ aolo)
{
    extern __shared__ __align__(16) char smem[];
    const uint32_t sb = smem_u32(smem);
    const int tid = threadIdx.x;
    const int wid = tid >> 5, lid = tid & 31;
    const int wrow = wid * 16;
    const int gid = lid >> 2, tig = lid & 3;
    const int lrow = lid & 15, lcol = (lid >> 4) * 16;
    const int qt = 15 - (int)blockIdx.x;     // heavy tiles first
    const int bh = blockIdx.y;

    const char* Khi = (const char*)(khh + (size_t)bh * T_ * D_);
    const char* Klo = (const char*)(khl + (size_t)bh * T_ * D_);

    auto issueK = [&](int kt, int st) {
        #pragma unroll
        for (int i = 0; i < 4; i++) {
            int idx = tid + i * 256;
            int r = idx >> 3, c = (idx & 7) * 16;
            cp16(sb + SM_KHI(st) + r * QSTRB + c, Khi + ((size_t)kt * 128 + r) * 128 + c);
            cp16(sb + SM_KLO(st) + r * QSTRB + c, Klo + ((size_t)kt * 128 + r) * 128 + c);
        }
        CP_COMMIT();
    };

    issueK(0, 0);

    // ---- preload Q fragments (hi/lo) straight from global ----
    uint32_t qh[4][4], ql[4][4];
    {
        const bf16* Qgh = qhh + (size_t)bh * T_ * D_ + (size_t)(qt * 128 + wrow) * D_;
        const bf16* Qgl = qhl + (size_t)bh * T_ * D_ + (size_t)(qt * 128 + wrow) * D_;
        #pragma unroll
        for (int ks = 0; ks < 4; ks++) {
            int c0 = ks * 16 + tig * 2;
            qh[ks][0] = *(const uint32_t*)(Qgh + (size_t)gid * D_ + c0);
            qh[ks][1] = *(const uint32_t*)(Qgh + (size_t)(gid + 8) * D_ + c0);
            qh[ks][2] = *(const uint32_t*)(Qgh + (size_t)gid * D_ + c0 + 8);
            qh[ks][3] = *(const uint32_t*)(Qgh + (size_t)(gid + 8) * D_ + c0 + 8);
            ql[ks][0] = *(const uint32_t*)(Qgl + (size_t)gid * D_ + c0);
            ql[ks][1] = *(const uint32_t*)(Qgl + (size_t)(gid + 8) * D_ + c0);
            ql[ks][2] = *(const uint32_t*)(Qgl + (size_t)gid * D_ + c0 + 8);
            ql[ks][3] = *(const uint32_t*)(Qgl + (size_t)(gid + 8) * D_ + c0 + 8);
        }
    }

    float mrow[2] = {-1e30f, -1e30f};
    float lrow_[2] = {0.f, 0.f};
    float o[8][4];
    #pragma unroll
    for (int nt = 0; nt < 8; nt++)
        #pragma unroll
        for (int c = 0; c < 4; c++) o[nt][c] = 0.f;

    for (int kt = 0; kt <= qt; kt++) {
        const int st = kt & 1;
        if (kt < qt) { issueK(kt + 1, st ^ 1); CP_WAIT(1); }
        else         { CP_WAIT(0); }
        __syncthreads();

        // ---- S = Qs @ K^T: K-frag reuse, 3 logical passes ----
        float s[16][4];
        #pragma unroll
        for (int nt = 0; nt < 16; nt++)
            #pragma unroll
            for (int c = 0; c < 4; c++) s[nt][c] = 0.f;

        #pragma unroll
        for (int ks = 0; ks < 4; ks++) {
            uint32_t b[16][2];
            // K-hi fragments, used by both Qhi and Qlo
            #pragma unroll
            for (int np = 0; np < 8; np++) {
                uint32_t r0,r1,r2,r3;
                ldm_x4(r0,r1,r2,r3, sb + SM_KHI(st) + (np*16 + lrow) * QSTRB + ks*32 + lcol);
                b[np*2][0] = r0;   b[np*2][1] = r2;
                b[np*2+1][0] = r1; b[np*2+1][1] = r3;
            }
            #pragma unroll
            for (int nt = 0; nt < 16; nt++)
                mma16816(s[nt][0], s[nt][1], s[nt][2], s[nt][3],
                         qh[ks][0], qh[ks][1], qh[ks][2], qh[ks][3], b[nt][0], b[nt][1]);
            #pragma unroll
            for (int nt = 0; nt < 16; nt++)
                mma16816(s[nt][0], s[nt][1], s[nt][2], s[nt][3],
                         ql[ks][0], ql[ks][1], ql[ks][2], ql[ks][3], b[nt][0], b[nt][1]);
            // K-lo fragments, used by Qhi
            #pragma unroll
            for (int np = 0; np < 8; np++) {
                uint32_t r0,r1,r2,r3;
                ldm_x4(r0,r1,r2,r3, sb + SM_KLO(st) + (np*16 + lrow) * QSTRB + ks*32 + lcol);
                b[np*2][0] = r0;   b[np*2][1] = r2;
                b[np*2+1][0] = r1; b[np*2+1][1] = r3;
            }
            #pragma unroll
            for (int nt = 0; nt < 16; nt++)
                mma16816(s[nt][0], s[nt][1], s[nt][2], s[nt][3],
                         qh[ks][0], qh[ks][1], qh[ks][2], qh[ks][3], b[nt][0], b[nt][1]);
        }

        // ---- causal mask on diagonal tile ----
        if (kt == qt) {
            #pragma unroll
            for (int nt = 0; nt < 16; nt++)
                #pragma unroll
                for (int c = 0; c < 4; c++) {
                    int row = wrow + gid + (c >> 1) * 8;
                    int col = nt*8 + tig*2 + (c & 1);
                    if (col > row) s[nt][c] = -1e30f;
                }
        }

        // ---- online softmax (per row half) ----
        #pragma unroll
        for (int r = 0; r < 2; r++) {
            float mx = -1e30f;
            #pragma unroll
            for (int nt = 0; nt < 16; nt++)
                mx = fmaxf(mx, fmaxf(s[nt][r*2], s[nt][r*2+1]));
            mx = fmaxf(mx, __shfl_xor_sync(0xffffffffu, mx, 1));
            mx = fmaxf(mx, __shfl_xor_sync(0xffffffffu, mx, 2));
            float mnew = fmaxf(mrow[r], mx);
            float psum = 0.f;
            #pragma unroll
            for (int nt = 0; nt < 16; nt++) {
                float p0 = __expf(s[nt][r*2]   - mnew);
                float p1 = __expf(s[nt][r*2+1] - mnew);
                s[nt][r*2] = p0; s[nt][r*2+1] = p1;
                psum += p0 + p1;
            }
            psum += __shfl_xor_sync(0xffffffffu, psum, 1);
            psum += __shfl_xor_sync(0xffffffffu, psum, 2);
            float corr = __expf(mrow[r] - mnew);
            lrow_[r] = lrow_[r] * corr + psum;
            mrow[r] = mnew;
            #pragma unroll
            for (int nt = 0; nt < 8; nt++) {
                o[nt][r*2]   *= corr;
                o[nt][r*2+1] *= corr;
            }
        }

        // ---- stage P hi and lo simultaneously (dual buffers) ----
        #pragma unroll
        for (int nt = 0; nt < 16; nt++)
            #pragma unroll
            for (int r = 0; r < 2; r++) {
                float p0 = s[nt][r*2], p1 = s[nt][r*2+1];
                bf16 h0 = __float2bfloat16_rn(p0), h1 = __float2bfloat16_rn(p1);
                uint32_t rowoff = (wrow + gid + r*8) * PSTRB + nt*16 + tig*4;
                *(bf162*)(smem + SM_PHI + rowoff) = bf162(h0, h1);
                *(bf162*)(smem + SM_PLO + rowoff) =
                    bf162(__float2bfloat16_rn(p0 - __bfloat162float(h0)),
                          __float2bfloat16_rn(p1 - __bfloat162float(h1)));
            }
        __syncwarp();

        // ---- PV: V-frag reuse across Phi and Plo ----
        #pragma unroll
        for (int ks = 0; ks < 8; ks++) {
            uint32_t pa0,pa1,pa2,pa3, pb0,pb1,pb2,pb3;
            ldm_x4(pa0,pa1,pa2,pa3, sb + SM_PHI + (wrow + lrow) * PSTRB + ks*32 + lcol);
            ldm_x4(pb0,pb1,pb2,pb3, sb + SM_PLO + (wrow + lrow) * PSTRB + ks*32 + lcol);
            #pragma unroll
            for (int nb = 0; nb < 4; nb++) {
                uint32_t r0,r1,r2,r3;
                ldm_x4t(r0,r1,r2,r3, sb + SM_KHI(st) + (ks*16 + lrow) * QSTRB + nb*32 + lcol);
                mma16816(o[nb*2][0],   o[nb*2][1],   o[nb*2][2],   o[nb*2][3],
                         pa0,pa1,pa2,pa3, r0, r1);
                mma16816(o[nb*2+1][0], o[nb*2+1][1], o[nb*2+1][2], o[nb*2+1][3],
                         pa0,pa1,pa2,pa3, r2, r3);
                mma16816(o[nb*2][0],   o[nb*2][1],   o[nb*2][2],   o[nb*2][3],
                         pb0,pb1,pb2,pb3, r0, r1);
                mma16816(o[nb*2+1][0], o[nb*2+1][1], o[nb*2+1][2], o[nb*2+1][3],
                         pb0,pb1,pb2,pb3, r2, r3);
            }
            #pragma unroll
            for (int nb = 0; nb < 4; nb++) {
                uint32_t r0,r1,r2,r3;
                ldm_x4t(r0,r1,r2,r3, sb + SM_KLO(st) + (ks*16 + lrow) * QSTRB + nb*32 + lcol);
                mma16816(o[nb*2][0],   o[nb*2][1],   o[nb*2][2],   o[nb*2][3],
                         pa0,pa1,pa2,pa3, r0, r1);
                mma16816(o[nb*2+1][0], o[nb*2+1][1], o[nb*2+1][2], o[nb*2+1][3],
                         pa0,pa1,pa2,pa3, r2, r3);
            }
        }
        __syncthreads();   // all warps done with stage st before it is overwritten
    }

    // ---- epilogue: normalize, split, write [b,t,(h d)] ----
    const int b = bh >> 4, h = bh & 15;
    #pragma unroll
    for (int r = 0; r < 2; r++) {
        float inv = 1.0f / lrow_[r];
        int t = qt*128 + wrow + gid + r*8;
        #pragma unroll
        for (int nt = 0; nt < 8; nt++) {
            float x0 = o[nt][r*2] * inv, x1 = o[nt][r*2+1] * inv;
            bf16 h0 = __float2bfloat16_rn(x0), h1 = __float2bfloat16_rn(x1);
            bf16 l0 = __float2bfloat16_rn(x0 - __bfloat162float(h0));
            bf16 l1 = __float2bfloat16_rn(x1 - __bfloat162float(h1));
            size_t idx = ((size_t)b * T_ + t) * E_ + h*64 + nt*8 + tig*2;
            *(bf162*)(aohi + idx) = bf162(h0, h1);
            *(bf162*)(aolo + idx) = bf162(l0, l1);
        }
    }
}

// ---------------------------------------------------------------------------
extern "C" void kernel_launch(void* const* d_in, const int* in_sizes, int n_in,
                              void* d_out, int out_size)
{
    const float* q  = (const float*)d_in[0];
    const float* k  = (const float*)d_in[1];
    // d_in[2] (v) dead: share_kv
    const float* Wq = (const float*)d_in[3];
    const float* Wk = (const float*)d_in[4];
    const float* Wo = (const float*)d_in[5];
    float* out = (float*)d_out;

    bf16 *pqhi,*pqlo,*pkhi,*pklo,*pwqhi,*pwqlo,*pwkhi,*pwklo,*pwohi,*pwolo;
    bf16 *pqhh,*pqhl,*pkhh,*pkhl,*paohi,*paolo;
    cudaGetSymbolAddress((void**)&pqhi, g_qhi);   cudaGetSymbolAddress((void**)&pqlo, g_qlo);
    cudaGetSymbolAddress((void**)&pkhi, g_khi);   cudaGetSymbolAddress((void**)&pklo, g_klo);
    cudaGetSymbolAddress((void**)&pwqhi, g_wqhi); cudaGetSymbolAddress((void**)&pwqlo, g_wqlo);
    cudaGetSymbolAddress((void**)&pwkhi, g_wkhi); cudaGetSymbolAddress((void**)&pwklo, g_wklo);
    cudaGetSymbolAddress((void**)&pwohi, g_wohi); cudaGetSymbolAddress((void**)&pwolo, g_wolo);
    cudaGetSymbolAddress((void**)&pqhh, g_qhh);   cudaGetSymbolAddress((void**)&pqhl, g_qhl);
    cudaGetSymbolAddress((void**)&pkhh, g_khh);   cudaGetSymbolAddress((void**)&pkhl, g_khl);
    cudaGetSymbolAddress((void**)&paohi, g_aohi); cudaGetSymbolAddress((void**)&paolo, g_aolo);

    static bool attr_done = false;
    if (!attr_done) {
        cudaFuncSetAttribute(attn_mma, cudaFuncAttributeMaxDynamicSharedMemorySize, ATTN_SMEM);
        attr_done = true;
    }

    const int n4_big = M_TOT * E_ / 4;
    const int n4_w   = E_ * E_ / 4;
    split_kernel<<<(n4_big + 255)/256, 256>>>((const float4*)q, (bf162*)pqhi, (bf162*)pqlo, n4_big);
    split_kernel<<<(n4_big + 255)/256, 256>>>((const float4*)k, (bf162*)pkhi, (bf162*)pklo, n4_big);
    split_kernel<<<(n4_w + 255)/256, 256>>>((const float4*)Wq, (bf162*)pwqhi, (bf162*)pwqlo, n4_w);
    split_kernel<<<(n4_w + 255)/256, 256>>>((const float4*)Wk, (bf162*)pwkhi, (bf162*)pwklo, n4_w);
    split_kernel<<<(n4_w + 255)/256, 256>>>((const float4*)Wo, (bf162*)pwohi, (bf162*)pwolo, n4_w);

    dim3 gg(E_/128, M_TOT/128);   // (8, 64)
    gemm_mma<1><<<gg, 256>>>(pqhi, pqlo, pwqhi, pwqlo, nullptr, pqhh, pqhl, 0.125f);
    gemm_mma<1><<<gg, 256>>>(pkhi, pklo, pwkhi, pwklo, nullptr, pkhh, pkhl, 1.0f);

    attn_mma<<<dim3(16, B_*H_), 256, ATTN_SMEM>>>(pqhh, pqhl, pkhh, pkhl, paohi, paolo);

    gemm_mma<0><<<gg, 256>>>(paohi, paolo, pwohi, pwolo, out, nullptr, nullptr, 1.0f);
}

// round 7
// speedup vs baseline: 2.8807x; 1.1802x over previous
#include <cuda_runtime.h>
#include <cuda_bf16.h>
#include <math.h>
#include <stdint.h>

#define B_ 4
#define T_ 2048
#define E_ 1024
#define H_ 16
#define D_ 64
#define M_TOT (B_*T_)   // 8192

typedef __nv_bfloat16 bf16;
typedef __nv_bfloat162 bf162;

// ---------------- scratch (allocation-free) ----------------
__device__ __align__(16) bf16 g_qhi[M_TOT*E_], g_qlo[M_TOT*E_];     // input splits (E-major)
__device__ __align__(16) bf16 g_khi[M_TOT*E_], g_klo[M_TOT*E_];
__device__ __align__(16) bf16 g_wqhi[E_*E_],  g_wqlo[E_*E_];
__device__ __align__(16) bf16 g_wkhi[E_*E_],  g_wklo[E_*E_];
__device__ __align__(16) bf16 g_wohi[E_*E_],  g_wolo[E_*E_];
__device__ __align__(16) bf16 g_qhh[M_TOT*E_], g_qhl[M_TOT*E_];     // Q head [b,h,t,d] hi/lo (scaled 1/8)
__device__ __align__(16) bf16 g_khh[M_TOT*E_], g_khl[M_TOT*E_];     // K head hi/lo
__device__ __align__(16) bf16 g_aohi[M_TOT*E_], g_aolo[M_TOT*E_];   // attn out [b,t,(h d)] hi/lo

// ---------------- helpers ----------------
__device__ __forceinline__ uint32_t smem_u32(const void* p) {
    uint32_t a;
    asm("{ .reg .u64 t; cvta.to.shared.u64 t, %1; cvt.u32.u64 %0, t; }" : "=r"(a) : "l"(p));
    return a;
}
__device__ __forceinline__ void cp16(uint32_t saddr, const void* gaddr) {
    asm volatile("cp.async.cg.shared.global [%0], [%1], 16;" :: "r"(saddr), "l"(gaddr));
}
#define CP_COMMIT() asm volatile("cp.async.commit_group;" ::: "memory")
#define CP_WAIT(n)  asm volatile("cp.async.wait_group %0;" :: "n"(n) : "memory")

__device__ __forceinline__ void ldm_x4(uint32_t& r0, uint32_t& r1, uint32_t& r2, uint32_t& r3,
                                       uint32_t addr) {
    asm volatile("ldmatrix.sync.aligned.m8n8.x4.shared.b16 {%0,%1,%2,%3}, [%4];"
                 : "=r"(r0), "=r"(r1), "=r"(r2), "=r"(r3) : "r"(addr));
}
__device__ __forceinline__ void ldm_x4t(uint32_t& r0, uint32_t& r1, uint32_t& r2, uint32_t& r3,
                                        uint32_t addr) {
    asm volatile("ldmatrix.sync.aligned.m8n8.x4.trans.shared.b16 {%0,%1,%2,%3}, [%4];"
                 : "=r"(r0), "=r"(r1), "=r"(r2), "=r"(r3) : "r"(addr));
}
__device__ __forceinline__ void mma16816(float& d0, float& d1, float& d2, float& d3,
                                         uint32_t a0, uint32_t a1, uint32_t a2, uint32_t a3,
                                         uint32_t b0, uint32_t b1) {
    asm volatile("mma.sync.aligned.m16n8k16.row.col.f32.bf16.bf16.f32 "
                 "{%0,%1,%2,%3}, {%4,%5,%6,%7}, {%8,%9}, {%0,%1,%2,%3};"
                 : "+f"(d0), "+f"(d1), "+f"(d2), "+f"(d3)
                 : "r"(a0), "r"(a1), "r"(a2), "r"(a3), "r"(b0), "r"(b1));
}

// ---------------- fp32 -> bf16 hi/lo split ----------------
__global__ __launch_bounds__(256) void split_kernel(const float4* __restrict__ src,
                                                    bf162* __restrict__ hi,
                                                    bf162* __restrict__ lo,
                                                    int n4)
{
    int i = blockIdx.x * 256 + threadIdx.x;
    if (i >= n4) return;
    float4 v = src[i];
    bf16 h0 = __float2bfloat16_rn(v.x), h1 = __float2bfloat16_rn(v.y);
    bf16 h2 = __float2bfloat16_rn(v.z), h3 = __float2bfloat16_rn(v.w);
    bf16 l0 = __float2bfloat16_rn(v.x - __bfloat162float(h0));
    bf16 l1 = __float2bfloat16_rn(v.y - __bfloat162float(h1));
    bf16 l2 = __float2bfloat16_rn(v.z - __bfloat162float(h2));
    bf16 l3 = __float2bfloat16_rn(v.w - __bfloat162float(h3));
    hi[2*i]   = bf162(h0, h1);  hi[2*i+1] = bf162(h2, h3);
    lo[2*i]   = bf162(l0, l1);  lo[2*i+1] = bf162(l2, l3);
}

// ---------------------------------------------------------------------------
// HMMA GEMM core: C = A @ W^T, bf16-split, 3 passes FUSED per K-chunk.
// Block 128x128, Kchunk=32, 8 warps, 2-stage cp.async pipeline over
// (Ahi, Alo, Bhi, Blo) tiles simultaneously.
// ---------------------------------------------------------------------------
#define SROWB 80
#define TILEB (128 * SROWB)           // 10240 B
#define NCHUNK 32
#define GEMM_SMEM (8 * TILEB)         // 81920 B

template<int MODE>
__device__ __forceinline__ void gemm_body(const bf16* __restrict__ Ahi,
                                          const bf16* __restrict__ Alo,
                                          const bf16* __restrict__ Bhi,
                                          const bf16* __restrict__ Blo,
                                          float* __restrict__ Cf,
                                          bf16* __restrict__ Chi,
                                          bf16* __restrict__ Clo,
                                          float scale, int m0, int n0, char* smem)
{
    const int tid = threadIdx.x;
    const int wid = tid >> 5, lid = tid & 31;
    const int warp_m = wid & 3, warp_n = wid >> 2;
    const int gr = tid >> 2, gc = tid & 3;
    const uint32_t sb = smem_u32(smem);

    float acc[2][8][4];
    #pragma unroll
    for (int i = 0; i < 2; i++)
        #pragma unroll
        for (int j = 0; j < 8; j++)
            #pragma unroll
            for (int c = 0; c < 4; c++) acc[i][j][c] = 0.f;

    auto issue = [&](int kc) {
        const int st = kc & 1;
        const size_t colB = (size_t)kc * 64;
        const char* srcs[4] = { (const char*)Ahi, (const char*)Alo,
                                (const char*)Bhi, (const char*)Blo };
        const int base[4] = { m0, m0, n0, n0 };
        #pragma unroll
        for (int t = 0; t < 4; t++) {
            const char* S = srcs[t];
            uint32_t dst = sb + (st * 4 + t) * TILEB;
            #pragma unroll
            for (int q = 0; q < 2; q++) {
                int r = gr + q * 64;
                cp16(dst + r * SROWB + gc * 16,
                     S + (size_t)(base[t] + r) * 2048 + colB + gc * 16);
            }
        }
        CP_COMMIT();
    };

    issue(0);
    for (int i = 0; i < NCHUNK; i++) {
        if (i + 1 < NCHUNK) { issue(i + 1); CP_WAIT(1); }
        else                { CP_WAIT(0); }
        __syncthreads();

        const int st = i & 1;
        const uint32_t bAhi = sb + (st * 4 + 0) * TILEB;
        const uint32_t bAlo = sb + (st * 4 + 1) * TILEB;
        const uint32_t bBhi = sb + (st * 4 + 2) * TILEB;
        const uint32_t bBlo = sb + (st * 4 + 3) * TILEB;
        const int lrow = lid & 15, lcol = (lid >> 4) * 16;

        #pragma unroll
        for (int s = 0; s < 2; s++) {
            uint32_t ah[2][4], al[2][4];
            #pragma unroll
            for (int mt = 0; mt < 2; mt++) {
                uint32_t off = (warp_m*32 + mt*16 + lrow) * SROWB + s*32 + lcol;
                ldm_x4(ah[mt][0], ah[mt][1], ah[mt][2], ah[mt][3], bAhi + off);
                ldm_x4(al[mt][0], al[mt][1], al[mt][2], al[mt][3], bAlo + off);
            }
            #pragma unroll
            for (int np = 0; np < 4; np++) {
                uint32_t off = (warp_n*64 + np*16 + lrow) * SROWB + s*32 + lcol;
                uint32_t h0,h1,h2,h3;
                ldm_x4(h0,h1,h2,h3, bBhi + off);
                #pragma unroll
                for (int mt = 0; mt < 2; mt++) {
                    // pass0: Ahi x Bhi
                    mma16816(acc[mt][np*2][0],acc[mt][np*2][1],acc[mt][np*2][2],acc[mt][np*2][3],
                             ah[mt][0],ah[mt][1],ah[mt][2],ah[mt][3], h0, h2);
                    mma16816(acc[mt][np*2+1][0],acc[mt][np*2+1][1],acc[mt][np*2+1][2],acc[mt][np*2+1][3],
                             ah[mt][0],ah[mt][1],ah[mt][2],ah[mt][3], h1, h3);
                    // pass2: Alo x Bhi
                    mma16816(acc[mt][np*2][0],acc[mt][np*2][1],acc[mt][np*2][2],acc[mt][np*2][3],
                             al[mt][0],al[mt][1],al[mt][2],al[mt][3], h0, h2);
                    mma16816(acc[mt][np*2+1][0],acc[mt][np*2+1][1],acc[mt][np*2+1][2],acc[mt][np*2+1][3],
                             al[mt][0],al[mt][1],al[mt][2],al[mt][3], h1, h3);
                }
                uint32_t l0,l1,l2,l3;
                ldm_x4(l0,l1,l2,l3, bBlo + off);
                #pragma unroll
                for (int mt = 0; mt < 2; mt++) {
                    // pass1: Ahi x Blo
                    mma16816(acc[mt][np*2][0],acc[mt][np*2][1],acc[mt][np*2][2],acc[mt][np*2][3],
                             ah[mt][0],ah[mt][1],ah[mt][2],ah[mt][3], l0, l2);
                    mma16816(acc[mt][np*2+1][0],acc[mt][np*2+1][1],acc[mt][np*2+1][2],acc[mt][np*2+1][3],
                             ah[mt][0],ah[mt][1],ah[mt][2],ah[mt][3], l1, l3);
                }
            }
        }
        __syncthreads();
    }

    const int gid = lid >> 2, tig = lid & 3;
    #pragma unroll
    for (int mt = 0; mt < 2; mt++) {
        #pragma unroll
        for (int nt = 0; nt < 8; nt++) {
            int m = m0 + warp_m*32 + mt*16 + gid;
            int n = n0 + warp_n*64 + nt*8 + tig*2;
            #pragma unroll
            for (int half = 0; half < 2; half++) {
                int mm = m + half * 8;
                float x0 = acc[mt][nt][half*2+0], x1 = acc[mt][nt][half*2+1];
                if (MODE == 0) {
                    *(float2*)(Cf + (size_t)mm * E_ + n) = make_float2(x0, x1);
                } else {
                    x0 *= scale; x1 *= scale;
                    bf16 h0 = __float2bfloat16_rn(x0), h1 = __float2bfloat16_rn(x1);
                    bf16 l0 = __float2bfloat16_rn(x0 - __bfloat162float(h0));
                    bf16 l1 = __float2bfloat16_rn(x1 - __bfloat162float(h1));
                    int b = mm >> 11, t = mm & (T_ - 1);
                    int h = n >> 6,  d = n & 63;
                    size_t idx = (((size_t)b * H_ + h) * T_ + t) * D_ + d;
                    *(bf162*)(Chi + idx) = bf162(h0, h1);
                    *(bf162*)(Clo + idx) = bf162(l0, l1);
                }
            }
        }
    }
}

// Merged Q+K projection: grid.y in [0,128): y<64 -> Q, else K.
__global__ __launch_bounds__(256, 2) void gemm_proj(
    const bf16* __restrict__ qAhi, const bf16* __restrict__ qAlo,
    const bf16* __restrict__ kAhi, const bf16* __restrict__ kAlo,
    const bf16* __restrict__ WqHi, const bf16* __restrict__ WqLo,
    const bf16* __restrict__ WkHi, const bf16* __restrict__ WkLo,
    bf16* __restrict__ qChi, bf16* __restrict__ qClo,
    bf16* __restrict__ kChi, bf16* __restrict__ kClo)
{
    extern __shared__ __align__(16) char smem[];
    const int y = blockIdx.y;
    const int n0 = blockIdx.x * 128;
    if (y < 64) {
        gemm_body<1>(qAhi, qAlo, WqHi, WqLo, nullptr, qChi, qClo,
                     0.125f, y * 128, n0, smem);
    } else {
        gemm_body<1>(kAhi, kAlo, WkHi, WkLo, nullptr, kChi, kClo,
                     1.0f, (y - 64) * 128, n0, smem);
    }
}

// O projection (fp32 output)
__global__ __launch_bounds__(256, 2) void gemm_out(
    const bf16* __restrict__ Ahi, const bf16* __restrict__ Alo,
    const bf16* __restrict__ Bhi, const bf16* __restrict__ Blo,
    float* __restrict__ Cf)
{
    extern __shared__ __align__(16) char smem[];
    gemm_body<0>(Ahi, Alo, Bhi, Blo, Cf, nullptr, nullptr,
                 1.0f, blockIdx.y * 128, blockIdx.x * 128, smem);
}

// ---------------------------------------------------------------------------
// Causal flash attention, V == K (share_kv), bf16-split HMMA. (round 6 proven)
// ---------------------------------------------------------------------------
#define QSTRB 144
#define PSTRB 272
#define KSTG  (128*QSTRB)
#define SM_KHI(st) ((st)*2*KSTG)
#define SM_KLO(st) ((st)*2*KSTG + KSTG)
#define SM_PHI (4*KSTG)
#define SM_PLO (SM_PHI + 128*PSTRB)
#define ATTN_SMEM (SM_PLO + 128*PSTRB)

__global__ __launch_bounds__(256) void attn_mma(const bf16* __restrict__ qhh,
                                                const bf16* __restrict__ qhl,
                                                const bf16* __restrict__ khh,
                                                const bf16* __restrict__ khl,
                                                bf16* __restrict__ aohi,
                                                bf16* __restrict__ aolo)
{
    extern __shared__ __align__(16) char smem[];
    const uint32_t sb = smem_u32(smem);
    const int tid = threadIdx.x;
    const int wid = tid >> 5, lid = tid & 31;
    const int wrow = wid * 16;
    const int gid = lid >> 2, tig = lid & 3;
    const int lrow = lid & 15, lcol = (lid >> 4) * 16;
    const int qt = 15 - (int)blockIdx.x;
    const int bh = blockIdx.y;

    const char* Khi = (const char*)(khh + (size_t)bh * T_ * D_);
    const char* Klo = (const char*)(khl + (size_t)bh * T_ * D_);

    auto issueK = [&](int kt, int st) {
        #pragma unroll
        for (int i = 0; i < 4; i++) {
            int idx = tid + i * 256;
            int r = idx >> 3, c = (idx & 7) * 16;
            cp16(sb + SM_KHI(st) + r * QSTRB + c, Khi + ((size_t)kt * 128 + r) * 128 + c);
            cp16(sb + SM_KLO(st) + r * QSTRB + c, Klo + ((size_t)kt * 128 + r) * 128 + c);
        }
        CP_COMMIT();
    };

    issueK(0, 0);

    uint32_t qh[4][4], ql[4][4];
    {
        const bf16* Qgh = qhh + (size_t)bh * T_ * D_ + (size_t)(qt * 128 + wrow) * D_;
        const bf16* Qgl = qhl + (size_t)bh * T_ * D_ + (size_t)(qt * 128 + wrow) * D_;
        #pragma unroll
        for (int ks = 0; ks < 4; ks++) {
            int c0 = ks * 16 + tig * 2;
            qh[ks][0] = *(const uint32_t*)(Qgh + (size_t)gid * D_ + c0);
            qh[ks][1] = *(const uint32_t*)(Qgh + (size_t)(gid + 8) * D_ + c0);
            qh[ks][2] = *(const uint32_t*)(Qgh + (size_t)gid * D_ + c0 + 8);
            qh[ks][3] = *(const uint32_t*)(Qgh + (size_t)(gid + 8) * D_ + c0 + 8);
            ql[ks][0] = *(const uint32_t*)(Qgl + (size_t)gid * D_ + c0);
            ql[ks][1] = *(const uint32_t*)(Qgl + (size_t)(gid + 8) * D_ + c0);
            ql[ks][2] = *(const uint32_t*)(Qgl + (size_t)gid * D_ + c0 + 8);
            ql[ks][3] = *(const uint32_t*)(Qgl + (size_t)(gid + 8) * D_ + c0 + 8);
        }
    }

    float mrow[2] = {-1e30f, -1e30f};
    float lrow_[2] = {0.f, 0.f};
    float o[8][4];
    #pragma unroll
    for (int nt = 0; nt < 8; nt++)
        #pragma unroll
        for (int c = 0; c < 4; c++) o[nt][c] = 0.f;

    for (int kt = 0; kt <= qt; kt++) {
        const int st = kt & 1;
        if (kt < qt) { issueK(kt + 1, st ^ 1); CP_WAIT(1); }
        else         { CP_WAIT(0); }
        __syncthreads();

        float s[16][4];
        #pragma unroll
        for (int nt = 0; nt < 16; nt++)
            #pragma unroll
            for (int c = 0; c < 4; c++) s[nt][c] = 0.f;

        #pragma unroll
        for (int ks = 0; ks < 4; ks++) {
            uint32_t b[16][2];
            #pragma unroll
            for (int np = 0; np < 8; np++) {
                uint32_t r0,r1,r2,r3;
                ldm_x4(r0,r1,r2,r3, sb + SM_KHI(st) + (np*16 + lrow) * QSTRB + ks*32 + lcol);
                b[np*2][0] = r0;   b[np*2][1] = r2;
                b[np*2+1][0] = r1; b[np*2+1][1] = r3;
            }
            #pragma unroll
            for (int nt = 0; nt < 16; nt++)
                mma16816(s[nt][0], s[nt][1], s[nt][2], s[nt][3],
                         qh[ks][0], qh[ks][1], qh[ks][2], qh[ks][3], b[nt][0], b[nt][1]);
            #pragma unroll
            for (int nt = 0; nt < 16; nt++)
                mma16816(s[nt][0], s[nt][1], s[nt][2], s[nt][3],
                         ql[ks][0], ql[ks][1], ql[ks][2], ql[ks][3], b[nt][0], b[nt][1]);
            #pragma unroll
            for (int np = 0; np < 8; np++) {
                uint32_t r0,r1,r2,r3;
                ldm_x4(r0,r1,r2,r3, sb + SM_KLO(st) + (np*16 + lrow) * QSTRB + ks*32 + lcol);
                b[np*2][0] = r0;   b[np*2][1] = r2;
                b[np*2+1][0] = r1; b[np*2+1][1] = r3;
            }
            #pragma unroll
            for (int nt = 0; nt < 16; nt++)
                mma16816(s[nt][0], s[nt][1], s[nt][2], s[nt][3],
                         qh[ks][0], qh[ks][1], qh[ks][2], qh[ks][3], b[nt][0], b[nt][1]);
        }

        if (kt == qt) {
            #pragma unroll
            for (int nt = 0; nt < 16; nt++)
                #pragma unroll
                for (int c = 0; c < 4; c++) {
                    int row = wrow + gid + (c >> 1) * 8;
                    int col = nt*8 + tig*2 + (c & 1);
                    if (col > row) s[nt][c] = -1e30f;
                }
        }

        #pragma unroll
        for (int r = 0; r < 2; r++) {
            float mx = -1e30f;
            #pragma unroll
            for (int nt = 0; nt < 16; nt++)
                mx = fmaxf(mx, fmaxf(s[nt][r*2], s[nt][r*2+1]));
            mx = fmaxf(mx, __shfl_xor_sync(0xffffffffu, mx, 1));
            mx = fmaxf(mx, __shfl_xor_sync(0xffffffffu, mx, 2));
            float mnew = fmaxf(mrow[r], mx);
            float psum = 0.f;
            #pragma unroll
            for (int nt = 0; nt < 16; nt++) {
                float p0 = __expf(s[nt][r*2]   - mnew);
                float p1 = __expf(s[nt][r*2+1] - mnew);
                s[nt][r*2] = p0; s[nt][r*2+1] = p1;
                psum += p0 + p1;
            }
            psum += __shfl_xor_sync(0xffffffffu, psum, 1);
            psum += __shfl_xor_sync(0xffffffffu, psum, 2);
            float corr = __expf(mrow[r] - mnew);
            lrow_[r] = lrow_[r] * corr + psum;
            mrow[r] = mnew;
            #pragma unroll
            for (int nt = 0; nt < 8; nt++) {
                o[nt][r*2]   *= corr;
                o[nt][r*2+1] *= corr;
            }
        }

        #pragma unroll
        for (int nt = 0; nt < 16; nt++)
            #pragma unroll
            for (int r = 0; r < 2; r++) {
                float p0 = s[nt][r*2], p1 = s[nt][r*2+1];
                bf16 h0 = __float2bfloat16_rn(p0), h1 = __float2bfloat16_rn(p1);
                uint32_t rowoff = (wrow + gid + r*8) * PSTRB + nt*16 + tig*4;
                *(bf162*)(smem + SM_PHI + rowoff) = bf162(h0, h1);
                *(bf162*)(smem + SM_PLO + rowoff) =
                    bf162(__float2bfloat16_rn(p0 - __bfloat162float(h0)),
                          __float2bfloat16_rn(p1 - __bfloat162float(h1)));
            }
        __syncwarp();

        #pragma unroll
        for (int ks = 0; ks < 8; ks++) {
            uint32_t pa0,pa1,pa2,pa3, pb0,pb1,pb2,pb3;
            ldm_x4(pa0,pa1,pa2,pa3, sb + SM_PHI + (wrow + lrow) * PSTRB + ks*32 + lcol);
            ldm_x4(pb0,pb1,pb2,pb3, sb + SM_PLO + (wrow + lrow) * PSTRB + ks*32 + lcol);
            #pragma unroll
            for (int nb = 0; nb < 4; nb++) {
                uint32_t r0,r1,r2,r3;
                ldm_x4t(r0,r1,r2,r3, sb + SM_KHI(st) + (ks*16 + lrow) * QSTRB + nb*32 + lcol);
                mma16816(o[nb*2][0],   o[nb*2][1],   o[nb*2][2],   o[nb*2][3],
                         pa0,pa1,pa2,pa3, r0, r1);
                mma16816(o[nb*2+1][0], o[nb*2+1][1], o[nb*2+1][2], o[nb*2+1][3],
                         pa0,pa1,pa2,pa3, r2, r3);
                mma16816(o[nb*2][0],   o[nb*2][1],   o[nb*2][2],   o[nb*2][3],
                         pb0,pb1,pb2,pb3, r0, r1);
                mma16816(o[nb*2+1][0], o[nb*2+1][1], o[nb*2+1][2], o[nb*2+1][3],
                         pb0,pb1,pb2,pb3, r2, r3);
            }
            #pragma unroll
            for (int nb = 0; nb < 4; nb++) {
                uint32_t r0,r1,r2,r3;
                ldm_x4t(r0,r1,r2,r3, sb + SM_KLO(st) + (ks*16 + lrow) * QSTRB + nb*32 + lcol);
                mma16816(o[nb*2][0],   o[nb*2][1],   o[nb*2][2],   o[nb*2][3],
                         pa0,pa1,pa2,pa3, r0, r1);
                mma16816(o[nb*2+1][0], o[nb*2+1][1], o[nb*2+1][2], o[nb*2+1][3],
                         pa0,pa1,pa2,pa3, r2, r3);
            }
        }
        __syncthreads();
    }

    const int b = bh >> 4, h = bh & 15;
    #pragma unroll
    for (int r = 0; r < 2; r++) {
        float inv = 1.0f / lrow_[r];
        int t = qt*128 + wrow + gid + r*8;
        #pragma unroll
        for (int nt = 0; nt < 8; nt++) {
            float x0 = o[nt][r*2] * inv, x1 = o[nt][r*2+1] * inv;
            bf16 h0 = __float2bfloat16_rn(x0), h1 = __float2bfloat16_rn(x1);
            bf16 l0 = __float2bfloat16_rn(x0 - __bfloat162float(h0));
            bf16 l1 = __float2bfloat16_rn(x1 - __bfloat162float(h1));
            size_t idx = ((size_t)b * T_ + t) * E_ + h*64 + nt*8 + tig*2;
            *(bf162*)(aohi + idx) = bf162(h0, h1);
            *(bf162*)(aolo + idx) = bf162(l0, l1);
        }
    }
}

// ---------------------------------------------------------------------------
extern "C" void kernel_launch(void* const* d_in, const int* in_sizes, int n_in,
                              void* d_out, int out_size)
{
    const float* q  = (const float*)d_in[0];
    const float* k  = (const float*)d_in[1];
    // d_in[2] (v) dead: share_kv
    const float* Wq = (const float*)d_in[3];
    const float* Wk = (const float*)d_in[4];
    const float* Wo = (const float*)d_in[5];
    float* out = (float*)d_out;

    bf16 *pqhi,*pqlo,*pkhi,*pklo,*pwqhi,*pwqlo,*pwkhi,*pwklo,*pwohi,*pwolo;
    bf16 *pqhh,*pqhl,*pkhh,*pkhl,*paohi,*paolo;
    cudaGetSymbolAddress((void**)&pqhi, g_qhi);   cudaGetSymbolAddress((void**)&pqlo, g_qlo);
    cudaGetSymbolAddress((void**)&pkhi, g_khi);   cudaGetSymbolAddress((void**)&pklo, g_klo);
    cudaGetSymbolAddress((void**)&pwqhi, g_wqhi); cudaGetSymbolAddress((void**)&pwqlo, g_wqlo);
    cudaGetSymbolAddress((void**)&pwkhi, g_wkhi); cudaGetSymbolAddress((void**)&pwklo, g_wklo);
    cudaGetSymbolAddress((void**)&pwohi, g_wohi); cudaGetSymbolAddress((void**)&pwolo, g_wolo);
    cudaGetSymbolAddress((void**)&pqhh, g_qhh);   cudaGetSymbolAddress((void**)&pqhl, g_qhl);
    cudaGetSymbolAddress((void**)&pkhh, g_khh);   cudaGetSymbolAddress((void**)&pkhl, g_khl);
    cudaGetSymbolAddress((void**)&paohi, g_aohi); cudaGetSymbolAddress((void**)&paolo, g_aolo);

    static bool attr_done = false;
    if (!attr_done) {
        cudaFuncSetAttribute(attn_mma, cudaFuncAttributeMaxDynamicSharedMemorySize, ATTN_SMEM);
        cudaFuncSetAttribute(gemm_proj, cudaFuncAttributeMaxDynamicSharedMemorySize, GEMM_SMEM);
        cudaFuncSetAttribute(gemm_out, cudaFuncAttributeMaxDynamicSharedMemorySize, GEMM_SMEM);
        attr_done = true;
    }

    const int n4_big = M_TOT * E_ / 4;
    const int n4_w   = E_ * E_ / 4;
    split_kernel<<<(n4_big + 255)/256, 256>>>((const float4*)q, (bf162*)pqhi, (bf162*)pqlo, n4_big);
    split_kernel<<<(n4_big + 255)/256, 256>>>((const float4*)k, (bf162*)pkhi, (bf162*)pklo, n4_big);
    split_kernel<<<(n4_w + 255)/256, 256>>>((const float4*)Wq, (bf162*)pwqhi, (bf162*)pwqlo, n4_w);
    split_kernel<<<(n4_w + 255)/256, 256>>>((const float4*)Wk, (bf162*)pwkhi, (bf162*)pwklo, n4_w);
    split_kernel<<<(n4_w + 255)/256, 256>>>((const float4*)Wo, (bf162*)pwohi, (bf162*)pwolo, n4_w);

    gemm_proj<<<dim3(8, 128), 256, GEMM_SMEM>>>(pqhi, pqlo, pkhi, pklo,
                                                pwqhi, pwqlo, pwkhi, pwklo,
                                                pqhh, pqhl, pkhh, pkhl);

    attn_mma<<<dim3(16, B_*H_), 256, ATTN_SMEM>>>(pqhh, pqhl, pkhh, pkhl, paohi, paolo);

    gemm_out<<<dim3(8, 64), 256, GEMM_SMEM>>>(paohi, paolo, pwohi, pwolo, out);
}

// round 8
// speedup vs baseline: 2.9750x; 1.0327x over previous
#include <cuda_runtime.h>
#include <cuda_bf16.h>
#include <math.h>
#include <stdint.h>

#define B_ 4
#define T_ 2048
#define E_ 1024
#define H_ 16
#define D_ 64
#define M_TOT (B_*T_)   // 8192

typedef __nv_bfloat16 bf16;
typedef __nv_bfloat162 bf162;

// ---------------- scratch (allocation-free) ----------------
__device__ __align__(16) bf16 g_qhi[M_TOT*E_], g_qlo[M_TOT*E_];
__device__ __align__(16) bf16 g_khi[M_TOT*E_], g_klo[M_TOT*E_];
__device__ __align__(16) bf16 g_wqhi[E_*E_],  g_wqlo[E_*E_];
__device__ __align__(16) bf16 g_wkhi[E_*E_],  g_wklo[E_*E_];
__device__ __align__(16) bf16 g_wohi[E_*E_],  g_wolo[E_*E_];
__device__ __align__(16) bf16 g_qhh[M_TOT*E_], g_qhl[M_TOT*E_];
__device__ __align__(16) bf16 g_khh[M_TOT*E_], g_khl[M_TOT*E_];
__device__ __align__(16) bf16 g_aohi[M_TOT*E_], g_aolo[M_TOT*E_];

// ---------------- helpers ----------------
__device__ __forceinline__ uint32_t smem_u32(const void* p) {
    uint32_t a;
    asm("{ .reg .u64 t; cvta.to.shared.u64 t, %1; cvt.u32.u64 %0, t; }" : "=r"(a) : "l"(p));
    return a;
}
__device__ __forceinline__ void cp16(uint32_t saddr, const void* gaddr) {
    asm volatile("cp.async.cg.shared.global [%0], [%1], 16;" :: "r"(saddr), "l"(gaddr));
}
#define CP_COMMIT() asm volatile("cp.async.commit_group;" ::: "memory")
#define CP_WAIT(n)  asm volatile("cp.async.wait_group %0;" :: "n"(n) : "memory")

__device__ __forceinline__ void ldm_x4(uint32_t& r0, uint32_t& r1, uint32_t& r2, uint32_t& r3,
                                       uint32_t addr) {
    asm volatile("ldmatrix.sync.aligned.m8n8.x4.shared.b16 {%0,%1,%2,%3}, [%4];"
                 : "=r"(r0), "=r"(r1), "=r"(r2), "=r"(r3) : "r"(addr));
}
__device__ __forceinline__ void ldm_x4t(uint32_t& r0, uint32_t& r1, uint32_t& r2, uint32_t& r3,
                                        uint32_t addr) {
    asm volatile("ldmatrix.sync.aligned.m8n8.x4.trans.shared.b16 {%0,%1,%2,%3}, [%4];"
                 : "=r"(r0), "=r"(r1), "=r"(r2), "=r"(r3) : "r"(addr));
}
__device__ __forceinline__ void mma16816(float& d0, float& d1, float& d2, float& d3,
                                         uint32_t a0, uint32_t a1, uint32_t a2, uint32_t a3,
                                         uint32_t b0, uint32_t b1) {
    asm volatile("mma.sync.aligned.m16n8k16.row.col.f32.bf16.bf16.f32 "
                 "{%0,%1,%2,%3}, {%4,%5,%6,%7}, {%8,%9}, {%0,%1,%2,%3};"
                 : "+f"(d0), "+f"(d1), "+f"(d2), "+f"(d3)
                 : "r"(a0), "r"(a1), "r"(a2), "r"(a3), "r"(b0), "r"(b1));
}
// fp32 pair -> packed bf16 hi pair + lo-residual pair
__device__ __forceinline__ void split2(float x0, float x1, uint32_t& hi, uint32_t& lo) {
    bf16 h0 = __float2bfloat16_rn(x0), h1 = __float2bfloat16_rn(x1);
    bf162 hv(h0, h1);
    bf162 lv(__float2bfloat16_rn(x0 - __bfloat162float(h0)),
             __float2bfloat16_rn(x1 - __bfloat162float(h1)));
    hi = *(uint32_t*)&hv;
    lo = *(uint32_t*)&lv;
}

// ---------------- fused fp32 -> bf16 hi/lo split (all 5 tensors) ----------------
#define N4BIG (M_TOT*E_/4)
#define N4W   (E_*E_/4)
__global__ __launch_bounds__(256) void split_all(
    const float4* __restrict__ q, const float4* __restrict__ k,
    const float4* __restrict__ wq, const float4* __restrict__ wk,
    const float4* __restrict__ wo,
    bf162* __restrict__ qhi, bf162* __restrict__ qlo,
    bf162* __restrict__ khi, bf162* __restrict__ klo,
    bf162* __restrict__ wqhi, bf162* __restrict__ wqlo,
    bf162* __restrict__ wkhi, bf162* __restrict__ wklo,
    bf162* __restrict__ wohi, bf162* __restrict__ wolo)
{
    int i = blockIdx.x * 256 + threadIdx.x;
    const float4* src; bf162 *hi, *lo;
    if      (i < N4BIG)                { src = q;  hi = qhi;  lo = qlo; }
    else if (i < 2*N4BIG)              { i -= N4BIG;   src = k;  hi = khi;  lo = klo; }
    else if (i < 2*N4BIG + N4W)        { i -= 2*N4BIG; src = wq; hi = wqhi; lo = wqlo; }
    else if (i < 2*N4BIG + 2*N4W)      { i -= 2*N4BIG + N4W;   src = wk; hi = wkhi; lo = wklo; }
    else if (i < 2*N4BIG + 3*N4W)      { i -= 2*N4BIG + 2*N4W; src = wo; hi = wohi; lo = wolo; }
    else return;
    float4 v = src[i];
    uint32_t h01, l01, h23, l23;
    split2(v.x, v.y, h01, l01);
    split2(v.z, v.w, h23, l23);
    hi[2*i]   = *(bf162*)&h01;  hi[2*i+1] = *(bf162*)&h23;
    lo[2*i]   = *(bf162*)&l01;  lo[2*i+1] = *(bf162*)&l23;
}

// ---------------------------------------------------------------------------
// HMMA GEMM core: C = A @ W^T, bf16-split, 3 passes fused per K-chunk.
// ---------------------------------------------------------------------------
#define SROWB 80
#define TILEB (128 * SROWB)
#define NCHUNK 32
#define GEMM_SMEM (8 * TILEB)

template<int MODE>
__device__ __forceinline__ void gemm_body(const bf16* __restrict__ Ahi,
                                          const bf16* __restrict__ Alo,
                                          const bf16* __restrict__ Bhi,
                                          const bf16* __restrict__ Blo,
                                          float* __restrict__ Cf,
                                          bf16* __restrict__ Chi,
                                          bf16* __restrict__ Clo,
                                          float scale, int m0, int n0, char* smem)
{
    const int tid = threadIdx.x;
    const int wid = tid >> 5, lid = tid & 31;
    const int warp_m = wid & 3, warp_n = wid >> 2;
    const int gr = tid >> 2, gc = tid & 3;
    const uint32_t sb = smem_u32(smem);

    float acc[2][8][4];
    #pragma unroll
    for (int i = 0; i < 2; i++)
        #pragma unroll
        for (int j = 0; j < 8; j++)
            #pragma unroll
            for (int c = 0; c < 4; c++) acc[i][j][c] = 0.f;

    auto issue = [&](int kc) {
        const int st = kc & 1;
        const size_t colB = (size_t)kc * 64;
        const char* srcs[4] = { (const char*)Ahi, (const char*)Alo,
                                (const char*)Bhi, (const char*)Blo };
        const int base[4] = { m0, m0, n0, n0 };
        #pragma unroll
        for (int t = 0; t < 4; t++) {
            const char* S = srcs[t];
            uint32_t dst = sb + (st * 4 + t) * TILEB;
            #pragma unroll
            for (int q = 0; q < 2; q++) {
                int r = gr + q * 64;
                cp16(dst + r * SROWB + gc * 16,
                     S + (size_t)(base[t] + r) * 2048 + colB + gc * 16);
            }
        }
        CP_COMMIT();
    };

    issue(0);
    for (int i = 0; i < NCHUNK; i++) {
        if (i + 1 < NCHUNK) { issue(i + 1); CP_WAIT(1); }
        else                { CP_WAIT(0); }
        __syncthreads();

        const int st = i & 1;
        const uint32_t bAhi = sb + (st * 4 + 0) * TILEB;
        const uint32_t bAlo = sb + (st * 4 + 1) * TILEB;
        const uint32_t bBhi = sb + (st * 4 + 2) * TILEB;
        const uint32_t bBlo = sb + (st * 4 + 3) * TILEB;
        const int lrow = lid & 15, lcol = (lid >> 4) * 16;

        #pragma unroll
        for (int s = 0; s < 2; s++) {
            uint32_t ah[2][4], al[2][4];
            #pragma unroll
            for (int mt = 0; mt < 2; mt++) {
                uint32_t off = (warp_m*32 + mt*16 + lrow) * SROWB + s*32 + lcol;
                ldm_x4(ah[mt][0], ah[mt][1], ah[mt][2], ah[mt][3], bAhi + off);
                ldm_x4(al[mt][0], al[mt][1], al[mt][2], al[mt][3], bAlo + off);
            }
            #pragma unroll
            for (int np = 0; np < 4; np++) {
                uint32_t off = (warp_n*64 + np*16 + lrow) * SROWB + s*32 + lcol;
                uint32_t h0,h1,h2,h3;
                ldm_x4(h0,h1,h2,h3, bBhi + off);
                #pragma unroll
                for (int mt = 0; mt < 2; mt++) {
                    mma16816(acc[mt][np*2][0],acc[mt][np*2][1],acc[mt][np*2][2],acc[mt][np*2][3],
                             ah[mt][0],ah[mt][1],ah[mt][2],ah[mt][3], h0, h2);
                    mma16816(acc[mt][np*2+1][0],acc[mt][np*2+1][1],acc[mt][np*2+1][2],acc[mt][np*2+1][3],
                             ah[mt][0],ah[mt][1],ah[mt][2],ah[mt][3], h1, h3);
                    mma16816(acc[mt][np*2][0],acc[mt][np*2][1],acc[mt][np*2][2],acc[mt][np*2][3],
                             al[mt][0],al[mt][1],al[mt][2],al[mt][3], h0, h2);
                    mma16816(acc[mt][np*2+1][0],acc[mt][np*2+1][1],acc[mt][np*2+1][2],acc[mt][np*2+1][3],
                             al[mt][0],al[mt][1],al[mt][2],al[mt][3], h1, h3);
                }
                uint32_t l0,l1,l2,l3;
                ldm_x4(l0,l1,l2,l3, bBlo + off);
                #pragma unroll
                for (int mt = 0; mt < 2; mt++) {
                    mma16816(acc[mt][np*2][0],acc[mt][np*2][1],acc[mt][np*2][2],acc[mt][np*2][3],
                             ah[mt][0],ah[mt][1],ah[mt][2],ah[mt][3], l0, l2);
                    mma16816(acc[mt][np*2+1][0],acc[mt][np*2+1][1],acc[mt][np*2+1][2],acc[mt][np*2+1][3],
                             ah[mt][0],ah[mt][1],ah[mt][2],ah[mt][3], l1, l3);
                }
            }
        }
        __syncthreads();
    }

    const int gid = lid >> 2, tig = lid & 3;
    #pragma unroll
    for (int mt = 0; mt < 2; mt++) {
        #pragma unroll
        for (int nt = 0; nt < 8; nt++) {
            int m = m0 + warp_m*32 + mt*16 + gid;
            int n = n0 + warp_n*64 + nt*8 + tig*2;
            #pragma unroll
            for (int half = 0; half < 2; half++) {
                int mm = m + half * 8;
                float x0 = acc[mt][nt][half*2+0], x1 = acc[mt][nt][half*2+1];
                if (MODE == 0) {
                    *(float2*)(Cf + (size_t)mm * E_ + n) = make_float2(x0, x1);
                } else {
                    x0 *= scale; x1 *= scale;
                    uint32_t hv, lv;
                    split2(x0, x1, hv, lv);
                    int b = mm >> 11, t = mm & (T_ - 1);
                    int h = n >> 6,  d = n & 63;
                    size_t idx = (((size_t)b * H_ + h) * T_ + t) * D_ + d;
                    *(bf162*)(Chi + idx) = *(bf162*)&hv;
                    *(bf162*)(Clo + idx) = *(bf162*)&lv;
                }
            }
        }
    }
}

__global__ __launch_bounds__(256, 2) void gemm_proj(
    const bf16* __restrict__ qAhi, const bf16* __restrict__ qAlo,
    const bf16* __restrict__ kAhi, const bf16* __restrict__ kAlo,
    const bf16* __restrict__ WqHi, const bf16* __restrict__ WqLo,
    const bf16* __restrict__ WkHi, const bf16* __restrict__ WkLo,
    bf16* __restrict__ qChi, bf16* __restrict__ qClo,
    bf16* __restrict__ kChi, bf16* __restrict__ kClo)
{
    extern __shared__ __align__(16) char smem[];
    const int y = blockIdx.y;
    const int n0 = blockIdx.x * 128;
    if (y < 64) {
        gemm_body<1>(qAhi, qAlo, WqHi, WqLo, nullptr, qChi, qClo,
                     0.125f, y * 128, n0, smem);
    } else {
        gemm_body<1>(kAhi, kAlo, WkHi, WkLo, nullptr, kChi, kClo,
                     1.0f, (y - 64) * 128, n0, smem);
    }
}

__global__ __launch_bounds__(256, 2) void gemm_out(
    const bf16* __restrict__ Ahi, const bf16* __restrict__ Alo,
    const bf16* __restrict__ Bhi, const bf16* __restrict__ Blo,
    float* __restrict__ Cf)
{
    extern __shared__ __align__(16) char smem[];
    gemm_body<0>(Ahi, Alo, Bhi, Blo, Cf, nullptr, nullptr,
                 1.0f, blockIdx.y * 128, blockIdx.x * 128, smem);
}

// ---------------------------------------------------------------------------
// Causal flash attention, V == K (share_kv), bf16-split HMMA.
// Round 8: P stays in registers (D-frag == A-frag layout), no P smem.
// ---------------------------------------------------------------------------
#define QSTRB 144
#define KSTG  (128*QSTRB)
#define SM_KHI(st) ((st)*2*KSTG)
#define SM_KLO(st) ((st)*2*KSTG + KSTG)
#define ATTN_SMEM (4*KSTG)            // 73728

__global__ __launch_bounds__(256) void attn_mma(const bf16* __restrict__ qhh,
                                                const bf16* __restrict__ qhl,
                                                const bf16* __restrict__ khh,
                                                const bf16* __restrict__ khl,
                                                bf16* __restrict__ aohi,
                                                bf16* __restrict__ aolo)
{
    extern __shared__ __align__(16) char smem[];
    const uint32_t sb = smem_u32(smem);
    const int tid = threadIdx.x;
    const int wid = tid >> 5, lid = tid & 31;
    const int wrow = wid * 16;
    const int gid = lid >> 2, tig = lid & 3;
    const int lrow = lid & 15, lcol = (lid >> 4) * 16;
    const int qt = 15 - (int)blockIdx.x;
    const int bh = blockIdx.y;

    const char* Khi = (const char*)(khh + (size_t)bh * T_ * D_);
    const char* Klo = (const char*)(khl + (size_t)bh * T_ * D_);

    auto issueK = [&](int kt, int st) {
        #pragma unroll
        for (int i = 0; i < 4; i++) {
            int idx = tid + i * 256;
            int r = idx >> 3, c = (idx & 7) * 16;
            cp16(sb + SM_KHI(st) + r * QSTRB + c, Khi + ((size_t)kt * 128 + r) * 128 + c);
            cp16(sb + SM_KLO(st) + r * QSTRB + c, Klo + ((size_t)kt * 128 + r) * 128 + c);
        }
        CP_COMMIT();
    };

    issueK(0, 0);

    uint32_t qh[4][4], ql[4][4];
    {
        const bf16* Qgh = qhh + (size_t)bh * T_ * D_ + (size_t)(qt * 128 + wrow) * D_;
        const bf16* Qgl = qhl + (size_t)bh * T_ * D_ + (size_t)(qt * 128 + wrow) * D_;
        #pragma unroll
        for (int ks = 0; ks < 4; ks++) {
            int c0 = ks * 16 + tig * 2;
            qh[ks][0] = *(const uint32_t*)(Qgh + (size_t)gid * D_ + c0);
            qh[ks][1] = *(const uint32_t*)(Qgh + (size_t)(gid + 8) * D_ + c0);
            qh[ks][2] = *(const uint32_t*)(Qgh + (size_t)gid * D_ + c0 + 8);
            qh[ks][3] = *(const uint32_t*)(Qgh + (size_t)(gid + 8) * D_ + c0 + 8);
            ql[ks][0] = *(const uint32_t*)(Qgl + (size_t)gid * D_ + c0);
            ql[ks][1] = *(const uint32_t*)(Qgl + (size_t)(gid + 8) * D_ + c0);
            ql[ks][2] = *(const uint32_t*)(Qgl + (size_t)gid * D_ + c0 + 8);
            ql[ks][3] = *(const uint32_t*)(Qgl + (size_t)(gid + 8) * D_ + c0 + 8);
        }
    }

    float mrow[2] = {-1e30f, -1e30f};
    float lrow_[2] = {0.f, 0.f};
    float o[8][4];
    #pragma unroll
    for (int nt = 0; nt < 8; nt++)
        #pragma unroll
        for (int c = 0; c < 4; c++) o[nt][c] = 0.f;

    for (int kt = 0; kt <= qt; kt++) {
        const int st = kt & 1;
        if (kt < qt) { issueK(kt + 1, st ^ 1); CP_WAIT(1); }
        else         { CP_WAIT(0); }
        __syncthreads();

        // ---- S = Qs @ K^T ----
        float s[16][4];
        #pragma unroll
        for (int nt = 0; nt < 16; nt++)
            #pragma unroll
            for (int c = 0; c < 4; c++) s[nt][c] = 0.f;

        #pragma unroll
        for (int ks = 0; ks < 4; ks++) {
            uint32_t b[16][2];
            #pragma unroll
            for (int np = 0; np < 8; np++) {
                uint32_t r0,r1,r2,r3;
                ldm_x4(r0,r1,r2,r3, sb + SM_KHI(st) + (np*16 + lrow) * QSTRB + ks*32 + lcol);
                b[np*2][0] = r0;   b[np*2][1] = r2;
                b[np*2+1][0] = r1; b[np*2+1][1] = r3;
            }
            #pragma unroll
            for (int nt = 0; nt < 16; nt++)
                mma16816(s[nt][0], s[nt][1], s[nt][2], s[nt][3],
                         qh[ks][0], qh[ks][1], qh[ks][2], qh[ks][3], b[nt][0], b[nt][1]);
            #pragma unroll
            for (int nt = 0; nt < 16; nt++)
                mma16816(s[nt][0], s[nt][1], s[nt][2], s[nt][3],
                         ql[ks][0], ql[ks][1], ql[ks][2], ql[ks][3], b[nt][0], b[nt][1]);
            #pragma unroll
            for (int np = 0; np < 8; np++) {
                uint32_t r0,r1,r2,r3;
                ldm_x4(r0,r1,r2,r3, sb + SM_KLO(st) + (np*16 + lrow) * QSTRB + ks*32 + lcol);
                b[np*2][0] = r0;   b[np*2][1] = r2;
                b[np*2+1][0] = r1; b[np*2+1][1] = r3;
            }
            #pragma unroll
            for (int nt = 0; nt < 16; nt++)
                mma16816(s[nt][0], s[nt][1], s[nt][2], s[nt][3],
                         qh[ks][0], qh[ks][1], qh[ks][2], qh[ks][3], b[nt][0], b[nt][1]);
        }

        if (kt == qt) {
            #pragma unroll
            for (int nt = 0; nt < 16; nt++)
                #pragma unroll
                for (int c = 0; c < 4; c++) {
                    int row = wrow + gid + (c >> 1) * 8;
                    int col = nt*8 + tig*2 + (c & 1);
                    if (col > row) s[nt][c] = -1e30f;
                }
        }

        // ---- online softmax ----
        #pragma unroll
        for (int r = 0; r < 2; r++) {
            float mx = -1e30f;
            #pragma unroll
            for (int nt = 0; nt < 16; nt++)
                mx = fmaxf(mx, fmaxf(s[nt][r*2], s[nt][r*2+1]));
            mx = fmaxf(mx, __shfl_xor_sync(0xffffffffu, mx, 1));
            mx = fmaxf(mx, __shfl_xor_sync(0xffffffffu, mx, 2));
            float mnew = fmaxf(mrow[r], mx);
            float psum = 0.f;
            #pragma unroll
            for (int nt = 0; nt < 16; nt++) {
                float p0 = __expf(s[nt][r*2]   - mnew);
                float p1 = __expf(s[nt][r*2+1] - mnew);
                s[nt][r*2] = p0; s[nt][r*2+1] = p1;
                psum += p0 + p1;
            }
            psum += __shfl_xor_sync(0xffffffffu, psum, 1);
            psum += __shfl_xor_sync(0xffffffffu, psum, 2);
            float corr = __expf(mrow[r] - mnew);
            lrow_[r] = lrow_[r] * corr + psum;
            mrow[r] = mnew;
            #pragma unroll
            for (int nt = 0; nt < 8; nt++) {
                o[nt][r*2]   *= corr;
                o[nt][r*2+1] *= corr;
            }
        }

        // ---- PV: P built in registers (D-frag == A-frag layout) ----
        #pragma unroll
        for (int ks = 0; ks < 8; ks++) {
            uint32_t pa0,pa1,pa2,pa3, pb0,pb1,pb2,pb3;
            split2(s[2*ks][0],   s[2*ks][1],   pa0, pb0);
            split2(s[2*ks][2],   s[2*ks][3],   pa1, pb1);
            split2(s[2*ks+1][0], s[2*ks+1][1], pa2, pb2);
            split2(s[2*ks+1][2], s[2*ks+1][3], pa3, pb3);
            #pragma unroll
            for (int nb = 0; nb < 4; nb++) {
                uint32_t r0,r1,r2,r3;
                ldm_x4t(r0,r1,r2,r3, sb + SM_KHI(st) + (ks*16 + lrow) * QSTRB + nb*32 + lcol);
                mma16816(o[nb*2][0],   o[nb*2][1],   o[nb*2][2],   o[nb*2][3],
                         pa0,pa1,pa2,pa3, r0, r1);
                mma16816(o[nb*2+1][0], o[nb*2+1][1], o[nb*2+1][2], o[nb*2+1][3],
                         pa0,pa1,pa2,pa3, r2, r3);
                mma16816(o[nb*2][0],   o[nb*2][1],   o[nb*2][2],   o[nb*2][3],
                         pb0,pb1,pb2,pb3, r0, r1);
                mma16816(o[nb*2+1][0], o[nb*2+1][1], o[nb*2+1][2], o[nb*2+1][3],
                         pb0,pb1,pb2,pb3, r2, r3);
            }
            #pragma unroll
            for (int nb = 0; nb < 4; nb++) {
                uint32_t r0,r1,r2,r3;
                ldm_x4t(r0,r1,r2,r3, sb + SM_KLO(st) + (ks*16 + lrow) * QSTRB + nb*32 + lcol);
                mma16816(o[nb*2][0],   o[nb*2][1],   o[nb*2][2],   o[nb*2][3],
                         pa0,pa1,pa2,pa3, r0, r1);
                mma16816(o[nb*2+1][0], o[nb*2+1][1], o[nb*2+1][2], o[nb*2+1][3],
                         pa0,pa1,pa2,pa3, r2, r3);
            }
        }
        __syncthreads();
    }

    const int b = bh >> 4, h = bh & 15;
    #pragma unroll
    for (int r = 0; r < 2; r++) {
        float inv = 1.0f / lrow_[r];
        int t = qt*128 + wrow + gid + r*8;
        #pragma unroll
        for (int nt = 0; nt < 8; nt++) {
            float x0 = o[nt][r*2] * inv, x1 = o[nt][r*2+1] * inv;
            uint32_t hv, lv;
            split2(x0, x1, hv, lv);
            size_t idx = ((size_t)b * T_ + t) * E_ + h*64 + nt*8 + tig*2;
            *(bf162*)(aohi + idx) = *(bf162*)&hv;
            *(bf162*)(aolo + idx) = *(bf162*)&lv;
        }
    }
}

// ---------------------------------------------------------------------------
extern "C" void kernel_launch(void* const* d_in, const int* in_sizes, int n_in,
                              void* d_out, int out_size)
{
    const float* q  = (const float*)d_in[0];
    const float* k  = (const float*)d_in[1];
    // d_in[2] (v) dead: share_kv
    const float* Wq = (const float*)d_in[3];
    const float* Wk = (const float*)d_in[4];
    const float* Wo = (const float*)d_in[5];
    float* out = (float*)d_out;

    bf16 *pqhi,*pqlo,*pkhi,*pklo,*pwqhi,*pwqlo,*pwkhi,*pwklo,*pwohi,*pwolo;
    bf16 *pqhh,*pqhl,*pkhh,*pkhl,*paohi,*paolo;
    cudaGetSymbolAddress((void**)&pqhi, g_qhi);   cudaGetSymbolAddress((void**)&pqlo, g_qlo);
    cudaGetSymbolAddress((void**)&pkhi, g_khi);   cudaGetSymbolAddress((void**)&pklo, g_klo);
    cudaGetSymbolAddress((void**)&pwqhi, g_wqhi); cudaGetSymbolAddress((void**)&pwqlo, g_wqlo);
    cudaGetSymbolAddress((void**)&pwkhi, g_wkhi); cudaGetSymbolAddress((void**)&pwklo, g_wklo);
    cudaGetSymbolAddress((void**)&pwohi, g_wohi); cudaGetSymbolAddress((void**)&pwolo, g_wolo);
    cudaGetSymbolAddress((void**)&pqhh, g_qhh);   cudaGetSymbolAddress((void**)&pqhl, g_qhl);
    cudaGetSymbolAddress((void**)&pkhh, g_khh);   cudaGetSymbolAddress((void**)&pkhl, g_khl);
    cudaGetSymbolAddress((void**)&paohi, g_aohi); cudaGetSymbolAddress((void**)&paolo, g_aolo);

    static bool attr_done = false;
    if (!attr_done) {
        cudaFuncSetAttribute(attn_mma, cudaFuncAttributeMaxDynamicSharedMemorySize, ATTN_SMEM);
        cudaFuncSetAttribute(gemm_proj, cudaFuncAttributeMaxDynamicSharedMemorySize, GEMM_SMEM);
        cudaFuncSetAttribute(gemm_out, cudaFuncAttributeMaxDynamicSharedMemorySize, GEMM_SMEM);
        attr_done = true;
    }

    const int total4 = 2*N4BIG + 3*N4W;
    split_all<<<(total4 + 255)/256, 256>>>(
        (const float4*)q, (const float4*)k,
        (const float4*)Wq, (const float4*)Wk, (const float4*)Wo,
        (bf162*)pqhi, (bf162*)pqlo, (bf162*)pkhi, (bf162*)pklo,
        (bf162*)pwqhi, (bf162*)pwqlo, (bf162*)pwkhi, (bf162*)pwklo,
        (bf162*)pwohi, (bf162*)pwolo);

    gemm_proj<<<dim3(8, 128), 256, GEMM_SMEM>>>(pqhi, pqlo, pkhi, pklo,
                                                pwqhi, pwqlo, pwkhi, pwklo,
                                                pqhh, pqhl, pkhh, pkhl);

    attn_mma<<<dim3(16, B_*H_), 256, ATTN_SMEM>>>(pqhh, pqhl, pkhh, pkhl, paohi, paolo);

    gemm_out<<<dim3(8, 64), 256, GEMM_SMEM>>>(paohi, paolo, pwohi, pwolo, out);
}

// round 9
// speedup vs baseline: 2.9882x; 1.0044x over previous
#include <cuda_runtime.h>
#include <cuda_bf16.h>
#include <math.h>
#include <stdint.h>

#define B_ 4
#define T_ 2048
#define E_ 1024
#define H_ 16
#define D_ 64
#define M_TOT (B_*T_)   // 8192

typedef __nv_bfloat16 bf16;
typedef __nv_bfloat162 bf162;

// ---------------- scratch (allocation-free) ----------------
__device__ __align__(16) bf16 g_qhi[M_TOT*E_], g_qlo[M_TOT*E_];
__device__ __align__(16) bf16 g_khi[M_TOT*E_], g_klo[M_TOT*E_];
__device__ __align__(16) bf16 g_wqhi[E_*E_],  g_wqlo[E_*E_];
__device__ __align__(16) bf16 g_wkhi[E_*E_],  g_wklo[E_*E_];
__device__ __align__(16) bf16 g_wohi[E_*E_],  g_wolo[E_*E_];
__device__ __align__(16) bf16 g_qhh[M_TOT*E_], g_qhl[M_TOT*E_];
__device__ __align__(16) bf16 g_khh[M_TOT*E_], g_khl[M_TOT*E_];
__device__ __align__(16) bf16 g_aohi[M_TOT*E_], g_aolo[M_TOT*E_];

// ---------------- helpers ----------------
__device__ __forceinline__ uint32_t smem_u32(const void* p) {
    uint32_t a;
    asm("{ .reg .u64 t; cvta.to.shared.u64 t, %1; cvt.u32.u64 %0, t; }" : "=r"(a) : "l"(p));
    return a;
}
__device__ __forceinline__ void cp16(uint32_t saddr, const void* gaddr) {
    asm volatile("cp.async.cg.shared.global [%0], [%1], 16;" :: "r"(saddr), "l"(gaddr));
}
#define CP_COMMIT() asm volatile("cp.async.commit_group;" ::: "memory")
#define CP_WAIT(n)  asm volatile("cp.async.wait_group %0;" :: "n"(n) : "memory")

__device__ __forceinline__ void ldm_x4(uint32_t& r0, uint32_t& r1, uint32_t& r2, uint32_t& r3,
                                       uint32_t addr) {
    asm volatile("ldmatrix.sync.aligned.m8n8.x4.shared.b16 {%0,%1,%2,%3}, [%4];"
                 : "=r"(r0), "=r"(r1), "=r"(r2), "=r"(r3) : "r"(addr));
}
__device__ __forceinline__ void ldm_x4t(uint32_t& r0, uint32_t& r1, uint32_t& r2, uint32_t& r3,
                                        uint32_t addr) {
    asm volatile("ldmatrix.sync.aligned.m8n8.x4.trans.shared.b16 {%0,%1,%2,%3}, [%4];"
                 : "=r"(r0), "=r"(r1), "=r"(r2), "=r"(r3) : "r"(addr));
}
__device__ __forceinline__ void mma16816(float& d0, float& d1, float& d2, float& d3,
                                         uint32_t a0, uint32_t a1, uint32_t a2, uint32_t a3,
                                         uint32_t b0, uint32_t b1) {
    asm volatile("mma.sync.aligned.m16n8k16.row.col.f32.bf16.bf16.f32 "
                 "{%0,%1,%2,%3}, {%4,%5,%6,%7}, {%8,%9}, {%0,%1,%2,%3};"
                 : "+f"(d0), "+f"(d1), "+f"(d2), "+f"(d3)
                 : "r"(a0), "r"(a1), "r"(a2), "r"(a3), "r"(b0), "r"(b1));
}
__device__ __forceinline__ void split2(float x0, float x1, uint32_t& hi, uint32_t& lo) {
    bf16 h0 = __float2bfloat16_rn(x0), h1 = __float2bfloat16_rn(x1);
    bf162 hv(h0, h1);
    bf162 lv(__float2bfloat16_rn(x0 - __bfloat162float(h0)),
             __float2bfloat16_rn(x1 - __bfloat162float(h1)));
    hi = *(uint32_t*)&hv;
    lo = *(uint32_t*)&lv;
}

// ---------------- fused fp32 -> bf16 hi/lo split ----------------
#define N4BIG (M_TOT*E_/4)
#define N4W   (E_*E_/4)
__global__ __launch_bounds__(256) void split_all(
    const float4* __restrict__ q, const float4* __restrict__ k,
    const float4* __restrict__ wq, const float4* __restrict__ wk,
    const float4* __restrict__ wo,
    bf162* __restrict__ qhi, bf162* __restrict__ qlo,
    bf162* __restrict__ khi, bf162* __restrict__ klo,
    bf162* __restrict__ wqhi, bf162* __restrict__ wqlo,
    bf162* __restrict__ wkhi, bf162* __restrict__ wklo,
    bf162* __restrict__ wohi, bf162* __restrict__ wolo)
{
    int i = blockIdx.x * 256 + threadIdx.x;
    const float4* src; bf162 *hi, *lo;
    if      (i < N4BIG)                { src = q;  hi = qhi;  lo = qlo; }
    else if (i < 2*N4BIG)              { i -= N4BIG;   src = k;  hi = khi;  lo = klo; }
    else if (i < 2*N4BIG + N4W)        { i -= 2*N4BIG; src = wq; hi = wqhi; lo = wqlo; }
    else if (i < 2*N4BIG + 2*N4W)      { i -= 2*N4BIG + N4W;   src = wk; hi = wkhi; lo = wklo; }
    else if (i < 2*N4BIG + 3*N4W)      { i -= 2*N4BIG + 2*N4W; src = wo; hi = wohi; lo = wolo; }
    else return;
    float4 v = src[i];
    uint32_t h01, l01, h23, l23;
    split2(v.x, v.y, h01, l01);
    split2(v.z, v.w, h23, l23);
    hi[2*i]   = *(bf162*)&h01;  hi[2*i+1] = *(bf162*)&h23;
    lo[2*i]   = *(bf162*)&l01;  lo[2*i+1] = *(bf162*)&l23;
}

// ---------------------------------------------------------------------------
// HMMA GEMM core: C = A @ W^T, bf16-split, pass-major inner loop (round 9).
// ---------------------------------------------------------------------------
#define SROWB 80
#define TILEB (128 * SROWB)
#define NCHUNK 32
#define GEMM_SMEM (8 * TILEB)

template<int MODE>
__device__ __forceinline__ void gemm_body(const bf16* __restrict__ Ahi,
                                          const bf16* __restrict__ Alo,
                                          const bf16* __restrict__ Bhi,
                                          const bf16* __restrict__ Blo,
                                          float* __restrict__ Cf,
                                          bf16* __restrict__ Chi,
                                          bf16* __restrict__ Clo,
                                          float scale, int m0, int n0, char* smem)
{
    const int tid = threadIdx.x;
    const int wid = tid >> 5, lid = tid & 31;
    const int warp_m = wid & 3, warp_n = wid >> 2;
    const int gr = tid >> 2, gc = tid & 3;
    const uint32_t sb = smem_u32(smem);

    float acc[2][8][4];
    #pragma unroll
    for (int i = 0; i < 2; i++)
        #pragma unroll
        for (int j = 0; j < 8; j++)
            #pragma unroll
            for (int c = 0; c < 4; c++) acc[i][j][c] = 0.f;

    auto issue = [&](int kc) {
        const int st = kc & 1;
        const size_t colB = (size_t)kc * 64;
        const char* srcs[4] = { (const char*)Ahi, (const char*)Alo,
                                (const char*)Bhi, (const char*)Blo };
        const int base[4] = { m0, m0, n0, n0 };
        #pragma unroll
        for (int t = 0; t < 4; t++) {
            const char* S = srcs[t];
            uint32_t dst = sb + (st * 4 + t) * TILEB;
            #pragma unroll
            for (int q = 0; q < 2; q++) {
                int r = gr + q * 64;
                cp16(dst + r * SROWB + gc * 16,
                     S + (size_t)(base[t] + r) * 2048 + colB + gc * 16);
            }
        }
        CP_COMMIT();
    };

    issue(0);
    for (int i = 0; i < NCHUNK; i++) {
        if (i + 1 < NCHUNK) { issue(i + 1); CP_WAIT(1); }
        else                { CP_WAIT(0); }
        __syncthreads();

        const int st = i & 1;
        const uint32_t bAhi = sb + (st * 4 + 0) * TILEB;
        const uint32_t bAlo = sb + (st * 4 + 1) * TILEB;
        const uint32_t bBhi = sb + (st * 4 + 2) * TILEB;
        const uint32_t bBlo = sb + (st * 4 + 3) * TILEB;
        const int lrow = lid & 15, lcol = (lid >> 4) * 16;

        #pragma unroll
        for (int s = 0; s < 2; s++) {
            uint32_t ah[2][4], al[2][4];
            #pragma unroll
            for (int mt = 0; mt < 2; mt++) {
                uint32_t off = (warp_m*32 + mt*16 + lrow) * SROWB + s*32 + lcol;
                ldm_x4(ah[mt][0], ah[mt][1], ah[mt][2], ah[mt][3], bAhi + off);
                ldm_x4(al[mt][0], al[mt][1], al[mt][2], al[mt][3], bAlo + off);
            }
            // pass0: Ahi x Bhi — 16 independent mma
            #pragma unroll
            for (int np = 0; np < 4; np++) {
                uint32_t off = (warp_n*64 + np*16 + lrow) * SROWB + s*32 + lcol;
                uint32_t h0,h1,h2,h3;
                ldm_x4(h0,h1,h2,h3, bBhi + off);
                #pragma unroll
                for (int mt = 0; mt < 2; mt++) {
                    mma16816(acc[mt][np*2][0],acc[mt][np*2][1],acc[mt][np*2][2],acc[mt][np*2][3],
                             ah[mt][0],ah[mt][1],ah[mt][2],ah[mt][3], h0, h2);
                    mma16816(acc[mt][np*2+1][0],acc[mt][np*2+1][1],acc[mt][np*2+1][2],acc[mt][np*2+1][3],
                             ah[mt][0],ah[mt][1],ah[mt][2],ah[mt][3], h1, h3);
                }
            }
            // pass1: Ahi x Blo — 16 independent mma
            #pragma unroll
            for (int np = 0; np < 4; np++) {
                uint32_t off = (warp_n*64 + np*16 + lrow) * SROWB + s*32 + lcol;
                uint32_t l0,l1,l2,l3;
                ldm_x4(l0,l1,l2,l3, bBlo + off);
                #pragma unroll
                for (int mt = 0; mt < 2; mt++) {
                    mma16816(acc[mt][np*2][0],acc[mt][np*2][1],acc[mt][np*2][2],acc[mt][np*2][3],
                             ah[mt][0],ah[mt][1],ah[mt][2],ah[mt][3], l0, l2);
                    mma16816(acc[mt][np*2+1][0],acc[mt][np*2+1][1],acc[mt][np*2+1][2],acc[mt][np*2+1][3],
                             ah[mt][0],ah[mt][1],ah[mt][2],ah[mt][3], l1, l3);
                }
            }
            // pass2: Alo x Bhi — 16 independent mma
            #pragma unroll
            for (int np = 0; np < 4; np++) {
                uint32_t off = (warp_n*64 + np*16 + lrow) * SROWB + s*32 + lcol;
                uint32_t h0,h1,h2,h3;
                ldm_x4(h0,h1,h2,h3, bBhi + off);
                #pragma unroll
                for (int mt = 0; mt < 2; mt++) {
                    mma16816(acc[mt][np*2][0],acc[mt][np*2][1],acc[mt][np*2][2],acc[mt][np*2][3],
                             al[mt][0],al[mt][1],al[mt][2],al[mt][3], h0, h2);
                    mma16816(acc[mt][np*2+1][0],acc[mt][np*2+1][1],acc[mt][np*2+1][2],acc[mt][np*2+1][3],
                             al[mt][0],al[mt][1],al[mt][2],al[mt][3], h1, h3);
                }
            }
        }
        __syncthreads();
    }

    const int gid = lid >> 2, tig = lid & 3;
    #pragma unroll
    for (int mt = 0; mt < 2; mt++) {
        #pragma unroll
        for (int nt = 0; nt < 8; nt++) {
            int m = m0 + warp_m*32 + mt*16 + gid;
            int n = n0 + warp_n*64 + nt*8 + tig*2;
            #pragma unroll
            for (int half = 0; half < 2; half++) {
                int mm = m + half * 8;
                float x0 = acc[mt][nt][half*2+0], x1 = acc[mt][nt][half*2+1];
                if (MODE == 0) {
                    *(float2*)(Cf + (size_t)mm * E_ + n) = make_float2(x0, x1);
                } else {
                    x0 *= scale; x1 *= scale;
                    uint32_t hv, lv;
                    split2(x0, x1, hv, lv);
                    int b = mm >> 11, t = mm & (T_ - 1);
                    int h = n >> 6,  d = n & 63;
                    size_t idx = (((size_t)b * H_ + h) * T_ + t) * D_ + d;
                    *(bf162*)(Chi + idx) = *(bf162*)&hv;
                    *(bf162*)(Clo + idx) = *(bf162*)&lv;
                }
            }
        }
    }
}

__global__ __launch_bounds__(256, 2) void gemm_proj(
    const bf16* __restrict__ qAhi, const bf16* __restrict__ qAlo,
    const bf16* __restrict__ kAhi, const bf16* __restrict__ kAlo,
    const bf16* __restrict__ WqHi, const bf16* __restrict__ WqLo,
    const bf16* __restrict__ WkHi, const bf16* __restrict__ WkLo,
    bf16* __restrict__ qChi, bf16* __restrict__ qClo,
    bf16* __restrict__ kChi, bf16* __restrict__ kClo)
{
    extern __shared__ __align__(16) char smem[];
    const int y = blockIdx.y;
    const int n0 = blockIdx.x * 128;
    if (y < 64) {
        gemm_body<1>(qAhi, qAlo, WqHi, WqLo, nullptr, qChi, qClo,
                     0.125f, y * 128, n0, smem);
    } else {
        gemm_body<1>(kAhi, kAlo, WkHi, WkLo, nullptr, kChi, kClo,
                     1.0f, (y - 64) * 128, n0, smem);
    }
}

__global__ __launch_bounds__(256, 2) void gemm_out(
    const bf16* __restrict__ Ahi, const bf16* __restrict__ Alo,
    const bf16* __restrict__ Bhi, const bf16* __restrict__ Blo,
    float* __restrict__ Cf)
{
    extern __shared__ __align__(16) char smem[];
    gemm_body<0>(Ahi, Alo, Bhi, Blo, Cf, nullptr, nullptr,
                 1.0f, blockIdx.y * 128, blockIdx.x * 128, smem);
}

// ---------------------------------------------------------------------------
// Causal flash attention, V == K (share_kv), bf16-split HMMA, register-P,
// PV loop reordered pass-major (round 9).
// ---------------------------------------------------------------------------
#define QSTRB 144
#define KSTG  (128*QSTRB)
#define SM_KHI(st) ((st)*2*KSTG)
#define SM_KLO(st) ((st)*2*KSTG + KSTG)
#define ATTN_SMEM (4*KSTG)

__global__ __launch_bounds__(256) void attn_mma(const bf16* __restrict__ qhh,
                                                const bf16* __restrict__ qhl,
                                                const bf16* __restrict__ khh,
                                                const bf16* __restrict__ khl,
                                                bf16* __restrict__ aohi,
                                                bf16* __restrict__ aolo)
{
    extern __shared__ __align__(16) char smem[];
    const uint32_t sb = smem_u32(smem);
    const int tid = threadIdx.x;
    const int wid = tid >> 5, lid = tid & 31;
    const int wrow = wid * 16;
    const int gid = lid >> 2, tig = lid & 3;
    const int lrow = lid & 15, lcol = (lid >> 4) * 16;
    const int qt = 15 - (int)blockIdx.x;
    const int bh = blockIdx.y;

    const char* Khi = (const char*)(khh + (size_t)bh * T_ * D_);
    const char* Klo = (const char*)(khl + (size_t)bh * T_ * D_);

    auto issueK = [&](int kt, int st) {
        #pragma unroll
        for (int i = 0; i < 4; i++) {
            int idx = tid + i * 256;
            int r = idx >> 3, c = (idx & 7) * 16;
            cp16(sb + SM_KHI(st) + r * QSTRB + c, Khi + ((size_t)kt * 128 + r) * 128 + c);
            cp16(sb + SM_KLO(st) + r * QSTRB + c, Klo + ((size_t)kt * 128 + r) * 128 + c);
        }
        CP_COMMIT();
    };

    issueK(0, 0);

    uint32_t qh[4][4], ql[4][4];
    {
        const bf16* Qgh = qhh + (size_t)bh * T_ * D_ + (size_t)(qt * 128 + wrow) * D_;
        const bf16* Qgl = qhl + (size_t)bh * T_ * D_ + (size_t)(qt * 128 + wrow) * D_;
        #pragma unroll
        for (int ks = 0; ks < 4; ks++) {
            int c0 = ks * 16 + tig * 2;
            qh[ks][0] = *(const uint32_t*)(Qgh + (size_t)gid * D_ + c0);
            qh[ks][1] = *(const uint32_t*)(Qgh + (size_t)(gid + 8) * D_ + c0);
            qh[ks][2] = *(const uint32_t*)(Qgh + (size_t)gid * D_ + c0 + 8);
            qh[ks][3] = *(const uint32_t*)(Qgh + (size_t)(gid + 8) * D_ + c0 + 8);
            ql[ks][0] = *(const uint32_t*)(Qgl + (size_t)gid * D_ + c0);
            ql[ks][1] = *(const uint32_t*)(Qgl + (size_t)(gid + 8) * D_ + c0);
            ql[ks][2] = *(const uint32_t*)(Qgl + (size_t)gid * D_ + c0 + 8);
            ql[ks][3] = *(const uint32_t*)(Qgl + (size_t)(gid + 8) * D_ + c0 + 8);
        }
    }

    float mrow[2] = {-1e30f, -1e30f};
    float lrow_[2] = {0.f, 0.f};
    float o[8][4];
    #pragma unroll
    for (int nt = 0; nt < 8; nt++)
        #pragma unroll
        for (int c = 0; c < 4; c++) o[nt][c] = 0.f;

    for (int kt = 0; kt <= qt; kt++) {
        const int st = kt & 1;
        if (kt < qt) { issueK(kt + 1, st ^ 1); CP_WAIT(1); }
        else         { CP_WAIT(0); }
        __syncthreads();

        // ---- S = Qs @ K^T (pass-major, already dependency-clean) ----
        float s[16][4];
        #pragma unroll
        for (int nt = 0; nt < 16; nt++)
            #pragma unroll
            for (int c = 0; c < 4; c++) s[nt][c] = 0.f;

        #pragma unroll
        for (int ks = 0; ks < 4; ks++) {
            uint32_t b[16][2];
            #pragma unroll
            for (int np = 0; np < 8; np++) {
                uint32_t r0,r1,r2,r3;
                ldm_x4(r0,r1,r2,r3, sb + SM_KHI(st) + (np*16 + lrow) * QSTRB + ks*32 + lcol);
                b[np*2][0] = r0;   b[np*2][1] = r2;
                b[np*2+1][0] = r1; b[np*2+1][1] = r3;
            }
            #pragma unroll
            for (int nt = 0; nt < 16; nt++)
                mma16816(s[nt][0], s[nt][1], s[nt][2], s[nt][3],
                         qh[ks][0], qh[ks][1], qh[ks][2], qh[ks][3], b[nt][0], b[nt][1]);
            #pragma unroll
            for (int nt = 0; nt < 16; nt++)
                mma16816(s[nt][0], s[nt][1], s[nt][2], s[nt][3],
                         ql[ks][0], ql[ks][1], ql[ks][2], ql[ks][3], b[nt][0], b[nt][1]);
            #pragma unroll
            for (int np = 0; np < 8; np++) {
                uint32_t r0,r1,r2,r3;
                ldm_x4(r0,r1,r2,r3, sb + SM_KLO(st) + (np*16 + lrow) * QSTRB + ks*32 + lcol);
                b[np*2][0] = r0;   b[np*2][1] = r2;
                b[np*2+1][0] = r1; b[np*2+1][1] = r3;
            }
            #pragma unroll
            for (int nt = 0; nt < 16; nt++)
                mma16816(s[nt][0], s[nt][1], s[nt][2], s[nt][3],
                         qh[ks][0], qh[ks][1], qh[ks][2], qh[ks][3], b[nt][0], b[nt][1]);
        }

        if (kt == qt) {
            #pragma unroll
            for (int nt = 0; nt < 16; nt++)
                #pragma unroll
                for (int c = 0; c < 4; c++) {
                    int row = wrow + gid + (c >> 1) * 8;
                    int col = nt*8 + tig*2 + (c & 1);
                    if (col > row) s[nt][c] = -1e30f;
                }
        }

        // ---- online softmax ----
        #pragma unroll
        for (int r = 0; r < 2; r++) {
            float mx = -1e30f;
            #pragma unroll
            for (int nt = 0; nt < 16; nt++)
                mx = fmaxf(mx, fmaxf(s[nt][r*2], s[nt][r*2+1]));
            mx = fmaxf(mx, __shfl_xor_sync(0xffffffffu, mx, 1));
            mx = fmaxf(mx, __shfl_xor_sync(0xffffffffu, mx, 2));
            float mnew = fmaxf(mrow[r], mx);
            float psum = 0.f;
            #pragma unroll
            for (int nt = 0; nt < 16; nt++) {
                float p0 = __expf(s[nt][r*2]   - mnew);
                float p1 = __expf(s[nt][r*2+1] - mnew);
                s[nt][r*2] = p0; s[nt][r*2+1] = p1;
                psum += p0 + p1;
            }
            psum += __shfl_xor_sync(0xffffffffu, psum, 1);
            psum += __shfl_xor_sync(0xffffffffu, psum, 2);
            float corr = __expf(mrow[r] - mnew);
            lrow_[r] = lrow_[r] * corr + psum;
            mrow[r] = mnew;
            #pragma unroll
            for (int nt = 0; nt < 8; nt++) {
                o[nt][r*2]   *= corr;
                o[nt][r*2+1] *= corr;
            }
        }

        // ---- PV pass-major: V frags loaded once, 8 independent mma per pass ----
        #pragma unroll
        for (int ks = 0; ks < 8; ks++) {
            uint32_t pa0,pa1,pa2,pa3, pb0,pb1,pb2,pb3;
            split2(s[2*ks][0],   s[2*ks][1],   pa0, pb0);
            split2(s[2*ks][2],   s[2*ks][3],   pa1, pb1);
            split2(s[2*ks+1][0], s[2*ks+1][1], pa2, pb2);
            split2(s[2*ks+1][2], s[2*ks+1][3], pa3, pb3);
            uint32_t v[4][4];
            #pragma unroll
            for (int nb = 0; nb < 4; nb++)
                ldm_x4t(v[nb][0], v[nb][1], v[nb][2], v[nb][3],
                        sb + SM_KHI(st) + (ks*16 + lrow) * QSTRB + nb*32 + lcol);
            #pragma unroll
            for (int nb = 0; nb < 4; nb++) {
                mma16816(o[nb*2][0],   o[nb*2][1],   o[nb*2][2],   o[nb*2][3],
                         pa0,pa1,pa2,pa3, v[nb][0], v[nb][1]);
                mma16816(o[nb*2+1][0], o[nb*2+1][1], o[nb*2+1][2], o[nb*2+1][3],
                         pa0,pa1,pa2,pa3, v[nb][2], v[nb][3]);
            }
            #pragma unroll
            for (int nb = 0; nb < 4; nb++) {
                mma16816(o[nb*2][0],   o[nb*2][1],   o[nb*2][2],   o[nb*2][3],
                         pb0,pb1,pb2,pb3, v[nb][0], v[nb][1]);
                mma16816(o[nb*2+1][0], o[nb*2+1][1], o[nb*2+1][2], o[nb*2+1][3],
                         pb0,pb1,pb2,pb3, v[nb][2], v[nb][3]);
            }
            #pragma unroll
            for (int nb = 0; nb < 4; nb++)
                ldm_x4t(v[nb][0], v[nb][1], v[nb][2], v[nb][3],
                        sb + SM_KLO(st) + (ks*16 + lrow) * QSTRB + nb*32 + lcol);
            #pragma unroll
            for (int nb = 0; nb < 4; nb++) {
                mma16816(o[nb*2][0],   o[nb*2][1],   o[nb*2][2],   o[nb*2][3],
                         pa0,pa1,pa2,pa3, v[nb][0], v[nb][1]);
                mma16816(o[nb*2+1][0], o[nb*2+1][1], o[nb*2+1][2], o[nb*2+1][3],
                         pa0,pa1,pa2,pa3, v[nb][2], v[nb][3]);
            }
        }
        __syncthreads();
    }

    const int b = bh >> 4, h = bh & 15;
    #pragma unroll
    for (int r = 0; r < 2; r++) {
        float inv = 1.0f / lrow_[r];
        int t = qt*128 + wrow + gid + r*8;
        #pragma unroll
        for (int nt = 0; nt < 8; nt++) {
            float x0 = o[nt][r*2] * inv, x1 = o[nt][r*2+1] * inv;
            uint32_t hv, lv;
            split2(x0, x1, hv, lv);
            size_t idx = ((size_t)b * T_ + t) * E_ + h*64 + nt*8 + tig*2;
            *(bf162*)(aohi + idx) = *(bf162*)&hv;
            *(bf162*)(aolo + idx) = *(bf162*)&lv;
        }
    }
}

// ---------------------------------------------------------------------------
extern "C" void kernel_launch(void* const* d_in, const int* in_sizes, int n_in,
                              void* d_out, int out_size)
{
    const float* q  = (const float*)d_in[0];
    const float* k  = (const float*)d_in[1];
    // d_in[2] (v) dead: share_kv
    const float* Wq = (const float*)d_in[3];
    const float* Wk = (const float*)d_in[4];
    const float* Wo = (const float*)d_in[5];
    float* out = (float*)d_out;

    bf16 *pqhi,*pqlo,*pkhi,*pklo,*pwqhi,*pwqlo,*pwkhi,*pwklo,*pwohi,*pwolo;
    bf16 *pqhh,*pqhl,*pkhh,*pkhl,*paohi,*paolo;
    cudaGetSymbolAddress((void**)&pqhi, g_qhi);   cudaGetSymbolAddress((void**)&pqlo, g_qlo);
    cudaGetSymbolAddress((void**)&pkhi, g_khi);   cudaGetSymbolAddress((void**)&pklo, g_klo);
    cudaGetSymbolAddress((void**)&pwqhi, g_wqhi); cudaGetSymbolAddress((void**)&pwqlo, g_wqlo);
    cudaGetSymbolAddress((void**)&pwkhi, g_wkhi); cudaGetSymbolAddress((void**)&pwklo, g_wklo);
    cudaGetSymbolAddress((void**)&pwohi, g_wohi); cudaGetSymbolAddress((void**)&pwolo, g_wolo);
    cudaGetSymbolAddress((void**)&pqhh, g_qhh);   cudaGetSymbolAddress((void**)&pqhl, g_qhl);
    cudaGetSymbolAddress((void**)&pkhh, g_khh);   cudaGetSymbolAddress((void**)&pkhl, g_khl);
    cudaGetSymbolAddress((void**)&paohi, g_aohi); cudaGetSymbolAddress((void**)&paolo, g_aolo);

    static bool attr_done = false;
    if (!attr_done) {
        cudaFuncSetAttribute(attn_mma, cudaFuncAttributeMaxDynamicSharedMemorySize, ATTN_SMEM);
        cudaFuncSetAttribute(gemm_proj, cudaFuncAttributeMaxDynamicSharedMemorySize, GEMM_SMEM);
        cudaFuncSetAttribute(gemm_out, cudaFuncAttributeMaxDynamicSharedMemorySize, GEMM_SMEM);
        attr_done = true;
    }

    const int total4 = 2*N4BIG + 3*N4W;
    split_all<<<(total4 + 255)/256, 256>>>(
        (const float4*)q, (const float4*)k,
        (const float4*)Wq, (const float4*)Wk, (const float4*)Wo,
        (bf162*)pqhi, (bf162*)pqlo, (bf162*)pkhi, (bf162*)pklo,
        (bf162*)pwqhi, (bf162*)pwqlo, (bf162*)pwkhi, (bf162*)pwklo,
        (bf162*)pwohi, (bf162*)pwolo);

    gemm_proj<<<dim3(8, 128), 256, GEMM_SMEM>>>(pqhi, pqlo, pkhi, pklo,
                                                pwqhi, pwqlo, pwkhi, pwklo,
                                                pqhh, pqhl, pkhh, pkhl);

    attn_mma<<<dim3(16, B_*H_), 256, ATTN_SMEM>>>(pqhh, pqhl, pkhh, pkhl, paohi, paolo);

    gemm_out<<<dim3(8, 64), 256, GEMM_SMEM>>>(paohi, paolo, pwohi, pwolo, out);
}

// round 10
// speedup vs baseline: 3.0158x; 1.0092x over previous
#include <cuda_runtime.h>
#include <cuda_bf16.h>
#include <math.h>
#include <stdint.h>

#define B_ 4
#define T_ 2048
#define E_ 1024
#define H_ 16
#define D_ 64
#define M_TOT (B_*T_)   // 8192

typedef __nv_bfloat16 bf16;
typedef __nv_bfloat162 bf162;

// ---------------- scratch (allocation-free) ----------------
__device__ __align__(16) bf16 g_qhi[M_TOT*E_], g_qlo[M_TOT*E_];
__device__ __align__(16) bf16 g_khi[M_TOT*E_], g_klo[M_TOT*E_];
__device__ __align__(16) bf16 g_wqhi[E_*E_],  g_wqlo[E_*E_];
__device__ __align__(16) bf16 g_wkhi[E_*E_],  g_wklo[E_*E_];
__device__ __align__(16) bf16 g_wohi[E_*E_],  g_wolo[E_*E_];
__device__ __align__(16) bf16 g_qhh[M_TOT*E_], g_qhl[M_TOT*E_];
__device__ __align__(16) bf16 g_khh[M_TOT*E_], g_khl[M_TOT*E_];
__device__ __align__(16) bf16 g_aohi[M_TOT*E_], g_aolo[M_TOT*E_];

// ---------------- helpers ----------------
__device__ __forceinline__ uint32_t smem_u32(const void* p) {
    uint32_t a;
    asm("{ .reg .u64 t; cvta.to.shared.u64 t, %1; cvt.u32.u64 %0, t; }" : "=r"(a) : "l"(p));
    return a;
}
__device__ __forceinline__ void cp16(uint32_t saddr, const void* gaddr) {
    asm volatile("cp.async.cg.shared.global [%0], [%1], 16;" :: "r"(saddr), "l"(gaddr));
}
#define CP_COMMIT() asm volatile("cp.async.commit_group;" ::: "memory")
#define CP_WAIT(n)  asm volatile("cp.async.wait_group %0;" :: "n"(n) : "memory")

__device__ __forceinline__ void ldm_x4(uint32_t& r0, uint32_t& r1, uint32_t& r2, uint32_t& r3,
                                       uint32_t addr) {
    asm volatile("ldmatrix.sync.aligned.m8n8.x4.shared.b16 {%0,%1,%2,%3}, [%4];"
                 : "=r"(r0), "=r"(r1), "=r"(r2), "=r"(r3) : "r"(addr));
}
__device__ __forceinline__ void ldm_x4t(uint32_t& r0, uint32_t& r1, uint32_t& r2, uint32_t& r3,
                                        uint32_t addr) {
    asm volatile("ldmatrix.sync.aligned.m8n8.x4.trans.shared.b16 {%0,%1,%2,%3}, [%4];"
                 : "=r"(r0), "=r"(r1), "=r"(r2), "=r"(r3) : "r"(addr));
}
__device__ __forceinline__ void mma16816(float& d0, float& d1, float& d2, float& d3,
                                         uint32_t a0, uint32_t a1, uint32_t a2, uint32_t a3,
                                         uint32_t b0, uint32_t b1) {
    asm volatile("mma.sync.aligned.m16n8k16.row.col.f32.bf16.bf16.f32 "
                 "{%0,%1,%2,%3}, {%4,%5,%6,%7}, {%8,%9}, {%0,%1,%2,%3};"
                 : "+f"(d0), "+f"(d1), "+f"(d2), "+f"(d3)
                 : "r"(a0), "r"(a1), "r"(a2), "r"(a3), "r"(b0), "r"(b1));
}
__device__ __forceinline__ void split2(float x0, float x1, uint32_t& hi, uint32_t& lo) {
    bf16 h0 = __float2bfloat16_rn(x0), h1 = __float2bfloat16_rn(x1);
    bf162 hv(h0, h1);
    bf162 lv(__float2bfloat16_rn(x0 - __bfloat162float(h0)),
             __float2bfloat16_rn(x1 - __bfloat162float(h1)));
    hi = *(uint32_t*)&hv;
    lo = *(uint32_t*)&lv;
}

// ---------------- fused fp32 -> bf16 hi/lo split ----------------
#define N4BIG (M_TOT*E_/4)
#define N4W   (E_*E_/4)
__global__ __launch_bounds__(256) void split_all(
    const float4* __restrict__ q, const float4* __restrict__ k,
    const float4* __restrict__ wq, const float4* __restrict__ wk,
    const float4* __restrict__ wo,
    bf162* __restrict__ qhi, bf162* __restrict__ qlo,
    bf162* __restrict__ khi, bf162* __restrict__ klo,
    bf162* __restrict__ wqhi, bf162* __restrict__ wqlo,
    bf162* __restrict__ wkhi, bf162* __restrict__ wklo,
    bf162* __restrict__ wohi, bf162* __restrict__ wolo)
{
    int i = blockIdx.x * 256 + threadIdx.x;
    const float4* src; bf162 *hi, *lo;
    if      (i < N4BIG)                { src = q;  hi = qhi;  lo = qlo; }
    else if (i < 2*N4BIG)              { i -= N4BIG;   src = k;  hi = khi;  lo = klo; }
    else if (i < 2*N4BIG + N4W)        { i -= 2*N4BIG; src = wq; hi = wqhi; lo = wqlo; }
    else if (i < 2*N4BIG + 2*N4W)      { i -= 2*N4BIG + N4W;   src = wk; hi = wkhi; lo = wklo; }
    else if (i < 2*N4BIG + 3*N4W)      { i -= 2*N4BIG + 2*N4W; src = wo; hi = wohi; lo = wolo; }
    else return;
    float4 v = src[i];
    uint32_t h01, l01, h23, l23;
    split2(v.x, v.y, h01, l01);
    split2(v.z, v.w, h23, l23);
    hi[2*i]   = *(bf162*)&h01;  hi[2*i+1] = *(bf162*)&h23;
    lo[2*i]   = *(bf162*)&l01;  lo[2*i+1] = *(bf162*)&l23;
}

// ---------------------------------------------------------------------------
// HMMA GEMM core (round 10): C = A @ W^T, bf16-split fused.
// Tile 128x64, 8 warps (4x2), 3 CTAs/SM, single barrier per chunk.
// ---------------------------------------------------------------------------
#define SROWB 80
#define ATILEB (128 * SROWB)          // 10240
#define BTILEB (64 * SROWB)           // 5120
#define STAGEB (2*ATILEB + 2*BTILEB)  // 30720
#define GEMM_SMEM (2 * STAGEB)        // 61440
#define NCHUNK 32

template<int MODE>
__device__ __forceinline__ void gemm_body(const bf16* __restrict__ Ahi,
                                          const bf16* __restrict__ Alo,
                                          const bf16* __restrict__ Bhi,
                                          const bf16* __restrict__ Blo,
                                          float* __restrict__ Cf,
                                          bf16* __restrict__ Chi,
                                          bf16* __restrict__ Clo,
                                          float scale, int m0, int n0, char* smem)
{
    const int tid = threadIdx.x;
    const int wid = tid >> 5, lid = tid & 31;
    const int warp_m = wid & 3, warp_n = wid >> 2;      // 4 x 2
    const int gr = tid >> 2, gc = tid & 3;
    const uint32_t sb = smem_u32(smem);

    float acc[2][4][4];
    #pragma unroll
    for (int i = 0; i < 2; i++)
        #pragma unroll
        for (int j = 0; j < 4; j++)
            #pragma unroll
            for (int c = 0; c < 4; c++) acc[i][j][c] = 0.f;

    auto issue = [&](int kc) {
        const int st = kc & 1;
        const uint32_t base = sb + st * STAGEB;
        const size_t colB = (size_t)kc * 64;
        // A hi/lo: 128 rows x 64 B
        #pragma unroll
        for (int q = 0; q < 2; q++) {
            int r = gr + q * 64;
            cp16(base + r * SROWB + gc * 16,
                 (const char*)Ahi + (size_t)(m0 + r) * 2048 + colB + gc * 16);
            cp16(base + ATILEB + r * SROWB + gc * 16,
                 (const char*)Alo + (size_t)(m0 + r) * 2048 + colB + gc * 16);
        }
        // B hi/lo: 64 rows x 64 B
        {
            int r = gr;            // 0..127 but only 0..63 valid slots
            if (r < 64) {
                cp16(base + 2*ATILEB + r * SROWB + gc * 16,
                     (const char*)Bhi + (size_t)(n0 + r) * 2048 + colB + gc * 16);
                cp16(base + 2*ATILEB + BTILEB + r * SROWB + gc * 16,
                     (const char*)Blo + (size_t)(n0 + r) * 2048 + colB + gc * 16);
            }
        }
        CP_COMMIT();
    };

    issue(0);
    for (int i = 0; i < NCHUNK; i++) {
        CP_WAIT(0);
        __syncthreads();                 // data ready + prev readers done
        if (i + 1 < NCHUNK) issue(i + 1);

        const int st = i & 1;
        const uint32_t base = sb + st * STAGEB;
        const uint32_t bAhi = base;
        const uint32_t bAlo = base + ATILEB;
        const uint32_t bBhi = base + 2*ATILEB;
        const uint32_t bBlo = base + 2*ATILEB + BTILEB;
        const int lrow = lid & 15, lcol = (lid >> 4) * 16;

        #pragma unroll
        for (int s = 0; s < 2; s++) {
            uint32_t ah[2][4], al[2][4];
            #pragma unroll
            for (int mt = 0; mt < 2; mt++) {
                uint32_t off = (warp_m*32 + mt*16 + lrow) * SROWB + s*32 + lcol;
                ldm_x4(ah[mt][0], ah[mt][1], ah[mt][2], ah[mt][3], bAhi + off);
                ldm_x4(al[mt][0], al[mt][1], al[mt][2], al[mt][3], bAlo + off);
            }
            uint32_t bh[2][4];
            #pragma unroll
            for (int np = 0; np < 2; np++) {
                uint32_t off = (warp_n*32 + np*16 + lrow) * SROWB + s*32 + lcol;
                ldm_x4(bh[np][0], bh[np][1], bh[np][2], bh[np][3], bBhi + off);
            }
            // pass0: Ahi x Bhi (8 indep mma)
            #pragma unroll
            for (int np = 0; np < 2; np++)
                #pragma unroll
                for (int mt = 0; mt < 2; mt++) {
                    mma16816(acc[mt][np*2][0],acc[mt][np*2][1],acc[mt][np*2][2],acc[mt][np*2][3],
                             ah[mt][0],ah[mt][1],ah[mt][2],ah[mt][3], bh[np][0], bh[np][2]);
                    mma16816(acc[mt][np*2+1][0],acc[mt][np*2+1][1],acc[mt][np*2+1][2],acc[mt][np*2+1][3],
                             ah[mt][0],ah[mt][1],ah[mt][2],ah[mt][3], bh[np][1], bh[np][3]);
                }
            // pass2: Alo x Bhi (reuse bh)
            #pragma unroll
            for (int np = 0; np < 2; np++)
                #pragma unroll
                for (int mt = 0; mt < 2; mt++) {
                    mma16816(acc[mt][np*2][0],acc[mt][np*2][1],acc[mt][np*2][2],acc[mt][np*2][3],
                             al[mt][0],al[mt][1],al[mt][2],al[mt][3], bh[np][0], bh[np][2]);
                    mma16816(acc[mt][np*2+1][0],acc[mt][np*2+1][1],acc[mt][np*2+1][2],acc[mt][np*2+1][3],
                             al[mt][0],al[mt][1],al[mt][2],al[mt][3], bh[np][1], bh[np][3]);
                }
            // pass1: Ahi x Blo
            #pragma unroll
            for (int np = 0; np < 2; np++) {
                uint32_t off = (warp_n*32 + np*16 + lrow) * SROWB + s*32 + lcol;
                uint32_t l0,l1,l2,l3;
                ldm_x4(l0,l1,l2,l3, bBlo + off);
                #pragma unroll
                for (int mt = 0; mt < 2; mt++) {
                    mma16816(acc[mt][np*2][0],acc[mt][np*2][1],acc[mt][np*2][2],acc[mt][np*2][3],
                             ah[mt][0],ah[mt][1],ah[mt][2],ah[mt][3], l0, l2);
                    mma16816(acc[mt][np*2+1][0],acc[mt][np*2+1][1],acc[mt][np*2+1][2],acc[mt][np*2+1][3],
                             ah[mt][0],ah[mt][1],ah[mt][2],ah[mt][3], l1, l3);
                }
            }
        }
    }

    const int gid = lid >> 2, tig = lid & 3;
    #pragma unroll
    for (int mt = 0; mt < 2; mt++) {
        #pragma unroll
        for (int nt = 0; nt < 4; nt++) {
            int m = m0 + warp_m*32 + mt*16 + gid;
            int n = n0 + warp_n*32 + nt*8 + tig*2;
            #pragma unroll
            for (int half = 0; half < 2; half++) {
                int mm = m + half * 8;
                float x0 = acc[mt][nt][half*2+0], x1 = acc[mt][nt][half*2+1];
                if (MODE == 0) {
                    *(float2*)(Cf + (size_t)mm * E_ + n) = make_float2(x0, x1);
                } else {
                    x0 *= scale; x1 *= scale;
                    uint32_t hv, lv;
                    split2(x0, x1, hv, lv);
                    int b = mm >> 11, t = mm & (T_ - 1);
                    int h = n >> 6,  d = n & 63;
                    size_t idx = (((size_t)b * H_ + h) * T_ + t) * D_ + d;
                    *(bf162*)(Chi + idx) = *(bf162*)&hv;
                    *(bf162*)(Clo + idx) = *(bf162*)&lv;
                }
            }
        }
    }
}

__global__ __launch_bounds__(256, 3) void gemm_proj(
    const bf16* __restrict__ qAhi, const bf16* __restrict__ qAlo,
    const bf16* __restrict__ kAhi, const bf16* __restrict__ kAlo,
    const bf16* __restrict__ WqHi, const bf16* __restrict__ WqLo,
    const bf16* __restrict__ WkHi, const bf16* __restrict__ WkLo,
    bf16* __restrict__ qChi, bf16* __restrict__ qClo,
    bf16* __restrict__ kChi, bf16* __restrict__ kClo)
{
    extern __shared__ __align__(16) char smem[];
    const int y = blockIdx.y;
    const int n0 = blockIdx.x * 64;
    if (y < 64) {
        gemm_body<1>(qAhi, qAlo, WqHi, WqLo, nullptr, qChi, qClo,
                     0.125f, y * 128, n0, smem);
    } else {
        gemm_body<1>(kAhi, kAlo, WkHi, WkLo, nullptr, kChi, kClo,
                     1.0f, (y - 64) * 128, n0, smem);
    }
}

__global__ __launch_bounds__(256, 3) void gemm_out(
    const bf16* __restrict__ Ahi, const bf16* __restrict__ Alo,
    const bf16* __restrict__ Bhi, const bf16* __restrict__ Blo,
    float* __restrict__ Cf)
{
    extern __shared__ __align__(16) char smem[];
    gemm_body<0>(Ahi, Alo, Bhi, Blo, Cf, nullptr, nullptr,
                 1.0f, blockIdx.y * 128, blockIdx.x * 64, smem);
}

// ---------------------------------------------------------------------------
// Causal flash attention (round 9 proven: register-P, pass-major PV).
// ---------------------------------------------------------------------------
#define QSTRB 144
#define KSTG  (128*QSTRB)
#define SM_KHI(st) ((st)*2*KSTG)
#define SM_KLO(st) ((st)*2*KSTG + KSTG)
#define ATTN_SMEM (4*KSTG)

__global__ __launch_bounds__(256) void attn_mma(const bf16* __restrict__ qhh,
                                                const bf16* __restrict__ qhl,
                                                const bf16* __restrict__ khh,
                                                const bf16* __restrict__ khl,
                                                bf16* __restrict__ aohi,
                                                bf16* __restrict__ aolo)
{
    extern __shared__ __align__(16) char smem[];
    const uint32_t sb = smem_u32(smem);
    const int tid = threadIdx.x;
    const int wid = tid >> 5, lid = tid & 31;
    const int wrow = wid * 16;
    const int gid = lid >> 2, tig = lid & 3;
    const int lrow = lid & 15, lcol = (lid >> 4) * 16;
    const int qt = 15 - (int)blockIdx.x;
    const int bh = blockIdx.y;

    const char* Khi = (const char*)(khh + (size_t)bh * T_ * D_);
    const char* Klo = (const char*)(khl + (size_t)bh * T_ * D_);

    auto issueK = [&](int kt, int st) {
        #pragma unroll
        for (int i = 0; i < 4; i++) {
            int idx = tid + i * 256;
            int r = idx >> 3, c = (idx & 7) * 16;
            cp16(sb + SM_KHI(st) + r * QSTRB + c, Khi + ((size_t)kt * 128 + r) * 128 + c);
            cp16(sb + SM_KLO(st) + r * QSTRB + c, Klo + ((size_t)kt * 128 + r) * 128 + c);
        }
        CP_COMMIT();
    };

    issueK(0, 0);

    uint32_t qh[4][4], ql[4][4];
    {
        const bf16* Qgh = qhh + (size_t)bh * T_ * D_ + (size_t)(qt * 128 + wrow) * D_;
        const bf16* Qgl = qhl + (size_t)bh * T_ * D_ + (size_t)(qt * 128 + wrow) * D_;
        #pragma unroll
        for (int ks = 0; ks < 4; ks++) {
            int c0 = ks * 16 + tig * 2;
            qh[ks][0] = *(const uint32_t*)(Qgh + (size_t)gid * D_ + c0);
            qh[ks][1] = *(const uint32_t*)(Qgh + (size_t)(gid + 8) * D_ + c0);
            qh[ks][2] = *(const uint32_t*)(Qgh + (size_t)gid * D_ + c0 + 8);
            qh[ks][3] = *(const uint32_t*)(Qgh + (size_t)(gid + 8) * D_ + c0 + 8);
            ql[ks][0] = *(const uint32_t*)(Qgl + (size_t)gid * D_ + c0);
            ql[ks][1] = *(const uint32_t*)(Qgl + (size_t)(gid + 8) * D_ + c0);
            ql[ks][2] = *(const uint32_t*)(Qgl + (size_t)gid * D_ + c0 + 8);
            ql[ks][3] = *(const uint32_t*)(Qgl + (size_t)(gid + 8) * D_ + c0 + 8);
        }
    }

    float mrow[2] = {-1e30f, -1e30f};
    float lrow_[2] = {0.f, 0.f};
    float o[8][4];
    #pragma unroll
    for (int nt = 0; nt < 8; nt++)
        #pragma unroll
        for (int c = 0; c < 4; c++) o[nt][c] = 0.f;

    for (int kt = 0; kt <= qt; kt++) {
        const int st = kt & 1;
        if (kt < qt) { issueK(kt + 1, st ^ 1); CP_WAIT(1); }
        else         { CP_WAIT(0); }
        __syncthreads();

        float s[16][4];
        #pragma unroll
        for (int nt = 0; nt < 16; nt++)
            #pragma unroll
            for (int c = 0; c < 4; c++) s[nt][c] = 0.f;

        #pragma unroll
        for (int ks = 0; ks < 4; ks++) {
            uint32_t b[16][2];
            #pragma unroll
            for (int np = 0; np < 8; np++) {
                uint32_t r0,r1,r2,r3;
                ldm_x4(r0,r1,r2,r3, sb + SM_KHI(st) + (np*16 + lrow) * QSTRB + ks*32 + lcol);
                b[np*2][0] = r0;   b[np*2][1] = r2;
                b[np*2+1][0] = r1; b[np*2+1][1] = r3;
            }
            #pragma unroll
            for (int nt = 0; nt < 16; nt++)
                mma16816(s[nt][0], s[nt][1], s[nt][2], s[nt][3],
                         qh[ks][0], qh[ks][1], qh[ks][2], qh[ks][3], b[nt][0], b[nt][1]);
            #pragma unroll
            for (int nt = 0; nt < 16; nt++)
                mma16816(s[nt][0], s[nt][1], s[nt][2], s[nt][3],
                         ql[ks][0], ql[ks][1], ql[ks][2], ql[ks][3], b[nt][0], b[nt][1]);
            #pragma unroll
            for (int np = 0; np < 8; np++) {
                uint32_t r0,r1,r2,r3;
                ldm_x4(r0,r1,r2,r3, sb + SM_KLO(st) + (np*16 + lrow) * QSTRB + ks*32 + lcol);
                b[np*2][0] = r0;   b[np*2][1] = r2;
                b[np*2+1][0] = r1; b[np*2+1][1] = r3;
            }
            #pragma unroll
            for (int nt = 0; nt < 16; nt++)
                mma16816(s[nt][0], s[nt][1], s[nt][2], s[nt][3],
                         qh[ks][0], qh[ks][1], qh[ks][2], qh[ks][3], b[nt][0], b[nt][1]);
        }

        if (kt == qt) {
            #pragma unroll
            for (int nt = 0; nt < 16; nt++)
                #pragma unroll
                for (int c = 0; c < 4; c++) {
                    int row = wrow + gid + (c >> 1) * 8;
                    int col = nt*8 + tig*2 + (c & 1);
                    if (col > row) s[nt][c] = -1e30f;
                }
        }

        #pragma unroll
        for (int r = 0; r < 2; r++) {
            float mx = -1e30f;
            #pragma unroll
            for (int nt = 0; nt < 16; nt++)
                mx = fmaxf(mx, fmaxf(s[nt][r*2], s[nt][r*2+1]));
            mx = fmaxf(mx, __shfl_xor_sync(0xffffffffu, mx, 1));
            mx = fmaxf(mx, __shfl_xor_sync(0xffffffffu, mx, 2));
            float mnew = fmaxf(mrow[r], mx);
            float psum = 0.f;
            #pragma unroll
            for (int nt = 0; nt < 16; nt++) {
                float p0 = __expf(s[nt][r*2]   - mnew);
                float p1 = __expf(s[nt][r*2+1] - mnew);
                s[nt][r*2] = p0; s[nt][r*2+1] = p1;
                psum += p0 + p1;
            }
            psum += __shfl_xor_sync(0xffffffffu, psum, 1);
            psum += __shfl_xor_sync(0xffffffffu, psum, 2);
            float corr = __expf(mrow[r] - mnew);
            lrow_[r] = lrow_[r] * corr + psum;
            mrow[r] = mnew;
            #pragma unroll
            for (int nt = 0; nt < 8; nt++) {
                o[nt][r*2]   *= corr;
                o[nt][r*2+1] *= corr;
            }
        }

        #pragma unroll
        for (int ks = 0; ks < 8; ks++) {
            uint32_t pa0,pa1,pa2,pa3, pb0,pb1,pb2,pb3;
            split2(s[2*ks][0],   s[2*ks][1],   pa0, pb0);
            split2(s[2*ks][2],   s[2*ks][3],   pa1, pb1);
            split2(s[2*ks+1][0], s[2*ks+1][1], pa2, pb2);
            split2(s[2*ks+1][2], s[2*ks+1][3], pa3, pb3);
            uint32_t v[4][4];
            #pragma unroll
            for (int nb = 0; nb < 4; nb++)
                ldm_x4t(v[nb][0], v[nb][1], v[nb][2], v[nb][3],
                        sb + SM_KHI(st) + (ks*16 + lrow) * QSTRB + nb*32 + lcol);
            #pragma unroll
            for (int nb = 0; nb < 4; nb++) {
                mma16816(o[nb*2][0],   o[nb*2][1],   o[nb*2][2],   o[nb*2][3],
                         pa0,pa1,pa2,pa3, v[nb][0], v[nb][1]);
                mma16816(o[nb*2+1][0], o[nb*2+1][1], o[nb*2+1][2], o[nb*2+1][3],
                         pa0,pa1,pa2,pa3, v[nb][2], v[nb][3]);
            }
            #pragma unroll
            for (int nb = 0; nb < 4; nb++) {
                mma16816(o[nb*2][0],   o[nb*2][1],   o[nb*2][2],   o[nb*2][3],
                         pb0,pb1,pb2,pb3, v[nb][0], v[nb][1]);
                mma16816(o[nb*2+1][0], o[nb*2+1][1], o[nb*2+1][2], o[nb*2+1][3],
                         pb0,pb1,pb2,pb3, v[nb][2], v[nb][3]);
            }
            #pragma unroll
            for (int nb = 0; nb < 4; nb++)
                ldm_x4t(v[nb][0], v[nb][1], v[nb][2], v[nb][3],
                        sb + SM_KLO(st) + (ks*16 + lrow) * QSTRB + nb*32 + lcol);
            #pragma unroll
            for (int nb = 0; nb < 4; nb++) {
                mma16816(o[nb*2][0],   o[nb*2][1],   o[nb*2][2],   o[nb*2][3],
                         pa0,pa1,pa2,pa3, v[nb][0], v[nb][1]);
                mma16816(o[nb*2+1][0], o[nb*2+1][1], o[nb*2+1][2], o[nb*2+1][3],
                         pa0,pa1,pa2,pa3, v[nb][2], v[nb][3]);
            }
        }
        __syncthreads();
    }

    const int b = bh >> 4, h = bh & 15;
    #pragma unroll
    for (int r = 0; r < 2; r++) {
        float inv = 1.0f / lrow_[r];
        int t = qt*128 + wrow + gid + r*8;
        #pragma unroll
        for (int nt = 0; nt < 8; nt++) {
            float x0 = o[nt][r*2] * inv, x1 = o[nt][r*2+1] * inv;
            uint32_t hv, lv;
            split2(x0, x1, hv, lv);
            size_t idx = ((size_t)b * T_ + t) * E_ + h*64 + nt*8 + tig*2;
            *(bf162*)(aohi + idx) = *(bf162*)&hv;
            *(bf162*)(aolo + idx) = *(bf162*)&lv;
        }
    }
}

// ---------------------------------------------------------------------------
extern "C" void kernel_launch(void* const* d_in, const int* in_sizes, int n_in,
                              void* d_out, int out_size)
{
    const float* q  = (const float*)d_in[0];
    const float* k  = (const float*)d_in[1];
    // d_in[2] (v) dead: share_kv
    const float* Wq = (const float*)d_in[3];
    const float* Wk = (const float*)d_in[4];
    const float* Wo = (const float*)d_in[5];
    float* out = (float*)d_out;

    bf16 *pqhi,*pqlo,*pkhi,*pklo,*pwqhi,*pwqlo,*pwkhi,*pwklo,*pwohi,*pwolo;
    bf16 *pqhh,*pqhl,*pkhh,*pkhl,*paohi,*paolo;
    cudaGetSymbolAddress((void**)&pqhi, g_qhi);   cudaGetSymbolAddress((void**)&pqlo, g_qlo);
    cudaGetSymbolAddress((void**)&pkhi, g_khi);   cudaGetSymbolAddress((void**)&pklo, g_klo);
    cudaGetSymbolAddress((void**)&pwqhi, g_wqhi); cudaGetSymbolAddress((void**)&pwqlo, g_wqlo);
    cudaGetSymbolAddress((void**)&pwkhi, g_wkhi); cudaGetSymbolAddress((void**)&pwklo, g_wklo);
    cudaGetSymbolAddress((void**)&pwohi, g_wohi); cudaGetSymbolAddress((void**)&pwolo, g_wolo);
    cudaGetSymbolAddress((void**)&pqhh, g_qhh);   cudaGetSymbolAddress((void**)&pqhl, g_qhl);
    cudaGetSymbolAddress((void**)&pkhh, g_khh);   cudaGetSymbolAddress((void**)&pkhl, g_khl);
    cudaGetSymbolAddress((void**)&paohi, g_aohi); cudaGetSymbolAddress((void**)&paolo, g_aolo);

    static bool attr_done = false;
    if (!attr_done) {
        cudaFuncSetAttribute(attn_mma, cudaFuncAttributeMaxDynamicSharedMemorySize, ATTN_SMEM);
        cudaFuncSetAttribute(gemm_proj, cudaFuncAttributeMaxDynamicSharedMemorySize, GEMM_SMEM);
        cudaFuncSetAttribute(gemm_out, cudaFuncAttributeMaxDynamicSharedMemorySize, GEMM_SMEM);
        attr_done = true;
    }

    const int total4 = 2*N4BIG + 3*N4W;
    split_all<<<(total4 + 255)/256, 256>>>(
        (const float4*)q, (const float4*)k,
        (const float4*)Wq, (const float4*)Wk, (const float4*)Wo,
        (bf162*)pqhi, (bf162*)pqlo, (bf162*)pkhi, (bf162*)pklo,
        (bf162*)pwqhi, (bf162*)pwqlo, (bf162*)pwkhi, (bf162*)pwklo,
        (bf162*)pwohi, (bf162*)pwolo);

    gemm_proj<<<dim3(16, 128), 256, GEMM_SMEM>>>(pqhi, pqlo, pkhi, pklo,
                                                 pwqhi, pwqlo, pwkhi, pwklo,
                                                 pqhh, pqhl, pkhh, pkhl);

    attn_mma<<<dim3(16, B_*H_), 256, ATTN_SMEM>>>(pqhh, pqhl, pkhh, pkhl, paohi, paolo);

    gemm_out<<<dim3(16, 64), 256, GEMM_SMEM>>>(paohi, paolo, pwohi, pwolo, out);
}

// round 11
// speedup vs baseline: 4.8198x; 1.5982x over previous
#include <cuda_runtime.h>
#include <cuda_fp16.h>
#include <math.h>
#include <stdint.h>

#define B_ 4
#define T_ 2048
#define E_ 1024
#define H_ 16
#define D_ 64
#define M_TOT (B_*T_)   // 8192

// ---------------- scratch (allocation-free) ----------------
__device__ __align__(16) __half g_qh[M_TOT*E_];                    // input q hi (fp16)
__device__ __align__(16) __half g_kh[M_TOT*E_];                    // input k hi
__device__ __align__(16) __half g_wqh[E_*E_], g_wql[E_*E_];
__device__ __align__(16) __half g_wkh[E_*E_], g_wkl[E_*E_];
__device__ __align__(16) __half g_woh[E_*E_], g_wol[E_*E_];
__device__ __align__(16) __half g_qhh[M_TOT*E_];                   // Q head hi (scaled 1/8)
__device__ __align__(16) __half g_khh[M_TOT*E_], g_khl[M_TOT*E_];  // K head hi/lo
__device__ __align__(16) __half g_aoh[M_TOT*E_];                   // attn out hi

// ---------------- helpers ----------------
__device__ __forceinline__ uint32_t smem_u32(const void* p) {
    uint32_t a;
    asm("{ .reg .u64 t; cvta.to.shared.u64 t, %1; cvt.u32.u64 %0, t; }" : "=r"(a) : "l"(p));
    return a;
}
__device__ __forceinline__ void cp16(uint32_t saddr, const void* gaddr) {
    asm volatile("cp.async.cg.shared.global [%0], [%1], 16;" :: "r"(saddr), "l"(gaddr));
}
#define CP_COMMIT() asm volatile("cp.async.commit_group;" ::: "memory")
#define CP_WAIT(n)  asm volatile("cp.async.wait_group %0;" :: "n"(n) : "memory")

__device__ __forceinline__ void ldm_x4(uint32_t& r0, uint32_t& r1, uint32_t& r2, uint32_t& r3,
                                       uint32_t addr) {
    asm volatile("ldmatrix.sync.aligned.m8n8.x4.shared.b16 {%0,%1,%2,%3}, [%4];"
                 : "=r"(r0), "=r"(r1), "=r"(r2), "=r"(r3) : "r"(addr));
}
__device__ __forceinline__ void ldm_x4t(uint32_t& r0, uint32_t& r1, uint32_t& r2, uint32_t& r3,
                                        uint32_t addr) {
    asm volatile("ldmatrix.sync.aligned.m8n8.x4.trans.shared.b16 {%0,%1,%2,%3}, [%4];"
                 : "=r"(r0), "=r"(r1), "=r"(r2), "=r"(r3) : "r"(addr));
}
__device__ __forceinline__ void mma16816(float& d0, float& d1, float& d2, float& d3,
                                         uint32_t a0, uint32_t a1, uint32_t a2, uint32_t a3,
                                         uint32_t b0, uint32_t b1) {
    asm volatile("mma.sync.aligned.m16n8k16.row.col.f32.f16.f16.f32 "
                 "{%0,%1,%2,%3}, {%4,%5,%6,%7}, {%8,%9}, {%0,%1,%2,%3};"
                 : "+f"(d0), "+f"(d1), "+f"(d2), "+f"(d3)
                 : "r"(a0), "r"(a1), "r"(a2), "r"(a3), "r"(b0), "r"(b1));
}
__device__ __forceinline__ uint32_t pkh2(float a, float b) {
    __half2 h = __floats2half2_rn(a, b);
    return *(uint32_t*)&h;
}
__device__ __forceinline__ void split2h(float x0, float x1, uint32_t& hi, uint32_t& lo) {
    __half h0 = __float2half_rn(x0), h1 = __float2half_rn(x1);
    __half2 hv = __halves2half2(h0, h1);
    __half2 lv = __halves2half2(__float2half_rn(x0 - __half2float(h0)),
                                __float2half_rn(x1 - __half2float(h1)));
    hi = *(uint32_t*)&hv;
    lo = *(uint32_t*)&lv;
}

// ---------------- fused fp32 -> fp16 split (q,k: hi only; weights: hi+lo) ----
#define N4BIG (M_TOT*E_/4)
#define N4W   (E_*E_/4)
__global__ __launch_bounds__(256) void split_all(
    const float4* __restrict__ q, const float4* __restrict__ k,
    const float4* __restrict__ wq, const float4* __restrict__ wk,
    const float4* __restrict__ wo,
    __half2* __restrict__ qh, __half2* __restrict__ kh,
    __half2* __restrict__ wqh, __half2* __restrict__ wql,
    __half2* __restrict__ wkh, __half2* __restrict__ wkl,
    __half2* __restrict__ woh, __half2* __restrict__ wol)
{
    int i = blockIdx.x * 256 + threadIdx.x;
    const float4* src; __half2 *hi, *lo = nullptr;
    if      (i < N4BIG)                { src = q;  hi = qh; }
    else if (i < 2*N4BIG)              { i -= N4BIG;          src = k;  hi = kh; }
    else if (i < 2*N4BIG + N4W)        { i -= 2*N4BIG;        src = wq; hi = wqh; lo = wql; }
    else if (i < 2*N4BIG + 2*N4W)      { i -= 2*N4BIG + N4W;  src = wk; hi = wkh; lo = wkl; }
    else if (i < 2*N4BIG + 3*N4W)      { i -= 2*N4BIG + 2*N4W; src = wo; hi = woh; lo = wol; }
    else return;
    float4 v = src[i];
    uint32_t h01, l01, h23, l23;
    split2h(v.x, v.y, h01, l01);
    split2h(v.z, v.w, h23, l23);
    hi[2*i]   = *(__half2*)&h01;  hi[2*i+1] = *(__half2*)&h23;
    if (lo) {
        lo[2*i]   = *(__half2*)&l01;  lo[2*i+1] = *(__half2*)&l23;
    }
}

// ---------------------------------------------------------------------------
// HMMA GEMM core: C = A_hi @ (W_hi + W_lo)^T, 2-pass fp16.
// Tile 128x64, 8 warps (4x2), 3 CTAs/SM.
// MODE 0: fp32 flat. MODE 1: hi-only head-split (Q). MODE 2: hi+lo head-split (K).
// ---------------------------------------------------------------------------
#define SROWB 80
#define ATILEB (128 * SROWB)          // 10240
#define BTILEB (64 * SROWB)           // 5120
#define STAGEB (ATILEB + 2*BTILEB)    // 20480
#define GEMM_SMEM (2 * STAGEB)        // 40960
#define NCHUNK 32

template<int MODE>
__device__ __forceinline__ void gemm_body(const __half* __restrict__ A,
                                          const __half* __restrict__ Bhi,
                                          const __half* __restrict__ Blo,
                                          float* __restrict__ Cf,
                                          __half* __restrict__ Chi,
                                          __half* __restrict__ Clo,
                                          float scale, int m0, int n0, char* smem)
{
    const int tid = threadIdx.x;
    const int wid = tid >> 5, lid = tid & 31;
    const int warp_m = wid & 3, warp_n = wid >> 2;      // 4 x 2
    const int gr = tid >> 2, gc = tid & 3;              // gr 0..63
    const uint32_t sb = smem_u32(smem);

    float acc[2][4][4];
    #pragma unroll
    for (int i = 0; i < 2; i++)
        #pragma unroll
        for (int j = 0; j < 4; j++)
            #pragma unroll
            for (int c = 0; c < 4; c++) acc[i][j][c] = 0.f;

    auto issue = [&](int kc) {
        const int st = kc & 1;
        const uint32_t base = sb + st * STAGEB;
        const size_t colB = (size_t)kc * 64;
        #pragma unroll
        for (int q = 0; q < 2; q++) {
            int r = gr + q * 64;
            cp16(base + r * SROWB + gc * 16,
                 (const char*)A + (size_t)(m0 + r) * 2048 + colB + gc * 16);
        }
        cp16(base + ATILEB + gr * SROWB + gc * 16,
             (const char*)Bhi + (size_t)(n0 + gr) * 2048 + colB + gc * 16);
        cp16(base + ATILEB + BTILEB + gr * SROWB + gc * 16,
             (const char*)Blo + (size_t)(n0 + gr) * 2048 + colB + gc * 16);
        CP_COMMIT();
    };

    issue(0);
    for (int i = 0; i < NCHUNK; i++) {
        CP_WAIT(0);
        __syncthreads();
        if (i + 1 < NCHUNK) issue(i + 1);

        const int st = i & 1;
        const uint32_t base = sb + st * STAGEB;
        const uint32_t bA   = base;
        const uint32_t bBhi = base + ATILEB;
        const uint32_t bBlo = base + ATILEB + BTILEB;
        const int lrow = lid & 15, lcol = (lid >> 4) * 16;

        #pragma unroll
        for (int s = 0; s < 2; s++) {
            uint32_t ah[2][4];
            #pragma unroll
            for (int mt = 0; mt < 2; mt++) {
                uint32_t off = (warp_m*32 + mt*16 + lrow) * SROWB + s*32 + lcol;
                ldm_x4(ah[mt][0], ah[mt][1], ah[mt][2], ah[mt][3], bA + off);
            }
            // pass0: A_hi x B_hi
            #pragma unroll
            for (int np = 0; np < 2; np++) {
                uint32_t off = (warp_n*32 + np*16 + lrow) * SROWB + s*32 + lcol;
                uint32_t h0,h1,h2,h3;
                ldm_x4(h0,h1,h2,h3, bBhi + off);
                #pragma unroll
                for (int mt = 0; mt < 2; mt++) {
                    mma16816(acc[mt][np*2][0],acc[mt][np*2][1],acc[mt][np*2][2],acc[mt][np*2][3],
                             ah[mt][0],ah[mt][1],ah[mt][2],ah[mt][3], h0, h2);
                    mma16816(acc[mt][np*2+1][0],acc[mt][np*2+1][1],acc[mt][np*2+1][2],acc[mt][np*2+1][3],
                             ah[mt][0],ah[mt][1],ah[mt][2],ah[mt][3], h1, h3);
                }
            }
            // pass1: A_hi x B_lo
            #pragma unroll
            for (int np = 0; np < 2; np++) {
                uint32_t off = (warp_n*32 + np*16 + lrow) * SROWB + s*32 + lcol;
                uint32_t l0,l1,l2,l3;
                ldm_x4(l0,l1,l2,l3, bBlo + off);
                #pragma unroll
                for (int mt = 0; mt < 2; mt++) {
                    mma16816(acc[mt][np*2][0],acc[mt][np*2][1],acc[mt][np*2][2],acc[mt][np*2][3],
                             ah[mt][0],ah[mt][1],ah[mt][2],ah[mt][3], l0, l2);
                    mma16816(acc[mt][np*2+1][0],acc[mt][np*2+1][1],acc[mt][np*2+1][2],acc[mt][np*2+1][3],
                             ah[mt][0],ah[mt][1],ah[mt][2],ah[mt][3], l1, l3);
                }
            }
        }
    }

    const int gid = lid >> 2, tig = lid & 3;
    #pragma unroll
    for (int mt = 0; mt < 2; mt++) {
        #pragma unroll
        for (int nt = 0; nt < 4; nt++) {
            int m = m0 + warp_m*32 + mt*16 + gid;
            int n = n0 + warp_n*32 + nt*8 + tig*2;
            #pragma unroll
            for (int half = 0; half < 2; half++) {
                int mm = m + half * 8;
                float x0 = acc[mt][nt][half*2+0], x1 = acc[mt][nt][half*2+1];
                if (MODE == 0) {
                    *(float2*)(Cf + (size_t)mm * E_ + n) = make_float2(x0, x1);
                } else {
                    x0 *= scale; x1 *= scale;
                    int b = mm >> 11, t = mm & (T_ - 1);
                    int h = n >> 6,  d = n & 63;
                    size_t idx = (((size_t)b * H_ + h) * T_ + t) * D_ + d;
                    if (MODE == 1) {
                        uint32_t hv = pkh2(x0, x1);
                        *(__half2*)(Chi + idx) = *(__half2*)&hv;
                    } else {
                        uint32_t hv, lv;
                        split2h(x0, x1, hv, lv);
                        *(__half2*)(Chi + idx) = *(__half2*)&hv;
                        *(__half2*)(Clo + idx) = *(__half2*)&lv;
                    }
                }
            }
        }
    }
}

__global__ __launch_bounds__(256, 3) void gemm_proj(
    const __half* __restrict__ qA, const __half* __restrict__ kA,
    const __half* __restrict__ WqHi, const __half* __restrict__ WqLo,
    const __half* __restrict__ WkHi, const __half* __restrict__ WkLo,
    __half* __restrict__ qChi,
    __half* __restrict__ kChi, __half* __restrict__ kClo)
{
    extern __shared__ __align__(16) char smem[];
    const int y = blockIdx.y;
    const int n0 = blockIdx.x * 64;
    if (y < 64) {
        gemm_body<1>(qA, WqHi, WqLo, nullptr, qChi, nullptr,
                     0.125f, y * 128, n0, smem);
    } else {
        gemm_body<2>(kA, WkHi, WkLo, nullptr, kChi, kClo,
                     1.0f, (y - 64) * 128, n0, smem);
    }
}

__global__ __launch_bounds__(256, 3) void gemm_out(
    const __half* __restrict__ A,
    const __half* __restrict__ Bhi, const __half* __restrict__ Blo,
    float* __restrict__ Cf)
{
    extern __shared__ __align__(16) char smem[];
    gemm_body<0>(A, Bhi, Blo, Cf, nullptr, nullptr,
                 1.0f, blockIdx.y * 128, blockIdx.x * 64, smem);
}

// ---------------------------------------------------------------------------
// Causal flash attention, V == K (share_kv), fp16 reduced-pass:
// S = Q_hi·(K_hi + K_lo)^T (2-pass), PV = P_hi·K_hi (1-pass). Register-P.
// ---------------------------------------------------------------------------
#define QSTRB 144
#define KSTG  (128*QSTRB)
#define SM_KHI(st) ((st)*2*KSTG)
#define SM_KLO(st) ((st)*2*KSTG + KSTG)
#define ATTN_SMEM (4*KSTG)            // 73728

__global__ __launch_bounds__(256) void attn_mma(const __half* __restrict__ qhh,
                                                const __half* __restrict__ khh,
                                                const __half* __restrict__ khl,
                                                __half* __restrict__ aoh)
{
    extern __shared__ __align__(16) char smem[];
    const uint32_t sb = smem_u32(smem);
    const int tid = threadIdx.x;
    const int wid = tid >> 5, lid = tid & 31;
    const int wrow = wid * 16;
    const int gid = lid >> 2, tig = lid & 3;
    const int lrow = lid & 15, lcol = (lid >> 4) * 16;
    const int qt = 15 - (int)blockIdx.x;
    const int bh = blockIdx.y;

    const char* Khi = (const char*)(khh + (size_t)bh * T_ * D_);
    const char* Klo = (const char*)(khl + (size_t)bh * T_ * D_);

    auto issueK = [&](int kt, int st) {
        #pragma unroll
        for (int i = 0; i < 4; i++) {
            int idx = tid + i * 256;
            int r = idx >> 3, c = (idx & 7) * 16;
            cp16(sb + SM_KHI(st) + r * QSTRB + c, Khi + ((size_t)kt * 128 + r) * 128 + c);
            cp16(sb + SM_KLO(st) + r * QSTRB + c, Klo + ((size_t)kt * 128 + r) * 128 + c);
        }
        CP_COMMIT();
    };

    issueK(0, 0);

    uint32_t qh[4][4];
    {
        const __half* Qg = qhh + (size_t)bh * T_ * D_ + (size_t)(qt * 128 + wrow) * D_;
        #pragma unroll
        for (int ks = 0; ks < 4; ks++) {
            int c0 = ks * 16 + tig * 2;
            qh[ks][0] = *(const uint32_t*)(Qg + (size_t)gid * D_ + c0);
            qh[ks][1] = *(const uint32_t*)(Qg + (size_t)(gid + 8) * D_ + c0);
            qh[ks][2] = *(const uint32_t*)(Qg + (size_t)gid * D_ + c0 + 8);
            qh[ks][3] = *(const uint32_t*)(Qg + (size_t)(gid + 8) * D_ + c0 + 8);
        }
    }

    float mrow[2] = {-1e30f, -1e30f};
    float lrow_[2] = {0.f, 0.f};
    float o[8][4];
    #pragma unroll
    for (int nt = 0; nt < 8; nt++)
        #pragma unroll
        for (int c = 0; c < 4; c++) o[nt][c] = 0.f;

    for (int kt = 0; kt <= qt; kt++) {
        const int st = kt & 1;
        if (kt < qt) { issueK(kt + 1, st ^ 1); CP_WAIT(1); }
        else         { CP_WAIT(0); }
        __syncthreads();

        // ---- S = Q_hi @ (K_hi + K_lo)^T ----
        float s[16][4];
        #pragma unroll
        for (int nt = 0; nt < 16; nt++)
            #pragma unroll
            for (int c = 0; c < 4; c++) s[nt][c] = 0.f;

        #pragma unroll
        for (int ks = 0; ks < 4; ks++) {
            uint32_t b[16][2];
            #pragma unroll
            for (int np = 0; np < 8; np++) {
                uint32_t r0,r1,r2,r3;
                ldm_x4(r0,r1,r2,r3, sb + SM_KHI(st) + (np*16 + lrow) * QSTRB + ks*32 + lcol);
                b[np*2][0] = r0;   b[np*2][1] = r2;
                b[np*2+1][0] = r1; b[np*2+1][1] = r3;
            }
            #pragma unroll
            for (int nt = 0; nt < 16; nt++)
                mma16816(s[nt][0], s[nt][1], s[nt][2], s[nt][3],
                         qh[ks][0], qh[ks][1], qh[ks][2], qh[ks][3], b[nt][0], b[nt][1]);
            #pragma unroll
            for (int np = 0; np < 8; np++) {
                uint32_t r0,r1,r2,r3;
                ldm_x4(r0,r1,r2,r3, sb + SM_KLO(st) + (np*16 + lrow) * QSTRB + ks*32 + lcol);
                b[np*2][0] = r0;   b[np*2][1] = r2;
                b[np*2+1][0] = r1; b[np*2+1][1] = r3;
            }
            #pragma unroll
            for (int nt = 0; nt < 16; nt++)
                mma16816(s[nt][0], s[nt][1], s[nt][2], s[nt][3],
                         qh[ks][0], qh[ks][1], qh[ks][2], qh[ks][3], b[nt][0], b[nt][1]);
        }

        if (kt == qt) {
            #pragma unroll
            for (int nt = 0; nt < 16; nt++)
                #pragma unroll
                for (int c = 0; c < 4; c++) {
                    int row = wrow + gid + (c >> 1) * 8;
                    int col = nt*8 + tig*2 + (c & 1);
                    if (col > row) s[nt][c] = -1e30f;
                }
        }

        // ---- online softmax ----
        #pragma unroll
        for (int r = 0; r < 2; r++) {
            float mx = -1e30f;
            #pragma unroll
            for (int nt = 0; nt < 16; nt++)
                mx = fmaxf(mx, fmaxf(s[nt][r*2], s[nt][r*2+1]));
            mx = fmaxf(mx, __shfl_xor_sync(0xffffffffu, mx, 1));
            mx = fmaxf(mx, __shfl_xor_sync(0xffffffffu, mx, 2));
            float mnew = fmaxf(mrow[r], mx);
            float psum = 0.f;
            #pragma unroll
            for (int nt = 0; nt < 16; nt++) {
                float p0 = __expf(s[nt][r*2]   - mnew);
                float p1 = __expf(s[nt][r*2+1] - mnew);
                s[nt][r*2] = p0; s[nt][r*2+1] = p1;
                psum += p0 + p1;
            }
            psum += __shfl_xor_sync(0xffffffffu, psum, 1);
            psum += __shfl_xor_sync(0xffffffffu, psum, 2);
            float corr = __expf(mrow[r] - mnew);
            lrow_[r] = lrow_[r] * corr + psum;
            mrow[r] = mnew;
            #pragma unroll
            for (int nt = 0; nt < 8; nt++) {
                o[nt][r*2]   *= corr;
                o[nt][r*2+1] *= corr;
            }
        }

        // ---- PV single pass: P_hi @ V_hi (V = K_hi) ----
        #pragma unroll
        for (int ks = 0; ks < 8; ks++) {
            uint32_t pa0 = pkh2(s[2*ks][0],   s[2*ks][1]);
            uint32_t pa1 = pkh2(s[2*ks][2],   s[2*ks][3]);
            uint32_t pa2 = pkh2(s[2*ks+1][0], s[2*ks+1][1]);
            uint32_t pa3 = pkh2(s[2*ks+1][2], s[2*ks+1][3]);
            uint32_t v[4][4];
            #pragma unroll
            for (int nb = 0; nb < 4; nb++)
                ldm_x4t(v[nb][0], v[nb][1], v[nb][2], v[nb][3],
                        sb + SM_KHI(st) + (ks*16 + lrow) * QSTRB + nb*32 + lcol);
            #pragma unroll
            for (int nb = 0; nb < 4; nb++) {
                mma16816(o[nb*2][0],   o[nb*2][1],   o[nb*2][2],   o[nb*2][3],
                         pa0,pa1,pa2,pa3, v[nb][0], v[nb][1]);
                mma16816(o[nb*2+1][0], o[nb*2+1][1], o[nb*2+1][2], o[nb*2+1][3],
                         pa0,pa1,pa2,pa3, v[nb][2], v[nb][3]);
            }
        }
        __syncthreads();
    }

    const int b = bh >> 4, h = bh & 15;
    #pragma unroll
    for (int r = 0; r < 2; r++) {
        float inv = 1.0f / lrow_[r];
        int t = qt*128 + wrow + gid + r*8;
        #pragma unroll
        for (int nt = 0; nt < 8; nt++) {
            uint32_t hv = pkh2(o[nt][r*2] * inv, o[nt][r*2+1] * inv);
            size_t idx = ((size_t)b * T_ + t) * E_ + h*64 + nt*8 + tig*2;
            *(__half2*)(aoh + idx) = *(__half2*)&hv;
        }
    }
}

// ---------------------------------------------------------------------------
extern "C" void kernel_launch(void* const* d_in, const int* in_sizes, int n_in,
                              void* d_out, int out_size)
{
    const float* q  = (const float*)d_in[0];
    const float* k  = (const float*)d_in[1];
    // d_in[2] (v) dead: share_kv
    const float* Wq = (const float*)d_in[3];
    const float* Wk = (const float*)d_in[4];
    const float* Wo = (const float*)d_in[5];
    float* out = (float*)d_out;

    __half *pqh,*pkh,*pwqh,*pwql,*pwkh,*pwkl,*pwoh,*pwol;
    __half *pqhh,*pkhh,*pkhl,*paoh;
    cudaGetSymbolAddress((void**)&pqh, g_qh);
    cudaGetSymbolAddress((void**)&pkh, g_kh);
    cudaGetSymbolAddress((void**)&pwqh, g_wqh); cudaGetSymbolAddress((void**)&pwql, g_wql);
    cudaGetSymbolAddress((void**)&pwkh, g_wkh); cudaGetSymbolAddress((void**)&pwkl, g_wkl);
    cudaGetSymbolAddress((void**)&pwoh, g_woh); cudaGetSymbolAddress((void**)&pwol, g_wol);
    cudaGetSymbolAddress((void**)&pqhh, g_qhh);
    cudaGetSymbolAddress((void**)&pkhh, g_khh); cudaGetSymbolAddress((void**)&pkhl, g_khl);
    cudaGetSymbolAddress((void**)&paoh, g_aoh);

    static bool attr_done = false;
    if (!attr_done) {
        cudaFuncSetAttribute(attn_mma, cudaFuncAttributeMaxDynamicSharedMemorySize, ATTN_SMEM);
        cudaFuncSetAttribute(gemm_proj, cudaFuncAttributeMaxDynamicSharedMemorySize, GEMM_SMEM);
        cudaFuncSetAttribute(gemm_out, cudaFuncAttributeMaxDynamicSharedMemorySize, GEMM_SMEM);
        attr_done = true;
    }

    const int total4 = 2*N4BIG + 3*N4W;
    split_all<<<(total4 + 255)/256, 256>>>(
        (const float4*)q, (const float4*)k,
        (const float4*)Wq, (const float4*)Wk, (const float4*)Wo,
        (__half2*)pqh, (__half2*)pkh,
        (__half2*)pwqh, (__half2*)pwql,
        (__half2*)pwkh, (__half2*)pwkl,
        (__half2*)pwoh, (__half2*)pwol);

    gemm_proj<<<dim3(16, 128), 256, GEMM_SMEM>>>(pqh, pkh,
                                                 pwqh, pwql, pwkh, pwkl,
                                                 pqhh, pkhh, pkhl);

    attn_mma<<<dim3(16, B_*H_), 256, ATTN_SMEM>>>(pqhh, pkhh, pkhl, paoh);

    gemm_out<<<dim3(16, 64), 256, GEMM_SMEM>>>(paoh, pwoh, pwol, out);
}

// round 12
// speedup vs baseline: 6.7466x; 1.3998x over previous
#include <cuda_runtime.h>
#include <cuda_fp16.h>
#include <math.h>
#include <stdint.h>

#define B_ 4
#define T_ 2048
#define E_ 1024
#define H_ 16
#define D_ 64
#define M_TOT (B_*T_)   // 8192

// ---------------- scratch (allocation-free) ----------------
__device__ __align__(16) __half g_qh[M_TOT*E_];    // input q (fp16)
__device__ __align__(16) __half g_kh[M_TOT*E_];    // input k
__device__ __align__(16) __half g_wqh[E_*E_];
__device__ __align__(16) __half g_wkh[E_*E_];
__device__ __align__(16) __half g_woh[E_*E_], g_wol[E_*E_];
__device__ __align__(16) __half g_qhh[M_TOT*E_];   // Q head [b,h,t,d] (scaled 1/8)
__device__ __align__(16) __half g_khh[M_TOT*E_];   // K head (V alias)
__device__ __align__(16) __half g_aoh[M_TOT*E_];   // attn out [b,t,(h d)]

// ---------------- helpers ----------------
__device__ __forceinline__ uint32_t smem_u32(const void* p) {
    uint32_t a;
    asm("{ .reg .u64 t; cvta.to.shared.u64 t, %1; cvt.u32.u64 %0, t; }" : "=r"(a) : "l"(p));
    return a;
}
__device__ __forceinline__ void cp16(uint32_t saddr, const void* gaddr) {
    asm volatile("cp.async.cg.shared.global [%0], [%1], 16;" :: "r"(saddr), "l"(gaddr));
}
#define CP_COMMIT() asm volatile("cp.async.commit_group;" ::: "memory")
#define CP_WAIT(n)  asm volatile("cp.async.wait_group %0;" :: "n"(n) : "memory")

__device__ __forceinline__ void ldm_x4(uint32_t& r0, uint32_t& r1, uint32_t& r2, uint32_t& r3,
                                       uint32_t addr) {
    asm volatile("ldmatrix.sync.aligned.m8n8.x4.shared.b16 {%0,%1,%2,%3}, [%4];"
                 : "=r"(r0), "=r"(r1), "=r"(r2), "=r"(r3) : "r"(addr));
}
__device__ __forceinline__ void ldm_x4t(uint32_t& r0, uint32_t& r1, uint32_t& r2, uint32_t& r3,
                                        uint32_t addr) {
    asm volatile("ldmatrix.sync.aligned.m8n8.x4.trans.shared.b16 {%0,%1,%2,%3}, [%4];"
                 : "=r"(r0), "=r"(r1), "=r"(r2), "=r"(r3) : "r"(addr));
}
__device__ __forceinline__ void mma16816(float& d0, float& d1, float& d2, float& d3,
                                         uint32_t a0, uint32_t a1, uint32_t a2, uint32_t a3,
                                         uint32_t b0, uint32_t b1) {
    asm volatile("mma.sync.aligned.m16n8k16.row.col.f32.f16.f16.f32 "
                 "{%0,%1,%2,%3}, {%4,%5,%6,%7}, {%8,%9}, {%0,%1,%2,%3};"
                 : "+f"(d0), "+f"(d1), "+f"(d2), "+f"(d3)
                 : "r"(a0), "r"(a1), "r"(a2), "r"(a3), "r"(b0), "r"(b1));
}
__device__ __forceinline__ uint32_t pkh2(float a, float b) {
    __half2 h = __floats2half2_rn(a, b);
    return *(uint32_t*)&h;
}
__device__ __forceinline__ void split2h(float x0, float x1, uint32_t& hi, uint32_t& lo) {
    __half h0 = __float2half_rn(x0), h1 = __float2half_rn(x1);
    __half2 hv = __halves2half2(h0, h1);
    __half2 lv = __halves2half2(__float2half_rn(x0 - __half2float(h0)),
                                __float2half_rn(x1 - __half2float(h1)));
    hi = *(uint32_t*)&hv;
    lo = *(uint32_t*)&lv;
}

// ---------------- fused fp32 -> fp16 convert/split ----------------
#define N4BIG (M_TOT*E_/4)
#define N4W   (E_*E_/4)
__global__ __launch_bounds__(256) void split_all(
    const float4* __restrict__ q, const float4* __restrict__ k,
    const float4* __restrict__ wq, const float4* __restrict__ wk,
    const float4* __restrict__ wo,
    __half2* __restrict__ qh, __half2* __restrict__ kh,
    __half2* __restrict__ wqh, __half2* __restrict__ wkh,
    __half2* __restrict__ woh, __half2* __restrict__ wol)
{
    int i = blockIdx.x * 256 + threadIdx.x;
    const float4* src; __half2 *hi, *lo = nullptr;
    if      (i < N4BIG)                { src = q;  hi = qh; }
    else if (i < 2*N4BIG)              { i -= N4BIG;          src = k;  hi = kh; }
    else if (i < 2*N4BIG + N4W)        { i -= 2*N4BIG;        src = wq; hi = wqh; }
    else if (i < 2*N4BIG + 2*N4W)      { i -= 2*N4BIG + N4W;  src = wk; hi = wkh; }
    else if (i < 2*N4BIG + 3*N4W)      { i -= 2*N4BIG + 2*N4W; src = wo; hi = woh; lo = wol; }
    else return;
    float4 v = src[i];
    uint32_t h01, l01, h23, l23;
    split2h(v.x, v.y, h01, l01);
    split2h(v.z, v.w, h23, l23);
    hi[2*i]   = *(__half2*)&h01;  hi[2*i+1] = *(__half2*)&h23;
    if (lo) {
        lo[2*i]   = *(__half2*)&l01;  lo[2*i+1] = *(__half2*)&l23;
    }
}

// ---------------------------------------------------------------------------
// HMMA GEMM core: C = A @ Bhi^T (+ A @ Blo^T if NPASS=2), fp16.
// Tile 128x64, K-chunk 64 (128B rows), NCHUNK 16, 8 warps, 3 CTAs/SM.
// MODE 0: fp32 flat out.  MODE 1: fp16 head-split out (scaled).
// ---------------------------------------------------------------------------
#define SROWB 144                     // 128 data + 16 pad
#define ATILEB (128 * SROWB)          // 18432
#define BTILEB (64 * SROWB)           // 9216
#define NCHUNK 16

template<int MODE, int NPASS>
__device__ __forceinline__ void gemm_body(const __half* __restrict__ A,
                                          const __half* __restrict__ Bhi,
                                          const __half* __restrict__ Blo,
                                          float* __restrict__ Cf,
                                          __half* __restrict__ Ch,
                                          float scale, int m0, int n0, char* smem)
{
    const int STAGEB_ = ATILEB + NPASS * BTILEB;
    const int tid = threadIdx.x;
    const int wid = tid >> 5, lid = tid & 31;
    const int warp_m = wid & 3, warp_n = wid >> 2;      // 4 x 2
    const uint32_t sb = smem_u32(smem);

    float acc[2][4][4];
    #pragma unroll
    for (int i = 0; i < 2; i++)
        #pragma unroll
        for (int j = 0; j < 4; j++)
            #pragma unroll
            for (int c = 0; c < 4; c++) acc[i][j][c] = 0.f;

    const int gr8 = tid >> 3, gc8 = (tid & 7) * 16;     // 32 rows per 256-thread pass

    auto issue = [&](int kc) {
        const int st = kc & 1;
        const uint32_t base = sb + st * STAGEB_;
        const size_t colB = (size_t)kc * 128;
        #pragma unroll
        for (int q = 0; q < 4; q++) {                   // A: 128 rows x 128B
            int r = gr8 + q * 32;
            cp16(base + r * SROWB + gc8,
                 (const char*)A + (size_t)(m0 + r) * 2048 + colB + gc8);
        }
        #pragma unroll
        for (int q = 0; q < 2; q++) {                   // Bhi: 64 rows x 128B
            int r = gr8 + q * 32;
            cp16(base + ATILEB + r * SROWB + gc8,
                 (const char*)Bhi + (size_t)(n0 + r) * 2048 + colB + gc8);
        }
        if (NPASS == 2) {
            #pragma unroll
            for (int q = 0; q < 2; q++) {
                int r = gr8 + q * 32;
                cp16(base + ATILEB + BTILEB + r * SROWB + gc8,
                     (const char*)Blo + (size_t)(n0 + r) * 2048 + colB + gc8);
            }
        }
        CP_COMMIT();
    };

    issue(0);
    for (int i = 0; i < NCHUNK; i++) {
        CP_WAIT(0);
        __syncthreads();
        if (i + 1 < NCHUNK) issue(i + 1);

        const int st = i & 1;
        const uint32_t base = sb + st * STAGEB_;
        const uint32_t bA   = base;
        const uint32_t bBhi = base + ATILEB;
        const uint32_t bBlo = base + ATILEB + BTILEB;
        const int lrow = lid & 15, lcol = (lid >> 4) * 16;

        #pragma unroll
        for (int s = 0; s < 4; s++) {                   // 4 k16-steps per chunk
            uint32_t ah[2][4];
            #pragma unroll
            for (int mt = 0; mt < 2; mt++) {
                uint32_t off = (warp_m*32 + mt*16 + lrow) * SROWB + s*32 + lcol;
                ldm_x4(ah[mt][0], ah[mt][1], ah[mt][2], ah[mt][3], bA + off);
            }
            #pragma unroll
            for (int np = 0; np < 2; np++) {
                uint32_t off = (warp_n*32 + np*16 + lrow) * SROWB + s*32 + lcol;
                uint32_t h0,h1,h2,h3;
                ldm_x4(h0,h1,h2,h3, bBhi + off);
                #pragma unroll
                for (int mt = 0; mt < 2; mt++) {
                    mma16816(acc[mt][np*2][0],acc[mt][np*2][1],acc[mt][np*2][2],acc[mt][np*2][3],
                             ah[mt][0],ah[mt][1],ah[mt][2],ah[mt][3], h0, h2);
                    mma16816(acc[mt][np*2+1][0],acc[mt][np*2+1][1],acc[mt][np*2+1][2],acc[mt][np*2+1][3],
                             ah[mt][0],ah[mt][1],ah[mt][2],ah[mt][3], h1, h3);
                }
            }
            if (NPASS == 2) {
                #pragma unroll
                for (int np = 0; np < 2; np++) {
                    uint32_t off = (warp_n*32 + np*16 + lrow) * SROWB + s*32 + lcol;
                    uint32_t l0,l1,l2,l3;
                    ldm_x4(l0,l1,l2,l3, bBlo + off);
                    #pragma unroll
                    for (int mt = 0; mt < 2; mt++) {
                        mma16816(acc[mt][np*2][0],acc[mt][np*2][1],acc[mt][np*2][2],acc[mt][np*2][3],
                                 ah[mt][0],ah[mt][1],ah[mt][2],ah[mt][3], l0, l2);
                        mma16816(acc[mt][np*2+1][0],acc[mt][np*2+1][1],acc[mt][np*2+1][2],acc[mt][np*2+1][3],
                                 ah[mt][0],ah[mt][1],ah[mt][2],ah[mt][3], l1, l3);
                    }
                }
            }
        }
    }

    const int gid = lid >> 2, tig = lid & 3;
    #pragma unroll
    for (int mt = 0; mt < 2; mt++) {
        #pragma unroll
        for (int nt = 0; nt < 4; nt++) {
            int m = m0 + warp_m*32 + mt*16 + gid;
            int n = n0 + warp_n*32 + nt*8 + tig*2;
            #pragma unroll
            for (int half = 0; half < 2; half++) {
                int mm = m + half * 8;
                float x0 = acc[mt][nt][half*2+0], x1 = acc[mt][nt][half*2+1];
                if (MODE == 0) {
                    *(float2*)(Cf + (size_t)mm * E_ + n) = make_float2(x0, x1);
                } else {
                    uint32_t hv = pkh2(x0 * scale, x1 * scale);
                    int b = mm >> 11, t = mm & (T_ - 1);
                    int h = n >> 6,  d = n & 63;
                    size_t idx = (((size_t)b * H_ + h) * T_ + t) * D_ + d;
                    *(__half2*)(Ch + idx) = *(__half2*)&hv;
                }
            }
        }
    }
}

#define GEMM_SMEM1 (2 * (ATILEB + BTILEB))       // 55296  (1-pass)
#define GEMM_SMEM2 (2 * (ATILEB + 2*BTILEB))     // 73728  (2-pass)

__global__ __launch_bounds__(256, 3) void gemm_proj(
    const __half* __restrict__ qA, const __half* __restrict__ kA,
    const __half* __restrict__ Wq, const __half* __restrict__ Wk,
    __half* __restrict__ qC, __half* __restrict__ kC)
{
    extern __shared__ __align__(16) char smem[];
    const int y = blockIdx.y;
    const int n0 = blockIdx.x * 64;
    if (y < 64) {
        gemm_body<1,1>(qA, Wq, nullptr, nullptr, qC, 0.125f, y * 128, n0, smem);
    } else {
        gemm_body<1,1>(kA, Wk, nullptr, nullptr, kC, 1.0f, (y - 64) * 128, n0, smem);
    }
}

__global__ __launch_bounds__(256, 3) void gemm_out(
    const __half* __restrict__ A,
    const __half* __restrict__ Bhi, const __half* __restrict__ Blo,
    float* __restrict__ Cf)
{
    extern __shared__ __align__(16) char smem[];
    gemm_body<0,2>(A, Bhi, Blo, Cf, nullptr, 1.0f, blockIdx.y * 128, blockIdx.x * 64, smem);
}

// ---------------------------------------------------------------------------
// Causal flash attention, V == K (share_kv), pure fp16:
// S = Q·K^T (1 pass), PV = P·K (1 pass). Register-P, K double-buffered.
// ---------------------------------------------------------------------------
#define QSTRB 144
#define KSTG  (128*QSTRB)             // 18432
#define SM_K(st) ((st)*KSTG)
#define ATTN_SMEM (2*KSTG)            // 36864

__global__ __launch_bounds__(256) void attn_mma(const __half* __restrict__ qhh,
                                                const __half* __restrict__ khh,
                                                __half* __restrict__ aoh)
{
    extern __shared__ __align__(16) char smem[];
    const uint32_t sb = smem_u32(smem);
    const int tid = threadIdx.x;
    const int wid = tid >> 5, lid = tid & 31;
    const int wrow = wid * 16;
    const int gid = lid >> 2, tig = lid & 3;
    const int lrow = lid & 15, lcol = (lid >> 4) * 16;
    const int qt = 15 - (int)blockIdx.x;
    const int bh = blockIdx.y;

    const char* Kg = (const char*)(khh + (size_t)bh * T_ * D_);

    auto issueK = [&](int kt, int st) {
        #pragma unroll
        for (int i = 0; i < 4; i++) {
            int idx = tid + i * 256;
            int r = idx >> 3, c = (idx & 7) * 16;
            cp16(sb + SM_K(st) + r * QSTRB + c, Kg + ((size_t)kt * 128 + r) * 128 + c);
        }
        CP_COMMIT();
    };

    issueK(0, 0);

    uint32_t qh[4][4];
    {
        const __half* Qg = qhh + (size_t)bh * T_ * D_ + (size_t)(qt * 128 + wrow) * D_;
        #pragma unroll
        for (int ks = 0; ks < 4; ks++) {
            int c0 = ks * 16 + tig * 2;
            qh[ks][0] = *(const uint32_t*)(Qg + (size_t)gid * D_ + c0);
            qh[ks][1] = *(const uint32_t*)(Qg + (size_t)(gid + 8) * D_ + c0);
            qh[ks][2] = *(const uint32_t*)(Qg + (size_t)gid * D_ + c0 + 8);
            qh[ks][3] = *(const uint32_t*)(Qg + (size_t)(gid + 8) * D_ + c0 + 8);
        }
    }

    float mrow[2] = {-1e30f, -1e30f};
    float lrow_[2] = {0.f, 0.f};
    float o[8][4];
    #pragma unroll
    for (int nt = 0; nt < 8; nt++)
        #pragma unroll
        for (int c = 0; c < 4; c++) o[nt][c] = 0.f;

    for (int kt = 0; kt <= qt; kt++) {
        const int st = kt & 1;
        if (kt < qt) { issueK(kt + 1, st ^ 1); CP_WAIT(1); }
        else         { CP_WAIT(0); }
        __syncthreads();

        // ---- S = Q @ K^T (single pass) ----
        float s[16][4];
        #pragma unroll
        for (int nt = 0; nt < 16; nt++)
            #pragma unroll
            for (int c = 0; c < 4; c++) s[nt][c] = 0.f;

        #pragma unroll
        for (int ks = 0; ks < 4; ks++) {
            uint32_t b[16][2];
            #pragma unroll
            for (int np = 0; np < 8; np++) {
                uint32_t r0,r1,r2,r3;
                ldm_x4(r0,r1,r2,r3, sb + SM_K(st) + (np*16 + lrow) * QSTRB + ks*32 + lcol);
                b[np*2][0] = r0;   b[np*2][1] = r2;
                b[np*2+1][0] = r1; b[np*2+1][1] = r3;
            }
            #pragma unroll
            for (int nt = 0; nt < 16; nt++)
                mma16816(s[nt][0], s[nt][1], s[nt][2], s[nt][3],
                         qh[ks][0], qh[ks][1], qh[ks][2], qh[ks][3], b[nt][0], b[nt][1]);
        }

        if (kt == qt) {
            #pragma unroll
            for (int nt = 0; nt < 16; nt++)
                #pragma unroll
                for (int c = 0; c < 4; c++) {
                    int row = wrow + gid + (c >> 1) * 8;
                    int col = nt*8 + tig*2 + (c & 1);
                    if (col > row) s[nt][c] = -1e30f;
                }
        }

        // ---- online softmax ----
        #pragma unroll
        for (int r = 0; r < 2; r++) {
            float mx = -1e30f;
            #pragma unroll
            for (int nt = 0; nt < 16; nt++)
                mx = fmaxf(mx, fmaxf(s[nt][r*2], s[nt][r*2+1]));
            mx = fmaxf(mx, __shfl_xor_sync(0xffffffffu, mx, 1));
            mx = fmaxf(mx, __shfl_xor_sync(0xffffffffu, mx, 2));
            float mnew = fmaxf(mrow[r], mx);
            float psum = 0.f;
            #pragma unroll
            for (int nt = 0; nt < 16; nt++) {
                float p0 = __expf(s[nt][r*2]   - mnew);
                float p1 = __expf(s[nt][r*2+1] - mnew);
                s[nt][r*2] = p0; s[nt][r*2+1] = p1;
                psum += p0 + p1;
            }
            psum += __shfl_xor_sync(0xffffffffu, psum, 1);
            psum += __shfl_xor_sync(0xffffffffu, psum, 2);
            float corr = __expf(mrow[r] - mnew);
            lrow_[r] = lrow_[r] * corr + psum;
            mrow[r] = mnew;
            #pragma unroll
            for (int nt = 0; nt < 8; nt++) {
                o[nt][r*2]   *= corr;
                o[nt][r*2+1] *= corr;
            }
        }

        // ---- PV single pass: P @ V (V = K tile) ----
        #pragma unroll
        for (int ks = 0; ks < 8; ks++) {
            uint32_t pa0 = pkh2(s[2*ks][0],   s[2*ks][1]);
            uint32_t pa1 = pkh2(s[2*ks][2],   s[2*ks][3]);
            uint32_t pa2 = pkh2(s[2*ks+1][0], s[2*ks+1][1]);
            uint32_t pa3 = pkh2(s[2*ks+1][2], s[2*ks+1][3]);
            uint32_t v[4][4];
            #pragma unroll
            for (int nb = 0; nb < 4; nb++)
                ldm_x4t(v[nb][0], v[nb][1], v[nb][2], v[nb][3],
                        sb + SM_K(st) + (ks*16 + lrow) * QSTRB + nb*32 + lcol);
            #pragma unroll
            for (int nb = 0; nb < 4; nb++) {
                mma16816(o[nb*2][0],   o[nb*2][1],   o[nb*2][2],   o[nb*2][3],
                         pa0,pa1,pa2,pa3, v[nb][0], v[nb][1]);
                mma16816(o[nb*2+1][0], o[nb*2+1][1], o[nb*2+1][2], o[nb*2+1][3],
                         pa0,pa1,pa2,pa3, v[nb][2], v[nb][3]);
            }
        }
        __syncthreads();
    }

    const int b = bh >> 4, h = bh & 15;
    #pragma unroll
    for (int r = 0; r < 2; r++) {
        float inv = 1.0f / lrow_[r];
        int t = qt*128 + wrow + gid + r*8;
        #pragma unroll
        for (int nt = 0; nt < 8; nt++) {
            uint32_t hv = pkh2(o[nt][r*2] * inv, o[nt][r*2+1] * inv);
            size_t idx = ((size_t)b * T_ + t) * E_ + h*64 + nt*8 + tig*2;
            *(__half2*)(aoh + idx) = *(__half2*)&hv;
        }
    }
}

// ---------------------------------------------------------------------------
extern "C" void kernel_launch(void* const* d_in, const int* in_sizes, int n_in,
                              void* d_out, int out_size)
{
    const float* q  = (const float*)d_in[0];
    const float* k  = (const float*)d_in[1];
    // d_in[2] (v) dead: share_kv
    const float* Wq = (const float*)d_in[3];
    const float* Wk = (const float*)d_in[4];
    const float* Wo = (const float*)d_in[5];
    float* out = (float*)d_out;

    __half *pqh,*pkh,*pwqh,*pwkh,*pwoh,*pwol,*pqhh,*pkhh,*paoh;
    cudaGetSymbolAddress((void**)&pqh, g_qh);
    cudaGetSymbolAddress((void**)&pkh, g_kh);
    cudaGetSymbolAddress((void**)&pwqh, g_wqh);
    cudaGetSymbolAddress((void**)&pwkh, g_wkh);
    cudaGetSymbolAddress((void**)&pwoh, g_woh); cudaGetSymbolAddress((void**)&pwol, g_wol);
    cudaGetSymbolAddress((void**)&pqhh, g_qhh);
    cudaGetSymbolAddress((void**)&pkhh, g_khh);
    cudaGetSymbolAddress((void**)&paoh, g_aoh);

    static bool attr_done = false;
    if (!attr_done) {
        cudaFuncSetAttribute(attn_mma, cudaFuncAttributeMaxDynamicSharedMemorySize, ATTN_SMEM);
        cudaFuncSetAttribute(gemm_proj, cudaFuncAttributeMaxDynamicSharedMemorySize, GEMM_SMEM1);
        cudaFuncSetAttribute(gemm_out, cudaFuncAttributeMaxDynamicSharedMemorySize, GEMM_SMEM2);
        attr_done = true;
    }

    const int total4 = 2*N4BIG + 3*N4W;
    split_all<<<(total4 + 255)/256, 256>>>(
        (const float4*)q, (const float4*)k,
        (const float4*)Wq, (const float4*)Wk, (const float4*)Wo,
        (__half2*)pqh, (__half2*)pkh,
        (__half2*)pwqh, (__half2*)pwkh,
        (__half2*)pwoh, (__half2*)pwol);

    gemm_proj<<<dim3(16, 128), 256, GEMM_SMEM1>>>(pqh, pkh, pwqh, pwkh, pqhh, pkhh);

    attn_mma<<<dim3(16, B_*H_), 256, ATTN_SMEM>>>(pqhh, pkhh, paoh);

    gemm_out<<<dim3(16, 64), 256, GEMM_SMEM2>>>(paoh, pwoh, pwol, out);
}

// round 13
// speedup vs baseline: 7.3181x; 1.0847x over previous
#include <cuda_runtime.h>
#include <cuda_fp16.h>
#include <math.h>
#include <stdint.h>

#define B_ 4
#define T_ 2048
#define E_ 1024
#define H_ 16
#define D_ 64
#define M_TOT (B_*T_)   // 8192

// ---------------- scratch (allocation-free) ----------------
__device__ __align__(16) __half g_qh[M_TOT*E_];    // input q (fp16)
__device__ __align__(16) __half g_kh[M_TOT*E_];    // input k
__device__ __align__(16) __half g_wqh[E_*E_];
__device__ __align__(16) __half g_wkh[E_*E_];
__device__ __align__(16) __half g_woh[E_*E_];
__device__ __align__(16) __half g_qhh[M_TOT*E_];   // Q head [b,h,t,d] (scaled 1/8)
__device__ __align__(16) __half g_khh[M_TOT*E_];   // K head (V alias)
__device__ __align__(16) __half g_aoh[M_TOT*E_];   // attn out [b,t,(h d)]

// ---------------- helpers ----------------
__device__ __forceinline__ uint32_t smem_u32(const void* p) {
    uint32_t a;
    asm("{ .reg .u64 t; cvta.to.shared.u64 t, %1; cvt.u32.u64 %0, t; }" : "=r"(a) : "l"(p));
    return a;
}
__device__ __forceinline__ void cp16(uint32_t saddr, const void* gaddr) {
    asm volatile("cp.async.cg.shared.global [%0], [%1], 16;" :: "r"(saddr), "l"(gaddr));
}
#define CP_COMMIT() asm volatile("cp.async.commit_group;" ::: "memory")
#define CP_WAIT(n)  asm volatile("cp.async.wait_group %0;" :: "n"(n) : "memory")

__device__ __forceinline__ void ldm_x4(uint32_t& r0, uint32_t& r1, uint32_t& r2, uint32_t& r3,
                                       uint32_t addr) {
    asm volatile("ldmatrix.sync.aligned.m8n8.x4.shared.b16 {%0,%1,%2,%3}, [%4];"
                 : "=r"(r0), "=r"(r1), "=r"(r2), "=r"(r3) : "r"(addr));
}
__device__ __forceinline__ void ldm_x4t(uint32_t& r0, uint32_t& r1, uint32_t& r2, uint32_t& r3,
                                        uint32_t addr) {
    asm volatile("ldmatrix.sync.aligned.m8n8.x4.trans.shared.b16 {%0,%1,%2,%3}, [%4];"
                 : "=r"(r0), "=r"(r1), "=r"(r2), "=r"(r3) : "r"(addr));
}
__device__ __forceinline__ void mma16816(float& d0, float& d1, float& d2, float& d3,
                                         uint32_t a0, uint32_t a1, uint32_t a2, uint32_t a3,
                                         uint32_t b0, uint32_t b1) {
    asm volatile("mma.sync.aligned.m16n8k16.row.col.f32.f16.f16.f32 "
                 "{%0,%1,%2,%3}, {%4,%5,%6,%7}, {%8,%9}, {%0,%1,%2,%3};"
                 : "+f"(d0), "+f"(d1), "+f"(d2), "+f"(d3)
                 : "r"(a0), "r"(a1), "r"(a2), "r"(a3), "r"(b0), "r"(b1));
}
__device__ __forceinline__ uint32_t pkh2(float a, float b) {
    __half2 h = __floats2half2_rn(a, b);
    return *(uint32_t*)&h;
}

// ---------------- fused fp32 -> fp16 convert ----------------
#define N4BIG (M_TOT*E_/4)
#define N4W   (E_*E_/4)
__global__ __launch_bounds__(256) void split_all(
    const float4* __restrict__ q, const float4* __restrict__ k,
    const float4* __restrict__ wq, const float4* __restrict__ wk,
    const float4* __restrict__ wo,
    __half2* __restrict__ qh, __half2* __restrict__ kh,
    __half2* __restrict__ wqh, __half2* __restrict__ wkh,
    __half2* __restrict__ woh)
{
    int i = blockIdx.x * 256 + threadIdx.x;
    const float4* src; __half2 *hi;
    if      (i < N4BIG)                { src = q;  hi = qh; }
    else if (i < 2*N4BIG)              { i -= N4BIG;          src = k;  hi = kh; }
    else if (i < 2*N4BIG + N4W)        { i -= 2*N4BIG;        src = wq; hi = wqh; }
    else if (i < 2*N4BIG + 2*N4W)      { i -= 2*N4BIG + N4W;  src = wk; hi = wkh; }
    else if (i < 2*N4BIG + 3*N4W)      { i -= 2*N4BIG + 2*N4W; src = wo; hi = woh; }
    else return;
    float4 v = src[i];
    hi[2*i]   = __floats2half2_rn(v.x, v.y);
    hi[2*i+1] = __floats2half2_rn(v.z, v.w);
}

// ---------------------------------------------------------------------------
// HMMA GEMM core: C = A @ B^T, pure fp16, 1-pass.
// Tile 128x64, K-chunk 64 (128B rows), NCHUNK 16, 8 warps, 3 CTAs/SM.
// MODE 0: fp32 flat out.  MODE 1: fp16 head-split out (scaled).
// ---------------------------------------------------------------------------
#define SROWB 144                     // 128 data + 16 pad
#define ATILEB (128 * SROWB)          // 18432
#define BTILEB (64 * SROWB)           // 9216
#define STAGEB (ATILEB + BTILEB)      // 27648
#define GEMM_SMEM (2 * STAGEB)        // 55296
#define NCHUNK 16

template<int MODE>
__device__ __forceinline__ void gemm_body(const __half* __restrict__ A,
                                          const __half* __restrict__ Bh,
                                          float* __restrict__ Cf,
                                          __half* __restrict__ Ch,
                                          float scale, int m0, int n0, char* smem)
{
    const int tid = threadIdx.x;
    const int wid = tid >> 5, lid = tid & 31;
    const int warp_m = wid & 3, warp_n = wid >> 2;      // 4 x 2
    const uint32_t sb = smem_u32(smem);

    float acc[2][4][4];
    #pragma unroll
    for (int i = 0; i < 2; i++)
        #pragma unroll
        for (int j = 0; j < 4; j++)
            #pragma unroll
            for (int c = 0; c < 4; c++) acc[i][j][c] = 0.f;

    const int gr8 = tid >> 3, gc8 = (tid & 7) * 16;     // 32 rows per 256-thread pass

    auto issue = [&](int kc) {
        const int st = kc & 1;
        const uint32_t base = sb + st * STAGEB;
        const size_t colB = (size_t)kc * 128;
        #pragma unroll
        for (int q = 0; q < 4; q++) {                   // A: 128 rows x 128B
            int r = gr8 + q * 32;
            cp16(base + r * SROWB + gc8,
                 (const char*)A + (size_t)(m0 + r) * 2048 + colB + gc8);
        }
        #pragma unroll
        for (int q = 0; q < 2; q++) {                   // B: 64 rows x 128B
            int r = gr8 + q * 32;
            cp16(base + ATILEB + r * SROWB + gc8,
                 (const char*)Bh + (size_t)(n0 + r) * 2048 + colB + gc8);
        }
        CP_COMMIT();
    };

    issue(0);
    for (int i = 0; i < NCHUNK; i++) {
        CP_WAIT(0);
        __syncthreads();
        if (i + 1 < NCHUNK) issue(i + 1);

        const int st = i & 1;
        const uint32_t base = sb + st * STAGEB;
        const uint32_t bA = base;
        const uint32_t bB = base + ATILEB;
        const int lrow = lid & 15, lcol = (lid >> 4) * 16;

        #pragma unroll
        for (int s = 0; s < 4; s++) {                   // 4 k16-steps per chunk
            uint32_t ah[2][4];
            #pragma unroll
            for (int mt = 0; mt < 2; mt++) {
                uint32_t off = (warp_m*32 + mt*16 + lrow) * SROWB + s*32 + lcol;
                ldm_x4(ah[mt][0], ah[mt][1], ah[mt][2], ah[mt][3], bA + off);
            }
            #pragma unroll
            for (int np = 0; np < 2; np++) {
                uint32_t off = (warp_n*32 + np*16 + lrow) * SROWB + s*32 + lcol;
                uint32_t h0,h1,h2,h3;
                ldm_x4(h0,h1,h2,h3, bB + off);
                #pragma unroll
                for (int mt = 0; mt < 2; mt++) {
                    mma16816(acc[mt][np*2][0],acc[mt][np*2][1],acc[mt][np*2][2],acc[mt][np*2][3],
                             ah[mt][0],ah[mt][1],ah[mt][2],ah[mt][3], h0, h2);
                    mma16816(acc[mt][np*2+1][0],acc[mt][np*2+1][1],acc[mt][np*2+1][2],acc[mt][np*2+1][3],
                             ah[mt][0],ah[mt][1],ah[mt][2],ah[mt][3], h1, h3);
                }
            }
        }
    }

    const int gid = lid >> 2, tig = lid & 3;
    #pragma unroll
    for (int mt = 0; mt < 2; mt++) {
        #pragma unroll
        for (int nt = 0; nt < 4; nt++) {
            int m = m0 + warp_m*32 + mt*16 + gid;
            int n = n0 + warp_n*32 + nt*8 + tig*2;
            #pragma unroll
            for (int half = 0; half < 2; half++) {
                int mm = m + half * 8;
                float x0 = acc[mt][nt][half*2+0], x1 = acc[mt][nt][half*2+1];
                if (MODE == 0) {
                    *(float2*)(Cf + (size_t)mm * E_ + n) = make_float2(x0, x1);
                } else {
                    uint32_t hv = pkh2(x0 * scale, x1 * scale);
                    int b = mm >> 11, t = mm & (T_ - 1);
                    int h = n >> 6,  d = n & 63;
                    size_t idx = (((size_t)b * H_ + h) * T_ + t) * D_ + d;
                    *(__half2*)(Ch + idx) = *(__half2*)&hv;
                }
            }
        }
    }
}

__global__ __launch_bounds__(256, 3) void gemm_proj(
    const __half* __restrict__ qA, const __half* __restrict__ kA,
    const __half* __restrict__ Wq, const __half* __restrict__ Wk,
    __half* __restrict__ qC, __half* __restrict__ kC)
{
    extern __shared__ __align__(16) char smem[];
    const int y = blockIdx.y;
    const int n0 = blockIdx.x * 64;
    if (y < 64) {
        gemm_body<1>(qA, Wq, nullptr, qC, 0.125f, y * 128, n0, smem);
    } else {
        gemm_body<1>(kA, Wk, nullptr, kC, 1.0f, (y - 64) * 128, n0, smem);
    }
}

__global__ __launch_bounds__(256, 3) void gemm_out(
    const __half* __restrict__ A, const __half* __restrict__ Wo,
    float* __restrict__ Cf)
{
    extern __shared__ __align__(16) char smem[];
    gemm_body<0>(A, Wo, Cf, nullptr, 1.0f, blockIdx.y * 128, blockIdx.x * 64, smem);
}

// ---------------------------------------------------------------------------
// Causal flash attention, V == K (share_kv), pure fp16, register-P packed
// early (reduces post-softmax pressure), 2 CTAs/SM.
// ---------------------------------------------------------------------------
#define QSTRB 144
#define KSTG  (128*QSTRB)             // 18432
#define SM_K(st) ((st)*KSTG)
#define ATTN_SMEM (2*KSTG)            // 36864

__global__ __launch_bounds__(256, 2) void attn_mma(const __half* __restrict__ qhh,
                                                   const __half* __restrict__ khh,
                                                   __half* __restrict__ aoh)
{
    extern __shared__ __align__(16) char smem[];
    const uint32_t sb = smem_u32(smem);
    const int tid = threadIdx.x;
    const int wid = tid >> 5, lid = tid & 31;
    const int wrow = wid * 16;
    const int gid = lid >> 2, tig = lid & 3;
    const int lrow = lid & 15, lcol = (lid >> 4) * 16;
    const int qt = 15 - (int)blockIdx.x;
    const int bh = blockIdx.y;

    const char* Kg = (const char*)(khh + (size_t)bh * T_ * D_);

    auto issueK = [&](int kt, int st) {
        #pragma unroll
        for (int i = 0; i < 4; i++) {
            int idx = tid + i * 256;
            int r = idx >> 3, c = (idx & 7) * 16;
            cp16(sb + SM_K(st) + r * QSTRB + c, Kg + ((size_t)kt * 128 + r) * 128 + c);
        }
        CP_COMMIT();
    };

    issueK(0, 0);

    uint32_t qh[4][4];
    {
        const __half* Qg = qhh + (size_t)bh * T_ * D_ + (size_t)(qt * 128 + wrow) * D_;
        #pragma unroll
        for (int ks = 0; ks < 4; ks++) {
            int c0 = ks * 16 + tig * 2;
            qh[ks][0] = *(const uint32_t*)(Qg + (size_t)gid * D_ + c0);
            qh[ks][1] = *(const uint32_t*)(Qg + (size_t)(gid + 8) * D_ + c0);
            qh[ks][2] = *(const uint32_t*)(Qg + (size_t)gid * D_ + c0 + 8);
            qh[ks][3] = *(const uint32_t*)(Qg + (size_t)(gid + 8) * D_ + c0 + 8);
        }
    }

    float mrow[2] = {-1e30f, -1e30f};
    float lrow_[2] = {0.f, 0.f};
    float o[8][4];
    #pragma unroll
    for (int nt = 0; nt < 8; nt++)
        #pragma unroll
        for (int c = 0; c < 4; c++) o[nt][c] = 0.f;

    for (int kt = 0; kt <= qt; kt++) {
        const int st = kt & 1;
        if (kt < qt) { issueK(kt + 1, st ^ 1); CP_WAIT(1); }
        else         { CP_WAIT(0); }
        __syncthreads();

        // ---- S = Q @ K^T ----
        float s[16][4];
        #pragma unroll
        for (int nt = 0; nt < 16; nt++)
            #pragma unroll
            for (int c = 0; c < 4; c++) s[nt][c] = 0.f;

        #pragma unroll
        for (int ks = 0; ks < 4; ks++) {
            uint32_t b[16][2];
            #pragma unroll
            for (int np = 0; np < 8; np++) {
                uint32_t r0,r1,r2,r3;
                ldm_x4(r0,r1,r2,r3, sb + SM_K(st) + (np*16 + lrow) * QSTRB + ks*32 + lcol);
                b[np*2][0] = r0;   b[np*2][1] = r2;
                b[np*2+1][0] = r1; b[np*2+1][1] = r3;
            }
            #pragma unroll
            for (int nt = 0; nt < 16; nt++)
                mma16816(s[nt][0], s[nt][1], s[nt][2], s[nt][3],
                         qh[ks][0], qh[ks][1], qh[ks][2], qh[ks][3], b[nt][0], b[nt][1]);
        }

        if (kt == qt) {
            #pragma unroll
            for (int nt = 0; nt < 16; nt++)
                #pragma unroll
                for (int c = 0; c < 4; c++) {
                    int row = wrow + gid + (c >> 1) * 8;
                    int col = nt*8 + tig*2 + (c & 1);
                    if (col > row) s[nt][c] = -1e30f;
                }
        }

        // ---- online softmax; pack P into half2 immediately (s dies here) ----
        uint32_t pk[16][2];
        #pragma unroll
        for (int r = 0; r < 2; r++) {
            float mx = -1e30f;
            #pragma unroll
            for (int nt = 0; nt < 16; nt++)
                mx = fmaxf(mx, fmaxf(s[nt][r*2], s[nt][r*2+1]));
            mx = fmaxf(mx, __shfl_xor_sync(0xffffffffu, mx, 1));
            mx = fmaxf(mx, __shfl_xor_sync(0xffffffffu, mx, 2));
            float mnew = fmaxf(mrow[r], mx);
            float psum = 0.f;
            #pragma unroll
            for (int nt = 0; nt < 16; nt++) {
                float p0 = __expf(s[nt][r*2]   - mnew);
                float p1 = __expf(s[nt][r*2+1] - mnew);
                psum += p0 + p1;
                pk[nt][r] = pkh2(p0, p1);
            }
            psum += __shfl_xor_sync(0xffffffffu, psum, 1);
            psum += __shfl_xor_sync(0xffffffffu, psum, 2);
            float corr = __expf(mrow[r] - mnew);
            lrow_[r] = lrow_[r] * corr + psum;
            mrow[r] = mnew;
            #pragma unroll
            for (int nt = 0; nt < 8; nt++) {
                o[nt][r*2]   *= corr;
                o[nt][r*2+1] *= corr;
            }
        }

        // ---- PV: P @ V (V = K tile) ----
        #pragma unroll
        for (int ks = 0; ks < 8; ks++) {
            uint32_t v[4][4];
            #pragma unroll
            for (int nb = 0; nb < 4; nb++)
                ldm_x4t(v[nb][0], v[nb][1], v[nb][2], v[nb][3],
                        sb + SM_K(st) + (ks*16 + lrow) * QSTRB + nb*32 + lcol);
            #pragma unroll
            for (int nb = 0; nb < 4; nb++) {
                mma16816(o[nb*2][0],   o[nb*2][1],   o[nb*2][2],   o[nb*2][3],
                         pk[2*ks][0], pk[2*ks][1], pk[2*ks+1][0], pk[2*ks+1][1],
                         v[nb][0], v[nb][1]);
                mma16816(o[nb*2+1][0], o[nb*2+1][1], o[nb*2+1][2], o[nb*2+1][3],
                         pk[2*ks][0], pk[2*ks][1], pk[2*ks+1][0], pk[2*ks+1][1],
                         v[nb][2], v[nb][3]);
            }
        }
        __syncthreads();
    }

    const int b = bh >> 4, h = bh & 15;
    #pragma unroll
    for (int r = 0; r < 2; r++) {
        float inv = 1.0f / lrow_[r];
        int t = qt*128 + wrow + gid + r*8;
        #pragma unroll
        for (int nt = 0; nt < 8; nt++) {
            uint32_t hv = pkh2(o[nt][r*2] * inv, o[nt][r*2+1] * inv);
            size_t idx = ((size_t)b * T_ + t) * E_ + h*64 + nt*8 + tig*2;
            *(__half2*)(aoh + idx) = *(__half2*)&hv;
        }
    }
}

// ---------------------------------------------------------------------------
extern "C" void kernel_launch(void* const* d_in, const int* in_sizes, int n_in,
                              void* d_out, int out_size)
{
    const float* q  = (const float*)d_in[0];
    const float* k  = (const float*)d_in[1];
    // d_in[2] (v) dead: share_kv
    const float* Wq = (const float*)d_in[3];
    const float* Wk = (const float*)d_in[4];
    const float* Wo = (const float*)d_in[5];
    float* out = (float*)d_out;

    __half *pqh,*pkh,*pwqh,*pwkh,*pwoh,*pqhh,*pkhh,*paoh;
    cudaGetSymbolAddress((void**)&pqh, g_qh);
    cudaGetSymbolAddress((void**)&pkh, g_kh);
    cudaGetSymbolAddress((void**)&pwqh, g_wqh);
    cudaGetSymbolAddress((void**)&pwkh, g_wkh);
    cudaGetSymbolAddress((void**)&pwoh, g_woh);
    cudaGetSymbolAddress((void**)&pqhh, g_qhh);
    cudaGetSymbolAddress((void**)&pkhh, g_khh);
    cudaGetSymbolAddress((void**)&paoh, g_aoh);

    static bool attr_done = false;
    if (!attr_done) {
        cudaFuncSetAttribute(attn_mma, cudaFuncAttributeMaxDynamicSharedMemorySize, ATTN_SMEM);
        cudaFuncSetAttribute(gemm_proj, cudaFuncAttributeMaxDynamicSharedMemorySize, GEMM_SMEM);
        cudaFuncSetAttribute(gemm_out, cudaFuncAttributeMaxDynamicSharedMemorySize, GEMM_SMEM);
        attr_done = true;
    }

    const int total4 = 2*N4BIG + 3*N4W;
    split_all<<<(total4 + 255)/256, 256>>>(
        (const float4*)q, (const float4*)k,
        (const float4*)Wq, (const float4*)Wk, (const float4*)Wo,
        (__half2*)pqh, (__half2*)pkh,
        (__half2*)pwqh, (__half2*)pwkh, (__half2*)pwoh);

    gemm_proj<<<dim3(16, 128), 256, GEMM_SMEM>>>(pqh, pkh, pwqh, pwkh, pqhh, pkhh);

    attn_mma<<<dim3(16, B_*H_), 256, ATTN_SMEM>>>(pqhh, pkhh, paoh);

    gemm_out<<<dim3(16, 64), 256, GEMM_SMEM>>>(paoh, pwoh, out);
}

// round 14
// speedup vs baseline: 7.5775x; 1.0355x over previous
#include <cuda_runtime.h>
#include <cuda_fp16.h>
#include <math.h>
#include <stdint.h>

#define B_ 4
#define T_ 2048
#define E_ 1024
#define H_ 16
#define D_ 64
#define M_TOT (B_*T_)   // 8192

// ---------------- scratch (allocation-free) ----------------
__device__ __align__(16) __half g_qh[M_TOT*E_];    // input q (fp16)
__device__ __align__(16) __half g_kh[M_TOT*E_];    // input k
__device__ __align__(16) __half g_wqh[E_*E_];
__device__ __align__(16) __half g_wkh[E_*E_];
__device__ __align__(16) __half g_woh[E_*E_];
__device__ __align__(16) __half g_qhh[M_TOT*E_];   // Q head [b,h,t,d] (scaled 0.125*log2e)
__device__ __align__(16) __half g_khh[M_TOT*E_];   // K head (V alias)
__device__ __align__(16) __half g_aoh[M_TOT*E_];   // attn out [b,t,(h d)]

// ---------------- helpers ----------------
__device__ __forceinline__ uint32_t smem_u32(const void* p) {
    uint32_t a;
    asm("{ .reg .u64 t; cvta.to.shared.u64 t, %1; cvt.u32.u64 %0, t; }" : "=r"(a) : "l"(p));
    return a;
}
__device__ __forceinline__ void cp16(uint32_t saddr, const void* gaddr) {
    asm volatile("cp.async.cg.shared.global [%0], [%1], 16;" :: "r"(saddr), "l"(gaddr));
}
#define CP_COMMIT() asm volatile("cp.async.commit_group;" ::: "memory")
#define CP_WAIT(n)  asm volatile("cp.async.wait_group %0;" :: "n"(n) : "memory")

__device__ __forceinline__ void ldm_x4(uint32_t& r0, uint32_t& r1, uint32_t& r2, uint32_t& r3,
                                       uint32_t addr) {
    asm volatile("ldmatrix.sync.aligned.m8n8.x4.shared.b16 {%0,%1,%2,%3}, [%4];"
                 : "=r"(r0), "=r"(r1), "=r"(r2), "=r"(r3) : "r"(addr));
}
__device__ __forceinline__ void ldm_x4t(uint32_t& r0, uint32_t& r1, uint32_t& r2, uint32_t& r3,
                                        uint32_t addr) {
    asm volatile("ldmatrix.sync.aligned.m8n8.x4.trans.shared.b16 {%0,%1,%2,%3}, [%4];"
                 : "=r"(r0), "=r"(r1), "=r"(r2), "=r"(r3) : "r"(addr));
}
__device__ __forceinline__ void mma16816(float& d0, float& d1, float& d2, float& d3,
                                         uint32_t a0, uint32_t a1, uint32_t a2, uint32_t a3,
                                         uint32_t b0, uint32_t b1) {
    asm volatile("mma.sync.aligned.m16n8k16.row.col.f32.f16.f16.f32 "
                 "{%0,%1,%2,%3}, {%4,%5,%6,%7}, {%8,%9}, {%0,%1,%2,%3};"
                 : "+f"(d0), "+f"(d1), "+f"(d2), "+f"(d3)
                 : "r"(a0), "r"(a1), "r"(a2), "r"(a3), "r"(b0), "r"(b1));
}
__device__ __forceinline__ uint32_t pkh2(float a, float b) {
    __half2 h = __floats2half2_rn(a, b);
    return *(uint32_t*)&h;
}

// ---------------- fused fp32 -> fp16 convert ----------------
#define N4BIG (M_TOT*E_/4)
#define N4W   (E_*E_/4)
__global__ __launch_bounds__(256) void split_all(
    const float4* __restrict__ q, const float4* __restrict__ k,
    const float4* __restrict__ wq, const float4* __restrict__ wk,
    const float4* __restrict__ wo,
    __half2* __restrict__ qh, __half2* __restrict__ kh,
    __half2* __restrict__ wqh, __half2* __restrict__ wkh,
    __half2* __restrict__ woh)
{
    int i = blockIdx.x * 256 + threadIdx.x;
    const float4* src; __half2 *hi;
    if      (i < N4BIG)                { src = q;  hi = qh; }
    else if (i < 2*N4BIG)              { i -= N4BIG;          src = k;  hi = kh; }
    else if (i < 2*N4BIG + N4W)        { i -= 2*N4BIG;        src = wq; hi = wqh; }
    else if (i < 2*N4BIG + 2*N4W)      { i -= 2*N4BIG + N4W;  src = wk; hi = wkh; }
    else if (i < 2*N4BIG + 3*N4W)      { i -= 2*N4BIG + 2*N4W; src = wo; hi = woh; }
    else return;
    float4 v = src[i];
    hi[2*i]   = __floats2half2_rn(v.x, v.y);
    hi[2*i+1] = __floats2half2_rn(v.z, v.w);
}

// ---------------------------------------------------------------------------
// HMMA GEMM core: C = A @ B^T, pure fp16, 1-pass.
// Tile 128x128 (halves A-refetch L2 traffic), K-chunk 64, NCHUNK 16,
// 8 warps (4m x 2n, warp 32x64), 2 CTAs/SM.
// MODE 0: fp32 flat out.  MODE 1: fp16 head-split out (scaled).
// ---------------------------------------------------------------------------
#define SROWB 144                     // 128 data + 16 pad
#define ATILEB (128 * SROWB)          // 18432
#define STAGEB (2 * ATILEB)           // 36864 (A + B, each 128 rows)
#define GEMM_SMEM (2 * STAGEB)        // 73728
#define NCHUNK 16

template<int MODE>
__device__ __forceinline__ void gemm_body(const __half* __restrict__ A,
                                          const __half* __restrict__ Bh,
                                          float* __restrict__ Cf,
                                          __half* __restrict__ Ch,
                                          float scale, int m0, int n0, char* smem)
{
    const int tid = threadIdx.x;
    const int wid = tid >> 5, lid = tid & 31;
    const int warp_m = wid & 3, warp_n = wid >> 2;      // 4 x 2; warp tile 32x64
    const uint32_t sb = smem_u32(smem);

    float acc[2][8][4];
    #pragma unroll
    for (int i = 0; i < 2; i++)
        #pragma unroll
        for (int j = 0; j < 8; j++)
            #pragma unroll
            for (int c = 0; c < 4; c++) acc[i][j][c] = 0.f;

    const int gr8 = tid >> 3, gc8 = (tid & 7) * 16;     // 32 rows per 256-thread pass

    auto issue = [&](int kc) {
        const int st = kc & 1;
        const uint32_t base = sb + st * STAGEB;
        const size_t colB = (size_t)kc * 128;
        #pragma unroll
        for (int q = 0; q < 4; q++) {                   // A: 128 rows x 128B
            int r = gr8 + q * 32;
            cp16(base + r * SROWB + gc8,
                 (const char*)A + (size_t)(m0 + r) * 2048 + colB + gc8);
        }
        #pragma unroll
        for (int q = 0; q < 4; q++) {                   // B: 128 rows x 128B
            int r = gr8 + q * 32;
            cp16(base + ATILEB + r * SROWB + gc8,
                 (const char*)Bh + (size_t)(n0 + r) * 2048 + colB + gc8);
        }
        CP_COMMIT();
    };

    issue(0);
    for (int i = 0; i < NCHUNK; i++) {
        CP_WAIT(0);
        __syncthreads();
        if (i + 1 < NCHUNK) issue(i + 1);

        const int st = i & 1;
        const uint32_t bA = sb + st * STAGEB;
        const uint32_t bB = bA + ATILEB;
        const int lrow = lid & 15, lcol = (lid >> 4) * 16;

        #pragma unroll
        for (int s = 0; s < 4; s++) {                   // 4 k16-steps per chunk
            uint32_t ah[2][4];
            #pragma unroll
            for (int mt = 0; mt < 2; mt++) {
                uint32_t off = (warp_m*32 + mt*16 + lrow) * SROWB + s*32 + lcol;
                ldm_x4(ah[mt][0], ah[mt][1], ah[mt][2], ah[mt][3], bA + off);
            }
            #pragma unroll
            for (int np = 0; np < 4; np++) {
                uint32_t off = (warp_n*64 + np*16 + lrow) * SROWB + s*32 + lcol;
                uint32_t h0,h1,h2,h3;
                ldm_x4(h0,h1,h2,h3, bB + off);
                #pragma unroll
                for (int mt = 0; mt < 2; mt++) {
                    mma16816(acc[mt][np*2][0],acc[mt][np*2][1],acc[mt][np*2][2],acc[mt][np*2][3],
                             ah[mt][0],ah[mt][1],ah[mt][2],ah[mt][3], h0, h2);
                    mma16816(acc[mt][np*2+1][0],acc[mt][np*2+1][1],acc[mt][np*2+1][2],acc[mt][np*2+1][3],
                             ah[mt][0],ah[mt][1],ah[mt][2],ah[mt][3], h1, h3);
                }
            }
        }
    }

    const int gid = lid >> 2, tig = lid & 3;
    #pragma unroll
    for (int mt = 0; mt < 2; mt++) {
        #pragma unroll
        for (int nt = 0; nt < 8; nt++) {
            int m = m0 + warp_m*32 + mt*16 + gid;
            int n = n0 + warp_n*64 + nt*8 + tig*2;
            #pragma unroll
            for (int half = 0; half < 2; half++) {
                int mm = m + half * 8;
                float x0 = acc[mt][nt][half*2+0], x1 = acc[mt][nt][half*2+1];
                if (MODE == 0) {
                    *(float2*)(Cf + (size_t)mm * E_ + n) = make_float2(x0, x1);
                } else {
                    uint32_t hv = pkh2(x0 * scale, x1 * scale);
                    int b = mm >> 11, t = mm & (T_ - 1);
                    int h = n >> 6,  d = n & 63;
                    size_t idx = (((size_t)b * H_ + h) * T_ + t) * D_ + d;
                    *(__half2*)(Ch + idx) = *(__half2*)&hv;
                }
            }
        }
    }
}

#define QSCALE (0.125f * 1.44269504089f)   // fold log2e into Q for exp2 softmax

__global__ __launch_bounds__(256, 2) void gemm_proj(
    const __half* __restrict__ qA, const __half* __restrict__ kA,
    const __half* __restrict__ Wq, const __half* __restrict__ Wk,
    __half* __restrict__ qC, __half* __restrict__ kC)
{
    extern __shared__ __align__(16) char smem[];
    const int y = blockIdx.y;
    const int n0 = blockIdx.x * 128;
    if (y < 64) {
        gemm_body<1>(qA, Wq, nullptr, qC, QSCALE, y * 128, n0, smem);
    } else {
        gemm_body<1>(kA, Wk, nullptr, kC, 1.0f, (y - 64) * 128, n0, smem);
    }
}

__global__ __launch_bounds__(256, 2) void gemm_out(
    const __half* __restrict__ A, const __half* __restrict__ Wo,
    float* __restrict__ Cf)
{
    extern __shared__ __align__(16) char smem[];
    gemm_body<0>(A, Wo, Cf, nullptr, 1.0f, blockIdx.y * 128, blockIdx.x * 128, smem);
}

// ---------------------------------------------------------------------------
// Causal flash attention, V == K (share_kv), pure fp16, register-P,
// exp2-domain softmax (log2e folded into Q), 2 CTAs/SM.
// ---------------------------------------------------------------------------
#define QSTRB 144
#define KSTG  (128*QSTRB)             // 18432
#define SM_K(st) ((st)*KSTG)
#define ATTN_SMEM (2*KSTG)            // 36864

__global__ __launch_bounds__(256, 2) void attn_mma(const __half* __restrict__ qhh,
                                                   const __half* __restrict__ khh,
                                                   __half* __restrict__ aoh)
{
    extern __shared__ __align__(16) char smem[];
    const uint32_t sb = smem_u32(smem);
    const int tid = threadIdx.x;
    const int wid = tid >> 5, lid = tid & 31;
    const int wrow = wid * 16;
    const int gid = lid >> 2, tig = lid & 3;
    const int lrow = lid & 15, lcol = (lid >> 4) * 16;
    const int qt = 15 - (int)blockIdx.x;
    const int bh = blockIdx.y;

    const char* Kg = (const char*)(khh + (size_t)bh * T_ * D_);

    auto issueK = [&](int kt, int st) {
        #pragma unroll
        for (int i = 0; i < 4; i++) {
            int idx = tid + i * 256;
            int r = idx >> 3, c = (idx & 7) * 16;
            cp16(sb + SM_K(st) + r * QSTRB + c, Kg + ((size_t)kt * 128 + r) * 128 + c);
        }
        CP_COMMIT();
    };

    issueK(0, 0);

    uint32_t qh[4][4];
    {
        const __half* Qg = qhh + (size_t)bh * T_ * D_ + (size_t)(qt * 128 + wrow) * D_;
        #pragma unroll
        for (int ks = 0; ks < 4; ks++) {
            int c0 = ks * 16 + tig * 2;
            qh[ks][0] = *(const uint32_t*)(Qg + (size_t)gid * D_ + c0);
            qh[ks][1] = *(const uint32_t*)(Qg + (size_t)(gid + 8) * D_ + c0);
            qh[ks][2] = *(const uint32_t*)(Qg + (size_t)gid * D_ + c0 + 8);
            qh[ks][3] = *(const uint32_t*)(Qg + (size_t)(gid + 8) * D_ + c0 + 8);
        }
    }

    float mrow[2] = {-1e30f, -1e30f};
    float lrow_[2] = {0.f, 0.f};
    float o[8][4];
    #pragma unroll
    for (int nt = 0; nt < 8; nt++)
        #pragma unroll
        for (int c = 0; c < 4; c++) o[nt][c] = 0.f;

    for (int kt = 0; kt <= qt; kt++) {
        const int st = kt & 1;
        if (kt < qt) { issueK(kt + 1, st ^ 1); CP_WAIT(1); }
        else         { CP_WAIT(0); }
        __syncthreads();

        // ---- S = Q @ K^T (S in log2 domain) ----
        float s[16][4];
        #pragma unroll
        for (int nt = 0; nt < 16; nt++)
            #pragma unroll
            for (int c = 0; c < 4; c++) s[nt][c] = 0.f;

        #pragma unroll
        for (int ks = 0; ks < 4; ks++) {
            uint32_t b[16][2];
            #pragma unroll
            for (int np = 0; np < 8; np++) {
                uint32_t r0,r1,r2,r3;
                ldm_x4(r0,r1,r2,r3, sb + SM_K(st) + (np*16 + lrow) * QSTRB + ks*32 + lcol);
                b[np*2][0] = r0;   b[np*2][1] = r2;
                b[np*2+1][0] = r1; b[np*2+1][1] = r3;
            }
            #pragma unroll
            for (int nt = 0; nt < 16; nt++)
                mma16816(s[nt][0], s[nt][1], s[nt][2], s[nt][3],
                         qh[ks][0], qh[ks][1], qh[ks][2], qh[ks][3], b[nt][0], b[nt][1]);
        }

        if (kt == qt) {
            #pragma unroll
            for (int nt = 0; nt < 16; nt++)
                #pragma unroll
                for (int c = 0; c < 4; c++) {
                    int row = wrow + gid + (c >> 1) * 8;
                    int col = nt*8 + tig*2 + (c & 1);
                    if (col > row) s[nt][c] = -1e30f;
                }
        }

        // ---- online softmax in exp2 domain; pack P immediately ----
        uint32_t pk[16][2];
        #pragma unroll
        for (int r = 0; r < 2; r++) {
            float mx = -1e30f;
            #pragma unroll
            for (int nt = 0; nt < 16; nt++)
                mx = fmaxf(mx, fmaxf(s[nt][r*2], s[nt][r*2+1]));
            mx = fmaxf(mx, __shfl_xor_sync(0xffffffffu, mx, 1));
            mx = fmaxf(mx, __shfl_xor_sync(0xffffffffu, mx, 2));
            float mnew = fmaxf(mrow[r], mx);
            float psum = 0.f;
            #pragma unroll
            for (int nt = 0; nt < 16; nt++) {
                float p0 = exp2f(s[nt][r*2]   - mnew);
                float p1 = exp2f(s[nt][r*2+1] - mnew);
                psum += p0 + p1;
                pk[nt][r] = pkh2(p0, p1);
            }
            psum += __shfl_xor_sync(0xffffffffu, psum, 1);
            psum += __shfl_xor_sync(0xffffffffu, psum, 2);
            float corr = exp2f(mrow[r] - mnew);
            lrow_[r] = lrow_[r] * corr + psum;
            mrow[r] = mnew;
            #pragma unroll
            for (int nt = 0; nt < 8; nt++) {
                o[nt][r*2]   *= corr;
                o[nt][r*2+1] *= corr;
            }
        }

        // ---- PV: P @ V (V = K tile) ----
        #pragma unroll
        for (int ks = 0; ks < 8; ks++) {
            uint32_t v[4][4];
            #pragma unroll
            for (int nb = 0; nb < 4; nb++)
                ldm_x4t(v[nb][0], v[nb][1], v[nb][2], v[nb][3],
                        sb + SM_K(st) + (ks*16 + lrow) * QSTRB + nb*32 + lcol);
            #pragma unroll
            for (int nb = 0; nb < 4; nb++) {
                mma16816(o[nb*2][0],   o[nb*2][1],   o[nb*2][2],   o[nb*2][3],
                         pk[2*ks][0], pk[2*ks][1], pk[2*ks+1][0], pk[2*ks+1][1],
                         v[nb][0], v[nb][1]);
                mma16816(o[nb*2+1][0], o[nb*2+1][1], o[nb*2+1][2], o[nb*2+1][3],
                         pk[2*ks][0], pk[2*ks][1], pk[2*ks+1][0], pk[2*ks+1][1],
                         v[nb][2], v[nb][3]);
            }
        }
        __syncthreads();
    }

    const int b = bh >> 4, h = bh & 15;
    #pragma unroll
    for (int r = 0; r < 2; r++) {
        float inv = 1.0f / lrow_[r];
        int t = qt*128 + wrow + gid + r*8;
        #pragma unroll
        for (int nt = 0; nt < 8; nt++) {
            uint32_t hv = pkh2(o[nt][r*2] * inv, o[nt][r*2+1] * inv);
            size_t idx = ((size_t)b * T_ + t) * E_ + h*64 + nt*8 + tig*2;
            *(__half2*)(aoh + idx) = *(__half2*)&hv;
        }
    }
}

// ---------------------------------------------------------------------------
extern "C" void kernel_launch(void* const* d_in, const int* in_sizes, int n_in,
                              void* d_out, int out_size)
{
    const float* q  = (const float*)d_in[0];
    const float* k  = (const float*)d_in[1];
    // d_in[2] (v) dead: share_kv
    const float* Wq = (const float*)d_in[3];
    const float* Wk = (const float*)d_in[4];
    const float* Wo = (const float*)d_in[5];
    float* out = (float*)d_out;

    __half *pqh,*pkh,*pwqh,*pwkh,*pwoh,*pqhh,*pkhh,*paoh;
    cudaGetSymbolAddress((void**)&pqh, g_qh);
    cudaGetSymbolAddress((void**)&pkh, g_kh);
    cudaGetSymbolAddress((void**)&pwqh, g_wqh);
    cudaGetSymbolAddress((void**)&pwkh, g_wkh);
    cudaGetSymbolAddress((void**)&pwoh, g_woh);
    cudaGetSymbolAddress((void**)&pqhh, g_qhh);
    cudaGetSymbolAddress((void**)&pkhh, g_khh);
    cudaGetSymbolAddress((void**)&paoh, g_aoh);

    static bool attr_done = false;
    if (!attr_done) {
        cudaFuncSetAttribute(attn_mma, cudaFuncAttributeMaxDynamicSharedMemorySize, ATTN_SMEM);
        cudaFuncSetAttribute(gemm_proj, cudaFuncAttributeMaxDynamicSharedMemorySize, GEMM_SMEM);
        cudaFuncSetAttribute(gemm_out, cudaFuncAttributeMaxDynamicSharedMemorySize, GEMM_SMEM);
        attr_done = true;
    }

    const int total4 = 2*N4BIG + 3*N4W;
    split_all<<<(total4 + 255)/256, 256>>>(
        (const float4*)q, (const float4*)k,
        (const float4*)Wq, (const float4*)Wk, (const float4*)Wo,
        (__half2*)pqh, (__half2*)pkh,
        (__half2*)pwqh, (__half2*)pwkh, (__half2*)pwoh);

    gemm_proj<<<dim3(8, 128), 256, GEMM_SMEM>>>(pqh, pkh, pwqh, pwkh, pqhh, pkhh);

    attn_mma<<<dim3(16, B_*H_), 256, ATTN_SMEM>>>(pqhh, pkhh, paoh);

    gemm_out<<<dim3(8, 64), 256, GEMM_SMEM>>>(paoh, pwoh, out);
}